// round 1
// baseline (speedup 1.0000x reference)
#include <cuda_runtime.h>
#include <cuda_bf16.h>
#include <math.h>

// AttentionWithPairBias: B=1, L=768, C_S=384, C_Z=128, H=8, HD=48
// Inputs (metadata order):
// 0 single[1,768,384] 1 pair[1,768,768,128] 2 g_s[384] 3 b_s[384]
// 4 g_z[128] 5 b_z[128] 6 Wq[384,384] 7 Wk 8 Wv 9 Wb[128,8]
// 10 Wo[384,384] 11 bo[384] 12 Wg[384,384] 13 bg[384]
// Output: float32 [1,768,384]

#define L 768
#define CS 384
#define CZ 128
#define NH 8
#define HD 48
#define LL (L*L)                 // 589824
#define OPS (L*CS)               // 294912 (one o-partial plane)

// -------------------- scratch (device globals; no allocs) --------------------
__device__ float g_sln[L*CS];            // layernorm(single)
__device__ float g_bias[(size_t)NH*LL];  // bias -> logits -> probs (in place)
__device__ float g_q[L*CS];
__device__ float g_k[L*CS];
__device__ float g_gate[L*CS];           // s@Wg^T (pre-activation, no bg)
__device__ float g_vt[CS*L];             // V transposed: [n=384][i=768]
__device__ float g_opart[4*OPS];         // split-K partials of attn@V

// -------------------- helpers --------------------
__device__ __forceinline__ float warp_sum(float v){
#pragma unroll
    for (int o = 16; o; o >>= 1) v += __shfl_xor_sync(0xffffffffu, v, o);
    return v;
}
__device__ __forceinline__ float warp_max(float v){
#pragma unroll
    for (int o = 16; o; o >>= 1) v = fmaxf(v, __shfl_xor_sync(0xffffffffu, v, o));
    return v;
}

// -------------------- K1: layernorm(single) --------------------
__global__ void ln_single_kernel(const float* __restrict__ x,
                                 const float* __restrict__ g,
                                 const float* __restrict__ b){
    __shared__ float rs[4], rq[4];
    int i = blockIdx.x, t = threadIdx.x;     // 128 threads
    int lane = t & 31, w = t >> 5;
    float v[3];
#pragma unroll
    for (int e = 0; e < 3; e++) v[e] = x[i*CS + e*128 + t];
    float s = v[0] + v[1] + v[2];
    float q = v[0]*v[0] + v[1]*v[1] + v[2]*v[2];
    s = warp_sum(s); q = warp_sum(q);
    if (lane == 0){ rs[w] = s; rq[w] = q; }
    __syncthreads();
    s = rs[0] + rs[1] + rs[2] + rs[3];
    q = rq[0] + rq[1] + rq[2] + rq[3];
    float mu   = s * (1.f/CS);
    float var  = q * (1.f/CS) - mu*mu;
    float rstd = rsqrtf(var + 1e-5f);
#pragma unroll
    for (int e = 0; e < 3; e++){
        int c = e*128 + t;
        g_sln[i*CS + c] = (v[e] - mu) * rstd * g[c] + b[c];
    }
}

// -------------------- K2: layernorm(pair) + bias = zn @ Wb --------------------
// grid (4, 768), 512 threads (16 warps). Each warp handles one (i,j) per iter:
// 128 z values as one float4 per lane. Output bias[h][i][j] via smem staging
// so global writes are coalesced.
__global__ void ln_pair_bias_kernel(const float4* __restrict__ z4,
                                    const float* __restrict__ gz,
                                    const float* __restrict__ bz,
                                    const float* __restrict__ Wb){
    __shared__ float stage[16][9];
    const int tid  = threadIdx.x;
    const int warp = tid >> 5, lane = tid & 31;
    const int i    = blockIdx.y;
    const int zb   = lane * 4;

    // per-lane constants: 4 rows of Wb + gamma/beta
    float wr[4][8], gzr[4], bzr[4];
#pragma unroll
    for (int e = 0; e < 4; e++){
        gzr[e] = gz[zb+e]; bzr[e] = bz[zb+e];
        float4 w0 = ((const float4*)Wb)[(zb+e)*2 + 0];
        float4 w1 = ((const float4*)Wb)[(zb+e)*2 + 1];
        wr[e][0]=w0.x; wr[e][1]=w0.y; wr[e][2]=w0.z; wr[e][3]=w0.w;
        wr[e][4]=w1.x; wr[e][5]=w1.y; wr[e][6]=w1.z; wr[e][7]=w1.w;
    }

    for (int it = 0; it < 12; it++){
        int j = blockIdx.x*192 + it*16 + warp;
        float4 zv = z4[((size_t)i*L + j)*32 + lane];
        float zs[4] = {zv.x, zv.y, zv.z, zv.w};
        float s = zs[0]+zs[1]+zs[2]+zs[3];
        float q = zs[0]*zs[0]+zs[1]*zs[1]+zs[2]*zs[2]+zs[3]*zs[3];
#pragma unroll
        for (int o = 16; o; o >>= 1){
            s += __shfl_xor_sync(0xffffffffu, s, o);
            q += __shfl_xor_sync(0xffffffffu, q, o);
        }
        float mu   = s * (1.f/128.f);
        float var  = q * (1.f/128.f) - mu*mu;
        float rstd = rsqrtf(var + 1e-5f);

        float acc[8] = {0,0,0,0,0,0,0,0};
#pragma unroll
        for (int e = 0; e < 4; e++){
            float zn = (zs[e]-mu)*rstd*gzr[e] + bzr[e];
#pragma unroll
            for (int h = 0; h < 8; h++) acc[h] = fmaf(zn, wr[e][h], acc[h]);
        }
#pragma unroll
        for (int h = 0; h < 8; h++)
#pragma unroll
            for (int o = 16; o; o >>= 1) acc[h] += __shfl_xor_sync(0xffffffffu, acc[h], o);

        if (lane < 8) stage[warp][lane] = acc[lane];
        __syncthreads();
        if (tid < 128){
            int h = tid >> 4, jj = tid & 15;
            g_bias[(size_t)h*LL + (size_t)i*L + blockIdx.x*192 + it*16 + jj] = stage[jj][h];
        }
        __syncthreads();
    }
}

// -------------------- generic fp32 GEMM body: C = A @ B^T (+ epilogue) -------
// A[M,K] row-major (lda), B[N,K] row-major (ldb). 256 threads.
// EPI: 0 plain store, 1 transposed store C[col][row], 2 C += acc*scale (bias add),
//      4 final: C = e0 + sigmoid(e1+e2) * (acc + e3)
template<int BM,int BN,int BK,int TM,int TN,bool SUMA,int EPI>
__device__ __forceinline__ void gemm_body(
    float* As, float* Bs,
    int M, int N, int K,
    const float* __restrict__ A, int lda, size_t aplane,
    const float* __restrict__ Bm, int ldb,
    float* __restrict__ C, int ldc,
    int m0, int n0, float scale,
    const float* __restrict__ e0, const float* __restrict__ e1,
    const float* __restrict__ e2, const float* __restrict__ e3)
{
    constexpr int TX = BN / TN;
    constexpr int TY = BM / TM;
    static_assert(TX * TY == 256, "need 256 threads");
    constexpr int KQ  = BK / 4;
    constexpr int AF4 = BM * KQ;
    constexpr int BF4 = BN * KQ;

    const int tid = threadIdx.x;
    const int tx  = tid % TX, ty = tid / TX;

    float acc[TM][TN];
#pragma unroll
    for (int i = 0; i < TM; i++)
#pragma unroll
        for (int j = 0; j < TN; j++) acc[i][j] = 0.f;

    for (int kt = 0; kt < K; kt += BK){
#pragma unroll
        for (int t4 = tid; t4 < AF4; t4 += 256){
            int row = t4 / KQ, kq = t4 % KQ;
            int grow = m0 + row;
            float4 v = make_float4(0.f,0.f,0.f,0.f);
            if (grow < M){
                const float* p = A + (size_t)grow*lda + kt + kq*4;
                v = *(const float4*)p;
                if (SUMA){
                    float4 v1 = *(const float4*)(p +   aplane);
                    float4 v2 = *(const float4*)(p + 2*aplane);
                    float4 v3 = *(const float4*)(p + 3*aplane);
                    v.x += v1.x+v2.x+v3.x; v.y += v1.y+v2.y+v3.y;
                    v.z += v1.z+v2.z+v3.z; v.w += v1.w+v2.w+v3.w;
                }
            }
            As[(kq*4+0)*BM+row] = v.x; As[(kq*4+1)*BM+row] = v.y;
            As[(kq*4+2)*BM+row] = v.z; As[(kq*4+3)*BM+row] = v.w;
        }
#pragma unroll
        for (int t4 = tid; t4 < BF4; t4 += 256){
            int row = t4 / KQ, kq = t4 % KQ;
            int gcol = n0 + row;
            float4 v = make_float4(0.f,0.f,0.f,0.f);
            if (gcol < N) v = *(const float4*)(Bm + (size_t)gcol*ldb + kt + kq*4);
            Bs[(kq*4+0)*BN+row] = v.x; Bs[(kq*4+1)*BN+row] = v.y;
            Bs[(kq*4+2)*BN+row] = v.z; Bs[(kq*4+3)*BN+row] = v.w;
        }
        __syncthreads();
#pragma unroll
        for (int kk = 0; kk < BK; kk++){
            float af[TM], bf[TN];
#pragma unroll
            for (int i = 0; i < TM; i++) af[i] = As[kk*BM + ty*TM + i];
#pragma unroll
            for (int j = 0; j < TN; j++) bf[j] = Bs[kk*BN + tx*TN + j];
#pragma unroll
            for (int i = 0; i < TM; i++)
#pragma unroll
                for (int j = 0; j < TN; j++)
                    acc[i][j] = fmaf(af[i], bf[j], acc[i][j]);
        }
        __syncthreads();
    }

#pragma unroll
    for (int i = 0; i < TM; i++){
        int row = m0 + ty*TM + i;
        if (row >= M) continue;
#pragma unroll
        for (int j = 0; j < TN; j++){
            int col = n0 + tx*TN + j;
            if (col >= N) continue;
            float r = acc[i][j];
            if (EPI == 0){
                C[(size_t)row*ldc + col] = r;
            } else if (EPI == 1){
                C[(size_t)col*ldc + row] = r;
            } else if (EPI == 2){
                size_t id = (size_t)row*ldc + col;
                C[id] = C[id] + r * scale;
            } else if (EPI == 4){
                float y  = r + e3[col];
                float gp = e1[(size_t)row*CS + col] + e2[col];
                float gg = 1.f / (1.f + __expf(-gp));
                C[(size_t)row*ldc + col] = e0[(size_t)row*CS + col] + gg * y;
            }
        }
    }
}

// -------------------- K3: Q,K,V^T,Gate projections (one launch) -------------
__global__ void qkvg_kernel(const float* __restrict__ Wq, const float* __restrict__ Wk,
                            const float* __restrict__ Wv, const float* __restrict__ Wg){
    __shared__ float As[16*128];
    __shared__ float Bs[16*64];
    int which = blockIdx.z;
    int m0 = blockIdx.y * 128, n0 = blockIdx.x * 64;
    if (which == 2){
        gemm_body<128,64,16,8,4,false,1>(As, Bs, L, CS, CS,
            g_sln, CS, 0, Wv, CS, g_vt, L, m0, n0, 0.f,
            nullptr, nullptr, nullptr, nullptr);
    } else {
        const float* B = (which == 0) ? Wq : (which == 1) ? Wk : Wg;
        float* C = (which == 0) ? g_q : (which == 1) ? g_k : g_gate;
        gemm_body<128,64,16,8,4,false,0>(As, Bs, L, CS, CS,
            g_sln, CS, 0, B, CS, C, CS, m0, n0, 0.f,
            nullptr, nullptr, nullptr, nullptr);
    }
}

// -------------------- K4: logits = Q K^T / sqrt(HD) + bias (in place) -------
__global__ void s_gemm_kernel(){
    __shared__ float As[16*128];
    __shared__ float Bs[16*64];
    int h = blockIdx.z;
    gemm_body<128,64,16,8,4,false,2>(As, Bs, L, L, HD,
        g_q + h*HD, CS, 0, g_k + h*HD, CS,
        g_bias + (size_t)h*LL, L,
        blockIdx.y*128, blockIdx.x*64, 0.14433756729740643f,
        nullptr, nullptr, nullptr, nullptr);
}

// -------------------- K5: row softmax (in place on g_bias) ------------------
__global__ void softmax_kernel(){
    __shared__ float red[8];
    size_t r = blockIdx.x;                    // 6144 rows of 768
    float* row = g_bias + r * L;
    int t = threadIdx.x, lane = t & 31, w = t >> 5;   // 256 threads
    float v[3];
#pragma unroll
    for (int e = 0; e < 3; e++) v[e] = row[t + e*256];
    float m = fmaxf(fmaxf(v[0], v[1]), v[2]);
    m = warp_max(m);
    if (lane == 0) red[w] = m;
    __syncthreads();
    float mm = red[0];
#pragma unroll
    for (int k = 1; k < 8; k++) mm = fmaxf(mm, red[k]);
    __syncthreads();
    float sum = 0.f;
#pragma unroll
    for (int e = 0; e < 3; e++){ v[e] = __expf(v[e] - mm); sum += v[e]; }
    sum = warp_sum(sum);
    if (lane == 0) red[w] = sum;
    __syncthreads();
    float tot = 0.f;
#pragma unroll
    for (int k = 0; k < 8; k++) tot += red[k];
    float inv = 1.f / tot;
#pragma unroll
    for (int e = 0; e < 3; e++) row[t + e*256] = v[e] * inv;
}

// -------------------- K6: O_partial = P @ V (split-K = 4) -------------------
__global__ void pv_kernel(){
    __shared__ float As[16*64];
    __shared__ float Bs[16*64];
    int h  = blockIdx.z >> 2;
    int ks = blockIdx.z & 3;
    gemm_body<64,64,16,4,4,false,0>(As, Bs, L, HD, 192,
        g_bias + (size_t)h*LL + ks*192, L, 0,
        g_vt + (size_t)(h*HD)*L + ks*192, L,
        g_opart + (size_t)ks*OPS + h*HD, CS,
        blockIdx.y*64, 0, 0.f,
        nullptr, nullptr, nullptr, nullptr);
}

// -------------------- K7: out = single + sigmoid(gate+bg)*(O@Wo^T+bo) -------
__global__ void final_kernel(const float* __restrict__ Wo, const float* __restrict__ bo,
                             const float* __restrict__ single, const float* __restrict__ bg,
                             float* __restrict__ out){
    __shared__ float As[16*64];
    __shared__ float Bs[16*64];
    gemm_body<64,64,16,4,4,true,4>(As, Bs, L, CS, CS,
        g_opart, CS, OPS, Wo, CS, out, CS,
        blockIdx.y*64, blockIdx.x*64, 1.f,
        single, g_gate, bg, bo);
}

// -------------------- launch --------------------
extern "C" void kernel_launch(void* const* d_in, const int* in_sizes, int n_in,
                              void* d_out, int out_size){
    const float* single = (const float*)d_in[0];
    const float* pair   = (const float*)d_in[1];
    const float* gs     = (const float*)d_in[2];
    const float* bs     = (const float*)d_in[3];
    const float* gz     = (const float*)d_in[4];
    const float* bz     = (const float*)d_in[5];
    const float* Wq     = (const float*)d_in[6];
    const float* Wk     = (const float*)d_in[7];
    const float* Wv     = (const float*)d_in[8];
    const float* Wb     = (const float*)d_in[9];
    const float* Wo     = (const float*)d_in[10];
    const float* bo     = (const float*)d_in[11];
    const float* Wg     = (const float*)d_in[12];
    const float* bg     = (const float*)d_in[13];
    float* out = (float*)d_out;

    ln_single_kernel<<<L, 128>>>(single, gs, bs);
    ln_pair_bias_kernel<<<dim3(4, L), 512>>>((const float4*)pair, gz, bz, Wb);
    qkvg_kernel<<<dim3(CS/64, L/128, 4), 256>>>(Wq, Wk, Wv, Wg);
    s_gemm_kernel<<<dim3(L/64, L/128, NH), 256>>>();
    softmax_kernel<<<NH*L, 256>>>();
    pv_kernel<<<dim3(1, L/64, 32), 256>>>();
    final_kernel<<<dim3(CS/64, L/64), 256>>>(Wo, bo, single, bg, out);
}

// round 2
// speedup vs baseline: 1.1456x; 1.1456x over previous
#include <cuda_runtime.h>
#include <cuda_bf16.h>
#include <math.h>

// AttentionWithPairBias: B=1, L=768, C_S=384, C_Z=128, H=8, HD=48
// Inputs (metadata order):
// 0 single[1,768,384] 1 pair[1,768,768,128] 2 g_s[384] 3 b_s[384]
// 4 g_z[128] 5 b_z[128] 6 Wq[384,384] 7 Wk 8 Wv 9 Wb[128,8]
// 10 Wo[384,384] 11 bo[384] 12 Wg[384,384] 13 bg[384]
// Output: float32 [1,768,384]

#define L 768
#define CS 384
#define CZ 128
#define NH 8
#define HD 48
#define LL (L*L)                 // 589824
#define OPS (L*CS)               // 294912 (one o-partial plane)

// -------------------- scratch (device globals; no allocs) --------------------
__device__ float g_sln[L*CS];            // layernorm(single)
__device__ float g_bias[(size_t)NH*LL];  // bias -> logits -> probs (in place)
__device__ float g_q[L*CS];
__device__ float g_k[L*CS];
__device__ float g_gate[L*CS];           // s@Wg^T (pre-activation, no bg)
__device__ float g_vt[CS*L];             // V transposed: [n=384][i=768]
__device__ float g_opart[4*OPS];         // split-K partials of attn@V

// -------------------- helpers --------------------
__device__ __forceinline__ float warp_sum(float v){
#pragma unroll
    for (int o = 16; o; o >>= 1) v += __shfl_xor_sync(0xffffffffu, v, o);
    return v;
}
__device__ __forceinline__ float warp_max(float v){
#pragma unroll
    for (int o = 16; o; o >>= 1) v = fmaxf(v, __shfl_xor_sync(0xffffffffu, v, o));
    return v;
}

// Reduce 8 per-lane partial vectors d[0..7] across all 32 lanes, distributing
// results so each lane ends with the TOTAL for head h = bits[4:2] of its lane id.
// 9 SHFL total (vs 40 for 8 naive butterflies).
__device__ __forceinline__ float tree8_distribute(float d[8], int lane){
    const unsigned F = 0xffffffffu;
    {   // fold lane-bit4 <-> value-bit2
        bool up = (lane & 16) != 0;
#pragma unroll
        for (int k = 0; k < 4; k++){
            float send = up ? d[k]   : d[k+4];
            float keep = up ? d[k+4] : d[k];
            d[k] = keep + __shfl_xor_sync(F, send, 16);
        }
    }
    {   // fold lane-bit3 <-> value-bit1
        bool up = (lane & 8) != 0;
#pragma unroll
        for (int k = 0; k < 2; k++){
            float send = up ? d[k]   : d[k+2];
            float keep = up ? d[k+2] : d[k];
            d[k] = keep + __shfl_xor_sync(F, send, 8);
        }
    }
    {   // fold lane-bit2 <-> value-bit0
        bool up = (lane & 4) != 0;
        float send = up ? d[0] : d[1];
        float keep = up ? d[1] : d[0];
        d[0] = keep + __shfl_xor_sync(F, send, 4);
    }
    float v = d[0];
    v += __shfl_xor_sync(F, v, 2);
    v += __shfl_xor_sync(F, v, 1);
    return v;
}

// -------------------- K1: layernorm(single) --------------------
__global__ void ln_single_kernel(const float* __restrict__ x,
                                 const float* __restrict__ g,
                                 const float* __restrict__ b){
    __shared__ float rs[4], rq[4];
    int i = blockIdx.x, t = threadIdx.x;     // 128 threads
    int lane = t & 31, w = t >> 5;
    float v[3];
#pragma unroll
    for (int e = 0; e < 3; e++) v[e] = x[i*CS + e*128 + t];
    float s = v[0] + v[1] + v[2];
    float q = v[0]*v[0] + v[1]*v[1] + v[2]*v[2];
    s = warp_sum(s); q = warp_sum(q);
    if (lane == 0){ rs[w] = s; rq[w] = q; }
    __syncthreads();
    s = rs[0] + rs[1] + rs[2] + rs[3];
    q = rq[0] + rq[1] + rq[2] + rq[3];
    float mu   = s * (1.f/CS);
    float var  = q * (1.f/CS) - mu*mu;
    float rstd = rsqrtf(var + 1e-5f);
#pragma unroll
    for (int e = 0; e < 3; e++){
        int c = e*128 + t;
        g_sln[i*CS + c] = (v[e] - mu) * rstd * g[c] + b[c];
    }
}

// -------------------- K2: layernorm(pair) + bias = zn @ Wb --------------------
// bias_h(i,j) = rstd*(sum_c z_c*gz_c*Wb[c,h]) - rstd*mu*G_h + B_h
// (affine fold of the layernorm into the head projection -> all 10 reductions
//  run concurrently; 19 SHFL per (i,j) instead of 50)
// One block per i (768 blocks, 256 threads = 8 warps, each warp 96 j's).
__global__ void ln_pair_bias_kernel(const float4* __restrict__ z4,
                                    const float* __restrict__ gz,
                                    const float* __restrict__ bz,
                                    const float* __restrict__ Wb){
    __shared__ float stage[8][772];          // padded: bank-conflict-free STS
    const unsigned F = 0xffffffffu;
    const int tid  = threadIdx.x;
    const int warp = tid >> 5, lane = tid & 31;
    const int i    = blockIdx.x;
    const int zb   = lane * 4;

    // per-lane constants: gw[e][h] = gz[c]*Wb[c][h] for my 4 channels
    float gw[4][8];
    float Gp[8] = {0,0,0,0,0,0,0,0};
    float Bp[8] = {0,0,0,0,0,0,0,0};
#pragma unroll
    for (int e = 0; e < 4; e++){
        float gze = gz[zb+e], bze = bz[zb+e];
        float4 w0 = ((const float4*)Wb)[(zb+e)*2 + 0];
        float4 w1 = ((const float4*)Wb)[(zb+e)*2 + 1];
        float w[8] = {w0.x,w0.y,w0.z,w0.w,w1.x,w1.y,w1.z,w1.w};
#pragma unroll
        for (int h = 0; h < 8; h++){
            gw[e][h] = gze * w[h];
            Gp[h] += gw[e][h];
            Bp[h] = fmaf(bze, w[h], Bp[h]);
        }
    }
    // distribute: this lane ends with G/B for head myh = lane bits[4:2]
    float Gh = tree8_distribute(Gp, lane);
    float Bh = tree8_distribute(Bp, lane);
    const int myh = (((lane>>4)&1)<<2) | (((lane>>3)&1)<<1) | ((lane>>2)&1);

    for (int jj = 0; jj < 96; jj++){
        int j = warp*96 + jj;
        float4 zv = z4[((size_t)i*L + j)*32 + lane];
        float z0 = zv.x, z1 = zv.y, z2 = zv.z, z3 = zv.w;
        float s = z0+z1+z2+z3;
        float q = fmaf(z0,z0, fmaf(z1,z1, fmaf(z2,z2, z3*z3)));
        float d[8];
#pragma unroll
        for (int h = 0; h < 8; h++)
            d[h] = fmaf(z3, gw[3][h], fmaf(z2, gw[2][h], fmaf(z1, gw[1][h], z0*gw[0][h])));
#pragma unroll
        for (int o = 16; o; o >>= 1){
            s += __shfl_xor_sync(F, s, o);
            q += __shfl_xor_sync(F, q, o);
        }
        float rd = tree8_distribute(d, lane);
        float mu   = s * (1.f/128.f);
        float var  = q * (1.f/128.f) - mu*mu;
        float rstd = rsqrtf(var + 1e-5f);
        float bias = fmaf(rstd, rd, fmaf(-rstd*mu, Gh, Bh));
        if ((lane & 3) == 0) stage[myh][j] = bias;
    }
    __syncthreads();
    // coalesced write-out: 768 contiguous floats per head plane
#pragma unroll
    for (int t = tid; t < 8*L; t += 256){
        int h = t / L, j = t % L;
        g_bias[(size_t)h*LL + (size_t)i*L + j] = stage[h][j];
    }
}

// -------------------- generic fp32 GEMM body: C = A @ B^T (+ epilogue) -------
// A[M,K] row-major (lda), B[N,K] row-major (ldb). 256 threads.
// EPI: 0 plain store, 1 transposed store C[col][row] (float4, needs TM==4),
//      2 C += acc*scale (bias add), 4 final: C = e0 + sigmoid(e1+e2)*(acc+e3)
template<int BM,int BN,int BK,int TM,int TN,bool SUMA,int EPI>
__device__ __forceinline__ void gemm_body(
    float* As, float* Bs,
    int M, int N, int K,
    const float* __restrict__ A, int lda, size_t aplane,
    const float* __restrict__ Bm, int ldb,
    float* __restrict__ C, int ldc,
    int m0, int n0, float scale,
    const float* __restrict__ e0, const float* __restrict__ e1,
    const float* __restrict__ e2, const float* __restrict__ e3)
{
    constexpr int TX = BN / TN;
    constexpr int TY = BM / TM;
    static_assert(TX * TY == 256, "need 256 threads");
    constexpr int KQ  = BK / 4;
    constexpr int AF4 = BM * KQ;
    constexpr int BF4 = BN * KQ;

    const int tid = threadIdx.x;
    const int tx  = tid % TX, ty = tid / TX;

    float acc[TM][TN];
#pragma unroll
    for (int i = 0; i < TM; i++)
#pragma unroll
        for (int j = 0; j < TN; j++) acc[i][j] = 0.f;

    for (int kt = 0; kt < K; kt += BK){
#pragma unroll
        for (int t4 = tid; t4 < AF4; t4 += 256){
            int row = t4 / KQ, kq = t4 % KQ;
            int grow = m0 + row;
            float4 v = make_float4(0.f,0.f,0.f,0.f);
            if (grow < M){
                const float* p = A + (size_t)grow*lda + kt + kq*4;
                v = *(const float4*)p;
                if (SUMA){
                    float4 v1 = *(const float4*)(p +   aplane);
                    float4 v2 = *(const float4*)(p + 2*aplane);
                    float4 v3 = *(const float4*)(p + 3*aplane);
                    v.x += v1.x+v2.x+v3.x; v.y += v1.y+v2.y+v3.y;
                    v.z += v1.z+v2.z+v3.z; v.w += v1.w+v2.w+v3.w;
                }
            }
            As[(kq*4+0)*BM+row] = v.x; As[(kq*4+1)*BM+row] = v.y;
            As[(kq*4+2)*BM+row] = v.z; As[(kq*4+3)*BM+row] = v.w;
        }
#pragma unroll
        for (int t4 = tid; t4 < BF4; t4 += 256){
            int row = t4 / KQ, kq = t4 % KQ;
            int gcol = n0 + row;
            float4 v = make_float4(0.f,0.f,0.f,0.f);
            if (gcol < N) v = *(const float4*)(Bm + (size_t)gcol*ldb + kt + kq*4);
            Bs[(kq*4+0)*BN+row] = v.x; Bs[(kq*4+1)*BN+row] = v.y;
            Bs[(kq*4+2)*BN+row] = v.z; Bs[(kq*4+3)*BN+row] = v.w;
        }
        __syncthreads();
#pragma unroll
        for (int kk = 0; kk < BK; kk++){
            float af[TM], bf[TN];
#pragma unroll
            for (int i = 0; i < TM; i++) af[i] = As[kk*BM + ty*TM + i];
#pragma unroll
            for (int j = 0; j < TN; j++) bf[j] = Bs[kk*BN + tx*TN + j];
#pragma unroll
            for (int i = 0; i < TM; i++)
#pragma unroll
                for (int j = 0; j < TN; j++)
                    acc[i][j] = fmaf(af[i], bf[j], acc[i][j]);
        }
        __syncthreads();
    }

    if (EPI == 1){
        // transposed store, vectorized over the 4 consecutive rows
#pragma unroll
        for (int j = 0; j < TN; j++){
            int col = n0 + tx*TN + j;
            int row = m0 + ty*TM;
            float4 v = make_float4(acc[0][j], acc[1][j], acc[2][j], acc[3][j]);
            *(float4*)&C[(size_t)col*ldc + row] = v;
        }
        return;
    }
#pragma unroll
    for (int i = 0; i < TM; i++){
        int row = m0 + ty*TM + i;
        if (row >= M) continue;
#pragma unroll
        for (int j = 0; j < TN; j++){
            int col = n0 + tx*TN + j;
            if (col >= N) continue;
            float r = acc[i][j];
            if (EPI == 0){
                C[(size_t)row*ldc + col] = r;
            } else if (EPI == 2){
                size_t id = (size_t)row*ldc + col;
                C[id] = C[id] + r * scale;
            } else if (EPI == 4){
                float y  = r + e3[col];
                float gp = e1[(size_t)row*CS + col] + e2[col];
                float gg = 1.f / (1.f + __expf(-gp));
                C[(size_t)row*ldc + col] = e0[(size_t)row*CS + col] + gg * y;
            }
        }
    }
}

// -------------------- K3: Q,K,V^T,Gate projections (one launch) -------------
__global__ void qkvg_kernel(const float* __restrict__ Wq, const float* __restrict__ Wk,
                            const float* __restrict__ Wv, const float* __restrict__ Wg){
    __shared__ float As[16*64];
    __shared__ float Bs[16*128];
    int which = blockIdx.z;
    int m0 = blockIdx.y * 64, n0 = blockIdx.x * 128;
    if (which == 2){
        gemm_body<64,128,16,4,8,false,1>(As, Bs, L, CS, CS,
            g_sln, CS, 0, Wv, CS, g_vt, L, m0, n0, 0.f,
            nullptr, nullptr, nullptr, nullptr);
    } else {
        const float* B = (which == 0) ? Wq : (which == 1) ? Wk : Wg;
        float* C = (which == 0) ? g_q : (which == 1) ? g_k : g_gate;
        gemm_body<64,128,16,4,8,false,0>(As, Bs, L, CS, CS,
            g_sln, CS, 0, B, CS, C, CS, m0, n0, 0.f,
            nullptr, nullptr, nullptr, nullptr);
    }
}

// -------------------- K4: logits = Q K^T / sqrt(HD) + bias (in place) -------
__global__ void s_gemm_kernel(){
    __shared__ float As[16*64];
    __shared__ float Bs[16*128];
    int h = blockIdx.z;
    gemm_body<64,128,16,4,8,false,2>(As, Bs, L, L, HD,
        g_q + h*HD, CS, 0, g_k + h*HD, CS,
        g_bias + (size_t)h*LL, L,
        blockIdx.y*64, blockIdx.x*128, 0.14433756729740643f,
        nullptr, nullptr, nullptr, nullptr);
}

// -------------------- K5: row softmax (in place on g_bias) ------------------
__global__ void softmax_kernel(){
    __shared__ float red[8];
    size_t r = blockIdx.x;                    // 6144 rows of 768
    float* row = g_bias + r * L;
    int t = threadIdx.x, lane = t & 31, w = t >> 5;   // 256 threads
    float v[3];
#pragma unroll
    for (int e = 0; e < 3; e++) v[e] = row[t + e*256];
    float m = fmaxf(fmaxf(v[0], v[1]), v[2]);
    m = warp_max(m);
    if (lane == 0) red[w] = m;
    __syncthreads();
    float mm = red[0];
#pragma unroll
    for (int k = 1; k < 8; k++) mm = fmaxf(mm, red[k]);
    __syncthreads();
    float sum = 0.f;
#pragma unroll
    for (int e = 0; e < 3; e++){ v[e] = __expf(v[e] - mm); sum += v[e]; }
    sum = warp_sum(sum);
    if (lane == 0) red[w] = sum;
    __syncthreads();
    float tot = 0.f;
#pragma unroll
    for (int k = 0; k < 8; k++) tot += red[k];
    float inv = 1.f / tot;
#pragma unroll
    for (int e = 0; e < 3; e++) row[t + e*256] = v[e] * inv;
}

// -------------------- K6: O_partial = P @ V (split-K = 4) -------------------
__global__ void pv_kernel(){
    __shared__ float As[16*128];
    __shared__ float Bs[16*48];
    int h  = blockIdx.z >> 2;
    int ks = blockIdx.z & 3;
    gemm_body<128,48,16,4,6,false,0>(As, Bs, L, HD, 192,
        g_bias + (size_t)h*LL + ks*192, L, 0,
        g_vt + (size_t)(h*HD)*L + ks*192, L,
        g_opart + (size_t)ks*OPS + h*HD, CS,
        blockIdx.y*128, 0, 0.f,
        nullptr, nullptr, nullptr, nullptr);
}

// -------------------- K7: out = single + sigmoid(gate+bg)*(O@Wo^T+bo) -------
__global__ void final_kernel(const float* __restrict__ Wo, const float* __restrict__ bo,
                             const float* __restrict__ single, const float* __restrict__ bg,
                             float* __restrict__ out){
    __shared__ float As[16*64];
    __shared__ float Bs[16*64];
    gemm_body<64,64,16,4,4,true,4>(As, Bs, L, CS, CS,
        g_opart, CS, OPS, Wo, CS, out, CS,
        blockIdx.y*64, blockIdx.x*64, 1.f,
        single, g_gate, bg, bo);
}

// -------------------- launch --------------------
extern "C" void kernel_launch(void* const* d_in, const int* in_sizes, int n_in,
                              void* d_out, int out_size){
    const float* single = (const float*)d_in[0];
    const float* pair   = (const float*)d_in[1];
    const float* gs     = (const float*)d_in[2];
    const float* bs     = (const float*)d_in[3];
    const float* gz     = (const float*)d_in[4];
    const float* bz     = (const float*)d_in[5];
    const float* Wq     = (const float*)d_in[6];
    const float* Wk     = (const float*)d_in[7];
    const float* Wv     = (const float*)d_in[8];
    const float* Wb     = (const float*)d_in[9];
    const float* Wo     = (const float*)d_in[10];
    const float* bo     = (const float*)d_in[11];
    const float* Wg     = (const float*)d_in[12];
    const float* bg     = (const float*)d_in[13];
    float* out = (float*)d_out;

    ln_single_kernel<<<L, 128>>>(single, gs, bs);
    ln_pair_bias_kernel<<<L, 256>>>((const float4*)pair, gz, bz, Wb);
    qkvg_kernel<<<dim3(CS/128, L/64, 4), 256>>>(Wq, Wk, Wv, Wg);
    s_gemm_kernel<<<dim3(L/128, L/64, NH), 256>>>();
    softmax_kernel<<<NH*L, 256>>>();
    pv_kernel<<<dim3(1, L/128, 32), 256>>>();
    final_kernel<<<dim3(CS/64, L/64), 256>>>(Wo, bo, single, bg, out);
}

// round 3
// speedup vs baseline: 1.3406x; 1.1702x over previous
#include <cuda_runtime.h>
#include <cuda_bf16.h>
#include <math.h>

// AttentionWithPairBias: B=1, L=768, C_S=384, C_Z=128, H=8, HD=48
// Output: float32 [1,768,384]

#define L 768
#define CS 384
#define CZ 128
#define NH 8
#define HD 48
#define LL (L*L)                 // 589824
#define OPS (L*CS)               // 294912 (one o-partial plane)

// -------------------- scratch (device globals; no allocs) --------------------
__device__ float g_sln[L*CS];            // layernorm(single)
__device__ float g_bias[(size_t)NH*LL];  // bias -> logits -> probs (in place)
__device__ float g_q[L*CS];
__device__ float g_k[L*CS];
__device__ float g_gate[L*CS];           // s@Wg^T (pre-activation, no bg)
__device__ float g_vt[CS*L];             // V transposed: [n=384][i=768]
__device__ float g_opart[4*OPS];         // split-K partials of attn@V

// -------------------- helpers --------------------
__device__ __forceinline__ float warp_sum(float v){
#pragma unroll
    for (int o = 16; o; o >>= 1) v += __shfl_xor_sync(0xffffffffu, v, o);
    return v;
}
__device__ __forceinline__ float warp_max(float v){
#pragma unroll
    for (int o = 16; o; o >>= 1) v = fmaxf(v, __shfl_xor_sync(0xffffffffu, v, o));
    return v;
}

// Reduce 8 per-lane partial vectors across lanes; lane ends with total for
// head h = bits[4:2] of lane id. 9 SHFL total.
__device__ __forceinline__ float tree8_distribute(float d[8], int lane){
    const unsigned F = 0xffffffffu;
    {
        bool up = (lane & 16) != 0;
#pragma unroll
        for (int k = 0; k < 4; k++){
            float send = up ? d[k]   : d[k+4];
            float keep = up ? d[k+4] : d[k];
            d[k] = keep + __shfl_xor_sync(F, send, 16);
        }
    }
    {
        bool up = (lane & 8) != 0;
#pragma unroll
        for (int k = 0; k < 2; k++){
            float send = up ? d[k]   : d[k+2];
            float keep = up ? d[k+2] : d[k];
            d[k] = keep + __shfl_xor_sync(F, send, 8);
        }
    }
    {
        bool up = (lane & 4) != 0;
        float send = up ? d[0] : d[1];
        float keep = up ? d[1] : d[0];
        d[0] = keep + __shfl_xor_sync(F, send, 4);
    }
    float v = d[0];
    v += __shfl_xor_sync(F, v, 2);
    v += __shfl_xor_sync(F, v, 1);
    return v;
}

// -------------------- K1: layernorm(single) --------------------
__global__ void ln_single_kernel(const float* __restrict__ x,
                                 const float* __restrict__ g,
                                 const float* __restrict__ b){
    __shared__ float rs[4], rq[4];
    int i = blockIdx.x, t = threadIdx.x;     // 128 threads
    int lane = t & 31, w = t >> 5;
    float v[3];
#pragma unroll
    for (int e = 0; e < 3; e++) v[e] = x[i*CS + e*128 + t];
    float s = v[0] + v[1] + v[2];
    float q = v[0]*v[0] + v[1]*v[1] + v[2]*v[2];
    s = warp_sum(s); q = warp_sum(q);
    if (lane == 0){ rs[w] = s; rq[w] = q; }
    __syncthreads();
    s = rs[0] + rs[1] + rs[2] + rs[3];
    q = rq[0] + rq[1] + rq[2] + rq[3];
    float mu   = s * (1.f/CS);
    float var  = q * (1.f/CS) - mu*mu;
    float rstd = rsqrtf(var + 1e-5f);
#pragma unroll
    for (int e = 0; e < 3; e++){
        int c = e*128 + t;
        g_sln[i*CS + c] = (v[e] - mu) * rstd * g[c] + b[c];
    }
}

// -------------------- K2: layernorm(pair) + bias = zn @ Wb --------------------
__global__ void ln_pair_bias_kernel(const float4* __restrict__ z4,
                                    const float* __restrict__ gz,
                                    const float* __restrict__ bz,
                                    const float* __restrict__ Wb){
    __shared__ float stage[8][772];
    const unsigned F = 0xffffffffu;
    const int tid  = threadIdx.x;
    const int warp = tid >> 5, lane = tid & 31;
    const int i    = blockIdx.x;
    const int zb   = lane * 4;

    float gw[4][8];
    float Gp[8] = {0,0,0,0,0,0,0,0};
    float Bp[8] = {0,0,0,0,0,0,0,0};
#pragma unroll
    for (int e = 0; e < 4; e++){
        float gze = gz[zb+e], bze = bz[zb+e];
        float4 w0 = ((const float4*)Wb)[(zb+e)*2 + 0];
        float4 w1 = ((const float4*)Wb)[(zb+e)*2 + 1];
        float w[8] = {w0.x,w0.y,w0.z,w0.w,w1.x,w1.y,w1.z,w1.w};
#pragma unroll
        for (int h = 0; h < 8; h++){
            gw[e][h] = gze * w[h];
            Gp[h] += gw[e][h];
            Bp[h] = fmaf(bze, w[h], Bp[h]);
        }
    }
    float Gh = tree8_distribute(Gp, lane);
    float Bh = tree8_distribute(Bp, lane);
    const int myh = (((lane>>4)&1)<<2) | (((lane>>3)&1)<<1) | ((lane>>2)&1);

    for (int jj = 0; jj < 96; jj++){
        int j = warp*96 + jj;
        float4 zv = z4[((size_t)i*L + j)*32 + lane];
        float z0 = zv.x, z1 = zv.y, z2 = zv.z, z3 = zv.w;
        float s = z0+z1+z2+z3;
        float q = fmaf(z0,z0, fmaf(z1,z1, fmaf(z2,z2, z3*z3)));
        float d[8];
#pragma unroll
        for (int h = 0; h < 8; h++)
            d[h] = fmaf(z3, gw[3][h], fmaf(z2, gw[2][h], fmaf(z1, gw[1][h], z0*gw[0][h])));
#pragma unroll
        for (int o = 16; o; o >>= 1){
            s += __shfl_xor_sync(F, s, o);
            q += __shfl_xor_sync(F, q, o);
        }
        float rd = tree8_distribute(d, lane);
        float mu   = s * (1.f/128.f);
        float var  = q * (1.f/128.f) - mu*mu;
        float rstd = rsqrtf(var + 1e-5f);
        float bias = fmaf(rstd, rd, fmaf(-rstd*mu, Gh, Bh));
        if ((lane & 3) == 0) stage[myh][j] = bias;
    }
    __syncthreads();
#pragma unroll
    for (int t = tid; t < 8*L; t += 256){
        int h = t / L, j = t % L;
        g_bias[(size_t)h*LL + (size_t)i*L + j] = stage[h][j];
    }
}

// -------------------- GEMM body v2: C = A @ B^T, vectorized smem -----------
// k-major smem tiles with +4 padding; af via 2x LDS.128 (warp-broadcast),
// bf via LDS.128 (TN=4/8) or 3x LDS.64 (TN=6). TM must be 8.
// EPI: 0 store, 1 transposed store (g_vt), 2 C += acc*scale, 4 final epilogue.
template<int BM,int BN,int BK,int TM,int TN,int THREADS,bool SUMA,int EPI>
__device__ __forceinline__ void gemm_body(
    float* As, float* Bs,
    const float* __restrict__ A, int lda, size_t aplane,
    const float* __restrict__ Bm, int ldb,
    float* __restrict__ C, int ldc,
    int m0, int n0, float scale, int K,
    const float* __restrict__ e0, const float* __restrict__ e1,
    const float* __restrict__ e2, const float* __restrict__ e3)
{
    constexpr int TX = BN / TN;
    constexpr int TY = BM / TM;
    static_assert(TX * TY == THREADS, "thread tiling mismatch");
    static_assert(TM == 8, "TM must be 8");
    constexpr int PA = BM + 4;
    constexpr int PB = BN + 4;
    constexpr int KQ  = BK / 4;
    constexpr int AF4 = BM * KQ;
    constexpr int BF4 = BN * KQ;
    constexpr int AIT = (AF4 + THREADS - 1) / THREADS;
    constexpr int BIT = (BF4 + THREADS - 1) / THREADS;

    const int tid = threadIdx.x;
    const int tx  = tid % TX, ty = tid / TX;

    float acc[TM][TN];
#pragma unroll
    for (int i = 0; i < TM; i++)
#pragma unroll
        for (int j = 0; j < TN; j++) acc[i][j] = 0.f;

    for (int kt = 0; kt < K; kt += BK){
#pragma unroll
        for (int u = 0; u < AIT; u++){
            int t4 = tid + u*THREADS;
            if ((AF4 % THREADS == 0) || t4 < AF4){
                int row = t4 / KQ, kq = t4 % KQ;
                const float* p = A + (size_t)(m0 + row)*lda + kt + kq*4;
                float4 v = *(const float4*)p;
                if (SUMA){
                    float4 v1 = *(const float4*)(p +   aplane);
                    float4 v2 = *(const float4*)(p + 2*aplane);
                    float4 v3 = *(const float4*)(p + 3*aplane);
                    v.x += v1.x+v2.x+v3.x; v.y += v1.y+v2.y+v3.y;
                    v.z += v1.z+v2.z+v3.z; v.w += v1.w+v2.w+v3.w;
                }
                As[(kq*4+0)*PA+row] = v.x; As[(kq*4+1)*PA+row] = v.y;
                As[(kq*4+2)*PA+row] = v.z; As[(kq*4+3)*PA+row] = v.w;
            }
        }
#pragma unroll
        for (int u = 0; u < BIT; u++){
            int t4 = tid + u*THREADS;
            if ((BF4 % THREADS == 0) || t4 < BF4){
                int row = t4 / KQ, kq = t4 % KQ;
                float4 v = *(const float4*)(Bm + (size_t)(n0 + row)*ldb + kt + kq*4);
                Bs[(kq*4+0)*PB+row] = v.x; Bs[(kq*4+1)*PB+row] = v.y;
                Bs[(kq*4+2)*PB+row] = v.z; Bs[(kq*4+3)*PB+row] = v.w;
            }
        }
        __syncthreads();
#pragma unroll
        for (int kk = 0; kk < BK; kk++){
            float af[TM], bf[TN];
            *(float4*)&af[0] = *(const float4*)&As[kk*PA + ty*TM];
            *(float4*)&af[4] = *(const float4*)&As[kk*PA + ty*TM + 4];
            if (TN == 4){
                *(float4*)&bf[0] = *(const float4*)&Bs[kk*PB + tx*TN];
            } else if (TN == 8){
                *(float4*)&bf[0] = *(const float4*)&Bs[kk*PB + tx*TN];
                *(float4*)&bf[4] = *(const float4*)&Bs[kk*PB + tx*TN + 4];
            } else {
#pragma unroll
                for (int j = 0; j < TN; j += 2)
                    *(float2*)&bf[j] = *(const float2*)&Bs[kk*PB + tx*TN + j];
            }
#pragma unroll
            for (int i = 0; i < TM; i++)
#pragma unroll
                for (int j = 0; j < TN; j++)
                    acc[i][j] = fmaf(af[i], bf[j], acc[i][j]);
        }
        __syncthreads();
    }

    if (EPI == 1){
        // transposed store into C[col][row], vectorized over 8 rows
#pragma unroll
        for (int j = 0; j < TN; j++){
            int col = n0 + tx*TN + j;
            int row = m0 + ty*TM;
            float4 v0 = make_float4(acc[0][j], acc[1][j], acc[2][j], acc[3][j]);
            float4 v1 = make_float4(acc[4][j], acc[5][j], acc[6][j], acc[7][j]);
            *(float4*)&C[(size_t)col*ldc + row]     = v0;
            *(float4*)&C[(size_t)col*ldc + row + 4] = v1;
        }
        return;
    }
#pragma unroll
    for (int i = 0; i < TM; i++){
        int row = m0 + ty*TM + i;
#pragma unroll
        for (int j = 0; j < TN; j++){
            int col = n0 + tx*TN + j;
            float r = acc[i][j];
            if (EPI == 0){
                C[(size_t)row*ldc + col] = r;
            } else if (EPI == 2){
                size_t id = (size_t)row*ldc + col;
                C[id] = C[id] + r * scale;
            } else if (EPI == 4){
                float y  = r + e3[col];
                float gp = e1[(size_t)row*CS + col] + e2[col];
                float gg = 1.f / (1.f + __expf(-gp));
                C[(size_t)row*ldc + col] = e0[(size_t)row*CS + col] + gg * y;
            }
        }
    }
}

// -------------------- K3: Q,K,V^T,Gate fused (N = 4*384 = 1536) -------------
__global__ void __launch_bounds__(256) qkvg_kernel(
        const float* __restrict__ Wq, const float* __restrict__ Wk,
        const float* __restrict__ Wv, const float* __restrict__ Wg){
    __shared__ float As[32*132];
    __shared__ float Bs[32*68];
    int m0 = blockIdx.y * 128;
    int ng = blockIdx.x * 64;
    int which = ng / 384, n0 = ng % 384;
    const float* B = (which == 0) ? Wq : (which == 1) ? Wk : (which == 2) ? Wv : Wg;
    if (which == 2){
        gemm_body<128,64,32,8,4,256,false,1>(As, Bs, g_sln, CS, 0, B, CS,
            g_vt, L, m0, n0, 0.f, CS, nullptr, nullptr, nullptr, nullptr);
    } else {
        float* C = (which == 0) ? g_q : (which == 1) ? g_k : g_gate;
        gemm_body<128,64,32,8,4,256,false,0>(As, Bs, g_sln, CS, 0, B, CS,
            C, CS, m0, n0, 0.f, CS, nullptr, nullptr, nullptr, nullptr);
    }
}

// -------------------- K4: logits = Q K^T / sqrt(HD) + bias (in place) -------
__global__ void __launch_bounds__(256) s_gemm_kernel(){
    __shared__ float As[48*132];
    __shared__ float Bs[48*68];
    int h = blockIdx.z;
    gemm_body<128,64,48,8,4,256,false,2>(As, Bs,
        g_q + h*HD, CS, 0, g_k + h*HD, CS,
        g_bias + (size_t)h*LL, L,
        blockIdx.y*128, blockIdx.x*64, 0.14433756729740643f, HD,
        nullptr, nullptr, nullptr, nullptr);
}

// -------------------- K5: row softmax (in place on g_bias) ------------------
__global__ void softmax_kernel(){
    __shared__ float red[8];
    size_t r = blockIdx.x;
    float* row = g_bias + r * L;
    int t = threadIdx.x, lane = t & 31, w = t >> 5;   // 256 threads
    float v[3];
#pragma unroll
    for (int e = 0; e < 3; e++) v[e] = row[t + e*256];
    float m = fmaxf(fmaxf(v[0], v[1]), v[2]);
    m = warp_max(m);
    if (lane == 0) red[w] = m;
    __syncthreads();
    float mm = red[0];
#pragma unroll
    for (int k = 1; k < 8; k++) mm = fmaxf(mm, red[k]);
    __syncthreads();
    float sum = 0.f;
#pragma unroll
    for (int e = 0; e < 3; e++){ v[e] = __expf(v[e] - mm); sum += v[e]; }
    sum = warp_sum(sum);
    if (lane == 0) red[w] = sum;
    __syncthreads();
    float tot = 0.f;
#pragma unroll
    for (int k = 0; k < 8; k++) tot += red[k];
    float inv = 1.f / tot;
#pragma unroll
    for (int e = 0; e < 3; e++) row[t + e*256] = v[e] * inv;
}

// -------------------- K6: O_partial = P @ V (split-K = 4) -------------------
__global__ void __launch_bounds__(128) pv_kernel(){
    __shared__ float As[32*132];
    __shared__ float Bs[32*52];
    int h  = blockIdx.z >> 2;
    int ks = blockIdx.z & 3;
    gemm_body<128,48,32,8,6,128,false,0>(As, Bs,
        g_bias + (size_t)h*LL + ks*192, L, 0,
        g_vt + (size_t)(h*HD)*L + ks*192, L,
        g_opart + (size_t)ks*OPS + h*HD, CS,
        blockIdx.y*128, 0, 0.f, 192,
        nullptr, nullptr, nullptr, nullptr);
}

// -------------------- K7: out = single + sigmoid(gate+bg)*(O@Wo^T+bo) -------
__global__ void __launch_bounds__(128) final_kernel(
        const float* __restrict__ Wo, const float* __restrict__ bo,
        const float* __restrict__ single, const float* __restrict__ bg,
        float* __restrict__ out){
    __shared__ float As[32*68];
    __shared__ float Bs[32*68];
    gemm_body<64,64,32,8,4,128,true,4>(As, Bs,
        g_opart, CS, OPS, Wo, CS, out, CS,
        blockIdx.y*64, blockIdx.x*64, 1.f, CS,
        single, g_gate, bg, bo);
}

// -------------------- launch --------------------
extern "C" void kernel_launch(void* const* d_in, const int* in_sizes, int n_in,
                              void* d_out, int out_size){
    const float* single = (const float*)d_in[0];
    const float* pair   = (const float*)d_in[1];
    const float* gs     = (const float*)d_in[2];
    const float* bs     = (const float*)d_in[3];
    const float* gz     = (const float*)d_in[4];
    const float* bz     = (const float*)d_in[5];
    const float* Wq     = (const float*)d_in[6];
    const float* Wk     = (const float*)d_in[7];
    const float* Wv     = (const float*)d_in[8];
    const float* Wb     = (const float*)d_in[9];
    const float* Wo     = (const float*)d_in[10];
    const float* bo     = (const float*)d_in[11];
    const float* Wg     = (const float*)d_in[12];
    const float* bg     = (const float*)d_in[13];
    float* out = (float*)d_out;

    ln_single_kernel<<<L, 128>>>(single, gs, bs);
    ln_pair_bias_kernel<<<L, 256>>>((const float4*)pair, gz, bz, Wb);
    qkvg_kernel<<<dim3(1536/64, L/128), 256>>>(Wq, Wk, Wv, Wg);
    s_gemm_kernel<<<dim3(L/64, L/128, NH), 256>>>();
    softmax_kernel<<<NH*L, 256>>>();
    pv_kernel<<<dim3(1, L/128, 32), 128>>>();
    final_kernel<<<dim3(CS/64, L/64), 128>>>(Wo, bo, single, bg, out);
}

// round 6
// speedup vs baseline: 1.4105x; 1.0521x over previous
#include <cuda_runtime.h>
#include <cuda_bf16.h>
#include <cstdint>
#include <math.h>

// AttentionWithPairBias: B=1, L=768, C_S=384, C_Z=128, H=8, HD=48
#define L 768
#define CS 384
#define NH 8
#define HD 48
#define LL (L*L)
#define OPS (L*CS)

// -------------------- scratch (device globals; no allocs) --------------------
__device__ float g_bias[(size_t)NH*LL];  // bias -> logits -> probs (in place)
__device__ float g_gate[L*CS];
__device__ float g_vt[CS*L];             // V transposed: [n][i]
__device__ float g_opart[4*OPS];
__device__ __nv_bfloat16 g_ah[L*CS], g_al[L*CS];         // layernorm(single) hi/lo
__device__ __nv_bfloat16 g_wh[4*CS*CS], g_wl[4*CS*CS];   // Wq|Wk|Wv|Wg rows, hi/lo
__device__ __nv_bfloat16 g_qh[L*CS], g_ql[L*CS];         // Q hi/lo
__device__ __nv_bfloat16 g_kh[L*CS], g_kl[L*CS];         // K hi/lo

// -------------------- warp helpers --------------------
__device__ __forceinline__ float warp_sum(float v){
#pragma unroll
    for (int o = 16; o; o >>= 1) v += __shfl_xor_sync(0xffffffffu, v, o);
    return v;
}
__device__ __forceinline__ float warp_max(float v){
#pragma unroll
    for (int o = 16; o; o >>= 1) v = fmaxf(v, __shfl_xor_sync(0xffffffffu, v, o));
    return v;
}
__device__ __forceinline__ float tree8_distribute(float d[8], int lane){
    const unsigned F = 0xffffffffu;
    {
        bool up = (lane & 16) != 0;
#pragma unroll
        for (int k = 0; k < 4; k++){
            float send = up ? d[k]   : d[k+4];
            float keep = up ? d[k+4] : d[k];
            d[k] = keep + __shfl_xor_sync(F, send, 16);
        }
    }
    {
        bool up = (lane & 8) != 0;
#pragma unroll
        for (int k = 0; k < 2; k++){
            float send = up ? d[k]   : d[k+2];
            float keep = up ? d[k+2] : d[k];
            d[k] = keep + __shfl_xor_sync(F, send, 8);
        }
    }
    {
        bool up = (lane & 4) != 0;
        float send = up ? d[0] : d[1];
        float keep = up ? d[1] : d[0];
        d[0] = keep + __shfl_xor_sync(F, send, 4);
    }
    float v = d[0];
    v += __shfl_xor_sync(F, v, 2);
    v += __shfl_xor_sync(F, v, 1);
    return v;
}

// -------------------- mma.sync / ldmatrix primitives (plain PTX, sm_80+) ----
__device__ __forceinline__ uint32_t smem_u32(const void* p){
    uint32_t a;
    asm("{ .reg .u64 t; cvta.to.shared.u64 t, %1; cvt.u32.u64 %0, t; }" : "=r"(a) : "l"(p));
    return a;
}
__device__ __forceinline__ void ldsm4(uint32_t* r, uint32_t addr){
    asm volatile("ldmatrix.sync.aligned.m8n8.x4.shared.b16 {%0,%1,%2,%3}, [%4];"
        : "=r"(r[0]), "=r"(r[1]), "=r"(r[2]), "=r"(r[3]) : "r"(addr));
}
__device__ __forceinline__ void mma16816(float* c, const uint32_t* a, const uint32_t* b){
    asm volatile(
        "mma.sync.aligned.m16n8k16.row.col.f32.bf16.bf16.f32 "
        "{%0,%1,%2,%3}, {%4,%5,%6,%7}, {%8,%9}, {%0,%1,%2,%3};"
        : "+f"(c[0]), "+f"(c[1]), "+f"(c[2]), "+f"(c[3])
        : "r"(a[0]), "r"(a[1]), "r"(a[2]), "r"(a[3]), "r"(b[0]), "r"(b[1]));
}

// smem slab layout: one k16 slab = ROWS rows x 16 bf16, row pitch 48 bytes
// (8 ldmatrix row addresses hit 8 distinct 16B granules mod 128 -> conflict-free)
#define SLA (128*48)
#define SLB (64*48)

// load one plane (NSLAB k16-slabs x ROWS rows) from global bf16 (row-major, ld)
template<int ROWS, int NSLAB>
__device__ __forceinline__ void load_plane(char* dst, const __nv_bfloat16* src,
                                           int ld, int tid){
    constexpr int CH = ROWS * NSLAB * 2;         // 16B chunks
#pragma unroll
    for (int idx = tid; idx < CH; idx += 256){
        int r  = idx / (NSLAB*2);
        int cc = idx - r*(NSLAB*2);
        int s = cc >> 1, c = cc & 1;
        *(uint4*)(dst + s*(ROWS*48) + r*48 + c*16) =
            *(const uint4*)(src + (size_t)r*ld + s*16 + c*8);
    }
}

// A-fragment ldmatrix addr: plane slab base, warp m-offset wm32, mt (0/1)
__device__ __forceinline__ void ldA(uint32_t a[4], uint32_t slab, int wm32, int mt, int t){
    ldsm4(a, slab + (uint32_t)((wm32 + mt*16 + (t & 15))*48 + (t >> 4)*16));
}
// B-fragment x4: covers 16 n (2 ntiles); nb16 = warp n-offset + pair*16
__device__ __forceinline__ void ldB(uint32_t b[4], uint32_t slab, int nb16, int t){
    ldsm4(b, slab + (uint32_t)((nb16 + ((t >> 4) << 3) + (t & 7))*48 + ((t >> 3) & 1)*16));
}

// -------------------- K0: split Wq|Wk|Wv|Wg into bf16 hi/lo ------------------
__global__ void conv_w_kernel(const float* __restrict__ Wq, const float* __restrict__ Wk,
                              const float* __restrict__ Wv, const float* __restrict__ Wg){
    int idx = blockIdx.x*256 + threadIdx.x;       // 147456 float4 slots
    int n  = idx / 96;
    int kq = idx - n*96;
    int which = n / 384;
    int r = n - which*384;
    const float* W = (which == 0) ? Wq : (which == 1) ? Wk : (which == 2) ? Wv : Wg;
    float4 v = *(const float4*)(W + (size_t)r*CS + kq*4);
    float x[4] = {v.x, v.y, v.z, v.w};
    __nv_bfloat16 h[4], l[4];
#pragma unroll
    for (int e = 0; e < 4; e++){
        h[e] = __float2bfloat16(x[e]);
        l[e] = __float2bfloat16(x[e] - __bfloat162float(h[e]));
    }
    size_t o = (size_t)n*CS + kq*4;
    *(__nv_bfloat162*)(g_wh + o)     = __halves2bfloat162(h[0], h[1]);
    *(__nv_bfloat162*)(g_wh + o + 2) = __halves2bfloat162(h[2], h[3]);
    *(__nv_bfloat162*)(g_wl + o)     = __halves2bfloat162(l[0], l[1]);
    *(__nv_bfloat162*)(g_wl + o + 2) = __halves2bfloat162(l[2], l[3]);
}

// -------------------- K1: layernorm(single) -> bf16 hi/lo --------------------
__global__ void ln_single_kernel(const float* __restrict__ x,
                                 const float* __restrict__ g,
                                 const float* __restrict__ b){
    __shared__ float rs[4], rq[4];
    int i = blockIdx.x, t = threadIdx.x;     // 128 threads
    int lane = t & 31, w = t >> 5;
    float v[3];
#pragma unroll
    for (int e = 0; e < 3; e++) v[e] = x[i*CS + e*128 + t];
    float s = v[0] + v[1] + v[2];
    float q = v[0]*v[0] + v[1]*v[1] + v[2]*v[2];
    s = warp_sum(s); q = warp_sum(q);
    if (lane == 0){ rs[w] = s; rq[w] = q; }
    __syncthreads();
    s = rs[0] + rs[1] + rs[2] + rs[3];
    q = rq[0] + rq[1] + rq[2] + rq[3];
    float mu   = s * (1.f/CS);
    float var  = q * (1.f/CS) - mu*mu;
    float rstd = rsqrtf(var + 1e-5f);
#pragma unroll
    for (int e = 0; e < 3; e++){
        int c = e*128 + t;
        float y = (v[e] - mu) * rstd * g[c] + b[c];
        __nv_bfloat16 hh = __float2bfloat16(y);
        g_ah[i*CS + c] = hh;
        g_al[i*CS + c] = __float2bfloat16(y - __bfloat162float(hh));
    }
}

// -------------------- K2: layernorm(pair) + bias = zn @ Wb -------------------
__global__ void ln_pair_bias_kernel(const float4* __restrict__ z4,
                                    const float* __restrict__ gz,
                                    const float* __restrict__ bz,
                                    const float* __restrict__ Wb){
    __shared__ float stage[8][772];
    const unsigned F = 0xffffffffu;
    const int tid  = threadIdx.x;
    const int warp = tid >> 5, lane = tid & 31;
    const int i    = blockIdx.x;
    const int zb   = lane * 4;

    float gw[4][8];
    float Gp[8] = {0,0,0,0,0,0,0,0};
    float Bp[8] = {0,0,0,0,0,0,0,0};
#pragma unroll
    for (int e = 0; e < 4; e++){
        float gze = gz[zb+e], bze = bz[zb+e];
        float4 w0 = ((const float4*)Wb)[(zb+e)*2 + 0];
        float4 w1 = ((const float4*)Wb)[(zb+e)*2 + 1];
        float w[8] = {w0.x,w0.y,w0.z,w0.w,w1.x,w1.y,w1.z,w1.w};
#pragma unroll
        for (int h = 0; h < 8; h++){
            gw[e][h] = gze * w[h];
            Gp[h] += gw[e][h];
            Bp[h] = fmaf(bze, w[h], Bp[h]);
        }
    }
    float Gh = tree8_distribute(Gp, lane);
    float Bh = tree8_distribute(Bp, lane);
    const int myh = (((lane>>4)&1)<<2) | (((lane>>3)&1)<<1) | ((lane>>2)&1);

    for (int jj = 0; jj < 96; jj++){
        int j = warp*96 + jj;
        float4 zv = z4[((size_t)i*L + j)*32 + lane];
        float z0 = zv.x, z1 = zv.y, z2 = zv.z, z3 = zv.w;
        float s = z0+z1+z2+z3;
        float q = fmaf(z0,z0, fmaf(z1,z1, fmaf(z2,z2, z3*z3)));
        float d[8];
#pragma unroll
        for (int h = 0; h < 8; h++)
            d[h] = fmaf(z3, gw[3][h], fmaf(z2, gw[2][h], fmaf(z1, gw[1][h], z0*gw[0][h])));
#pragma unroll
        for (int o = 16; o; o >>= 1){
            s += __shfl_xor_sync(F, s, o);
            q += __shfl_xor_sync(F, q, o);
        }
        float rd = tree8_distribute(d, lane);
        float mu   = s * (1.f/128.f);
        float var  = q * (1.f/128.f) - mu*mu;
        float rstd = rsqrtf(var + 1e-5f);
        float bias = fmaf(rstd, rd, fmaf(-rstd*mu, Gh, Bh));
        if ((lane & 3) == 0) stage[myh][j] = bias;
    }
    __syncthreads();
#pragma unroll
    for (int t = tid; t < 8*L; t += 256){
        int h = t / L, j = t % L;
        g_bias[(size_t)h*LL + (size_t)i*L + j] = stage[h][j];
    }
}

// -------------------- K3: Q,K,V^T,Gate via mma.sync bf16-split --------------
// C = sln @ W^T. Block 128x64, 8 warps (warp tile 32x32). K=384 in 12 chunks.
__global__ void __launch_bounds__(256) qkvg_mma(){
    __shared__ char sm[4*SLA + 4*SLB];   // A hi(2 slabs), A lo(2), B hi(2), B lo(2)
    char* pAH = sm;
    char* pAL = sm + 2*SLA;
    char* pBH = sm + 4*SLA;
    char* pBL = sm + 4*SLA + 2*SLB;
    const uint32_t uAH = smem_u32(pAH), uAL = smem_u32(pAL);
    const uint32_t uBH = smem_u32(pBH), uBL = smem_u32(pBL);

    const int tid = threadIdx.x, lane = tid & 31, wid = tid >> 5;
    const int wm32 = (wid & 3) * 32, wn32 = (wid >> 2) * 32;
    const int m0 = blockIdx.y * 128;
    const int ng = blockIdx.x * 64;

    float acc[2][4][4];
#pragma unroll
    for (int a = 0; a < 2; a++)
#pragma unroll
        for (int b = 0; b < 4; b++)
#pragma unroll
            for (int c = 0; c < 4; c++) acc[a][b][c] = 0.f;

    for (int ch = 0; ch < 12; ch++){
        int koff = ch * 32;
        if (ch) __syncthreads();
        load_plane<128,2>(pAH, g_ah + (size_t)m0*CS + koff, CS, tid);
        load_plane<128,2>(pAL, g_al + (size_t)m0*CS + koff, CS, tid);
        load_plane<64,2>(pBH, g_wh + (size_t)ng*CS + koff, CS, tid);
        load_plane<64,2>(pBL, g_wl + (size_t)ng*CS + koff, CS, tid);
        __syncthreads();
#pragma unroll
        for (int s = 0; s < 2; s++){
            uint32_t ah[2][4], al[2][4], bh[2][4], bl[2][4];
#pragma unroll
            for (int mt = 0; mt < 2; mt++){
                ldA(ah[mt], uAH + s*SLA, wm32, mt, lane);
                ldA(al[mt], uAL + s*SLA, wm32, mt, lane);
            }
#pragma unroll
            for (int pr = 0; pr < 2; pr++){
                ldB(bh[pr], uBH + s*SLB, wn32 + pr*16, lane);
                ldB(bl[pr], uBL + s*SLB, wn32 + pr*16, lane);
            }
#pragma unroll
            for (int mt = 0; mt < 2; mt++)
#pragma unroll
                for (int nt = 0; nt < 4; nt++){
                    const uint32_t* bhp = &bh[nt>>1][(nt&1)*2];
                    const uint32_t* blp = &bl[nt>>1][(nt&1)*2];
                    mma16816(acc[mt][nt], ah[mt], bhp);
                    mma16816(acc[mt][nt], ah[mt], blp);
                    mma16816(acc[mt][nt], al[mt], bhp);
                }
        }
    }

    // epilogue
    const int which = ng / 384;
    const int nloc  = ng - which*384;
    const int rb = m0 + wm32 + (lane >> 2);
    const int cb = wn32 + (lane & 3)*2;
    if (which <= 1){
        __nv_bfloat16* PH = which ? g_kh : g_qh;
        __nv_bfloat16* PL = which ? g_kl : g_ql;
#pragma unroll
        for (int mt = 0; mt < 2; mt++)
#pragma unroll
            for (int half = 0; half < 2; half++){
                int i = rb + mt*16 + half*8;
#pragma unroll
                for (int nt = 0; nt < 4; nt++){
                    int cg = nloc + cb + nt*8;
                    float v0 = acc[mt][nt][half*2], v1 = acc[mt][nt][half*2+1];
                    __nv_bfloat16 h0 = __float2bfloat16(v0);
                    __nv_bfloat16 h1 = __float2bfloat16(v1);
                    __nv_bfloat16 l0 = __float2bfloat16(v0 - __bfloat162float(h0));
                    __nv_bfloat16 l1 = __float2bfloat16(v1 - __bfloat162float(h1));
                    *(__nv_bfloat162*)(PH + (size_t)i*CS + cg) = __halves2bfloat162(h0, h1);
                    *(__nv_bfloat162*)(PL + (size_t)i*CS + cg) = __halves2bfloat162(l0, l1);
                }
            }
    } else if (which == 2){
#pragma unroll
        for (int mt = 0; mt < 2; mt++)
#pragma unroll
            for (int half = 0; half < 2; half++){
                int i = rb + mt*16 + half*8;
#pragma unroll
                for (int nt = 0; nt < 4; nt++){
                    int cg = nloc + cb + nt*8;
                    g_vt[(size_t)cg*L + i]     = acc[mt][nt][half*2];
                    g_vt[(size_t)(cg+1)*L + i] = acc[mt][nt][half*2+1];
                }
            }
    } else {
#pragma unroll
        for (int mt = 0; mt < 2; mt++)
#pragma unroll
            for (int half = 0; half < 2; half++){
                int i = rb + mt*16 + half*8;
#pragma unroll
                for (int nt = 0; nt < 4; nt++){
                    int cg = nloc + cb + nt*8;
                    float2 v = make_float2(acc[mt][nt][half*2], acc[mt][nt][half*2+1]);
                    *(float2*)(g_gate + (size_t)i*CS + cg) = v;
                }
            }
    }
}

// -------------------- K4: logits = Q K^T / sqrt(HD) + bias (mma) ------------
__global__ void __launch_bounds__(256) s_mma(){
    __shared__ char sm[6*SLA + 3*SLB];   // A hi(3), A lo(3), B(3, reloaded)
    char* pAH = sm;
    char* pAL = sm + 3*SLA;
    char* pB  = sm + 6*SLA;
    const uint32_t uAH = smem_u32(pAH), uAL = smem_u32(pAL), uB = smem_u32(pB);

    const int tid = threadIdx.x, lane = tid & 31, wid = tid >> 5;
    const int wm32 = (wid & 3) * 32, wn32 = (wid >> 2) * 32;
    const int n0 = blockIdx.x * 64;
    const int m0 = blockIdx.y * 128;
    const int h  = blockIdx.z;

    float acc[2][4][4];
#pragma unroll
    for (int a = 0; a < 2; a++)
#pragma unroll
        for (int b = 0; b < 4; b++)
#pragma unroll
            for (int c = 0; c < 4; c++) acc[a][b][c] = 0.f;

    load_plane<128,3>(pAH, g_qh + (size_t)m0*CS + h*HD, CS, tid);
    load_plane<128,3>(pAL, g_ql + (size_t)m0*CS + h*HD, CS, tid);
    load_plane<64,3>(pB,  g_kh + (size_t)n0*CS + h*HD, CS, tid);
    __syncthreads();
#pragma unroll
    for (int s = 0; s < 3; s++){
        uint32_t ah[2][4], al[2][4], bh[2][4];
#pragma unroll
        for (int mt = 0; mt < 2; mt++){
            ldA(ah[mt], uAH + s*SLA, wm32, mt, lane);
            ldA(al[mt], uAL + s*SLA, wm32, mt, lane);
        }
#pragma unroll
        for (int pr = 0; pr < 2; pr++)
            ldB(bh[pr], uB + s*SLB, wn32 + pr*16, lane);
#pragma unroll
        for (int mt = 0; mt < 2; mt++)
#pragma unroll
            for (int nt = 0; nt < 4; nt++){
                const uint32_t* bp = &bh[nt>>1][(nt&1)*2];
                mma16816(acc[mt][nt], ah[mt], bp);
                mma16816(acc[mt][nt], al[mt], bp);
            }
    }
    __syncthreads();
    load_plane<64,3>(pB, g_kl + (size_t)n0*CS + h*HD, CS, tid);
    __syncthreads();
#pragma unroll
    for (int s = 0; s < 3; s++){
        uint32_t ah[2][4], bl[2][4];
#pragma unroll
        for (int mt = 0; mt < 2; mt++)
            ldA(ah[mt], uAH + s*SLA, wm32, mt, lane);
#pragma unroll
        for (int pr = 0; pr < 2; pr++)
            ldB(bl[pr], uB + s*SLB, wn32 + pr*16, lane);
#pragma unroll
        for (int mt = 0; mt < 2; mt++)
#pragma unroll
            for (int nt = 0; nt < 4; nt++)
                mma16816(acc[mt][nt], ah[mt], &bl[nt>>1][(nt&1)*2]);
    }

    // epilogue: g_bias += acc * 1/sqrt(48)
    const float sc = 0.14433756729740643f;
    const int rb = m0 + wm32 + (lane >> 2);
    const int cb = n0 + wn32 + (lane & 3)*2;
#pragma unroll
    for (int mt = 0; mt < 2; mt++)
#pragma unroll
        for (int half = 0; half < 2; half++){
            int i = rb + mt*16 + half*8;
            float* bp = g_bias + (size_t)h*LL + (size_t)i*L;
#pragma unroll
            for (int nt = 0; nt < 4; nt++){
                int cg = cb + nt*8;
                float2 b = *(float2*)(bp + cg);
                b.x = fmaf(acc[mt][nt][half*2],   sc, b.x);
                b.y = fmaf(acc[mt][nt][half*2+1], sc, b.y);
                *(float2*)(bp + cg) = b;
            }
        }
}

// -------------------- FFMA GEMM body (pv / final) ---------------------------
template<int BM,int BN,int BK,int TM,int TN,int THREADS,bool SUMA,int EPI>
__device__ __forceinline__ void gemm_body(
    float* As, float* Bs,
    const float* __restrict__ A, int lda, size_t aplane,
    const float* __restrict__ Bm, int ldb,
    float* __restrict__ C, int ldc,
    int m0, int n0, float scale, int K,
    const float* __restrict__ e0, const float* __restrict__ e1,
    const float* __restrict__ e2, const float* __restrict__ e3)
{
    constexpr int TX = BN / TN;
    constexpr int TY = BM / TM;
    static_assert(TX * TY == THREADS, "thread tiling mismatch");
    static_assert(TM == 8, "TM must be 8");
    constexpr int PA = BM + 4;
    constexpr int PB = BN + 4;
    constexpr int KQ  = BK / 4;
    constexpr int AF4 = BM * KQ;
    constexpr int BF4 = BN * KQ;
    constexpr int AIT = (AF4 + THREADS - 1) / THREADS;
    constexpr int BIT = (BF4 + THREADS - 1) / THREADS;

    const int tid = threadIdx.x;
    const int tx  = tid % TX, ty = tid / TX;

    float acc[TM][TN];
#pragma unroll
    for (int i = 0; i < TM; i++)
#pragma unroll
        for (int j = 0; j < TN; j++) acc[i][j] = 0.f;

    for (int kt = 0; kt < K; kt += BK){
#pragma unroll
        for (int u = 0; u < AIT; u++){
            int t4 = tid + u*THREADS;
            if ((AF4 % THREADS == 0) || t4 < AF4){
                int row = t4 / KQ, kq = t4 % KQ;
                const float* p = A + (size_t)(m0 + row)*lda + kt + kq*4;
                float4 v = *(const float4*)p;
                if (SUMA){
                    float4 v1 = *(const float4*)(p +   aplane);
                    float4 v2 = *(const float4*)(p + 2*aplane);
                    float4 v3 = *(const float4*)(p + 3*aplane);
                    v.x += v1.x+v2.x+v3.x; v.y += v1.y+v2.y+v3.y;
                    v.z += v1.z+v2.z+v3.z; v.w += v1.w+v2.w+v3.w;
                }
                As[(kq*4+0)*PA+row] = v.x; As[(kq*4+1)*PA+row] = v.y;
                As[(kq*4+2)*PA+row] = v.z; As[(kq*4+3)*PA+row] = v.w;
            }
        }
#pragma unroll
        for (int u = 0; u < BIT; u++){
            int t4 = tid + u*THREADS;
            if ((BF4 % THREADS == 0) || t4 < BF4){
                int row = t4 / KQ, kq = t4 % KQ;
                float4 v = *(const float4*)(Bm + (size_t)(n0 + row)*ldb + kt + kq*4);
                Bs[(kq*4+0)*PB+row] = v.x; Bs[(kq*4+1)*PB+row] = v.y;
                Bs[(kq*4+2)*PB+row] = v.z; Bs[(kq*4+3)*PB+row] = v.w;
            }
        }
        __syncthreads();
#pragma unroll
        for (int kk = 0; kk < BK; kk++){
            float af[TM], bf[TN];
            *(float4*)&af[0] = *(const float4*)&As[kk*PA + ty*TM];
            *(float4*)&af[4] = *(const float4*)&As[kk*PA + ty*TM + 4];
            if (TN == 4){
                *(float4*)&bf[0] = *(const float4*)&Bs[kk*PB + tx*TN];
            } else {
#pragma unroll
                for (int j = 0; j < TN; j += 2)
                    *(float2*)&bf[j] = *(const float2*)&Bs[kk*PB + tx*TN + j];
            }
#pragma unroll
            for (int i = 0; i < TM; i++)
#pragma unroll
                for (int j = 0; j < TN; j++)
                    acc[i][j] = fmaf(af[i], bf[j], acc[i][j]);
        }
        __syncthreads();
    }

#pragma unroll
    for (int i = 0; i < TM; i++){
        int row = m0 + ty*TM + i;
#pragma unroll
        for (int j = 0; j < TN; j++){
            int col = n0 + tx*TN + j;
            float r = acc[i][j];
            if (EPI == 0){
                C[(size_t)row*ldc + col] = r;
            } else if (EPI == 4){
                float y  = r + e3[col];
                float gp = e1[(size_t)row*CS + col] + e2[col];
                float gg = 1.f / (1.f + __expf(-gp));
                C[(size_t)row*ldc + col] = e0[(size_t)row*CS + col] + gg * y;
            }
        }
    }
}

// -------------------- K5: row softmax (in place on g_bias) ------------------
__global__ void softmax_kernel(){
    __shared__ float red[8];
    size_t r = blockIdx.x;
    float* row = g_bias + r * L;
    int t = threadIdx.x, lane = t & 31, w = t >> 5;   // 256 threads
    float v[3];
#pragma unroll
    for (int e = 0; e < 3; e++) v[e] = row[t + e*256];
    float m = fmaxf(fmaxf(v[0], v[1]), v[2]);
    m = warp_max(m);
    if (lane == 0) red[w] = m;
    __syncthreads();
    float mm = red[0];
#pragma unroll
    for (int k = 1; k < 8; k++) mm = fmaxf(mm, red[k]);
    __syncthreads();
    float sum = 0.f;
#pragma unroll
    for (int e = 0; e < 3; e++){ v[e] = __expf(v[e] - mm); sum += v[e]; }
    sum = warp_sum(sum);
    if (lane == 0) red[w] = sum;
    __syncthreads();
    float tot = 0.f;
#pragma unroll
    for (int k = 0; k < 8; k++) tot += red[k];
    float inv = 1.f / tot;
#pragma unroll
    for (int e = 0; e < 3; e++) row[t + e*256] = v[e] * inv;
}

// -------------------- K6: O_partial = P @ V (split-K = 4) -------------------
__global__ void __launch_bounds__(128) pv_kernel(){
    __shared__ float As[32*132];
    __shared__ float Bs[32*52];
    int h  = blockIdx.z >> 2;
    int ks = blockIdx.z & 3;
    gemm_body<128,48,32,8,6,128,false,0>(As, Bs,
        g_bias + (size_t)h*LL + ks*192, L, 0,
        g_vt + (size_t)(h*HD)*L + ks*192, L,
        g_opart + (size_t)ks*OPS + h*HD, CS,
        blockIdx.y*128, 0, 0.f, 192,
        nullptr, nullptr, nullptr, nullptr);
}

// -------------------- K7: out = single + sigmoid(gate+bg)*(O@Wo^T+bo) -------
__global__ void __launch_bounds__(128) final_kernel(
        const float* __restrict__ Wo, const float* __restrict__ bo,
        const float* __restrict__ single, const float* __restrict__ bg,
        float* __restrict__ out){
    __shared__ float As[32*68];
    __shared__ float Bs[32*68];
    gemm_body<64,64,32,8,4,128,true,4>(As, Bs,
        g_opart, CS, OPS, Wo, CS, out, CS,
        blockIdx.y*64, blockIdx.x*64, 1.f, CS,
        single, g_gate, bg, bo);
}

// -------------------- launch --------------------
extern "C" void kernel_launch(void* const* d_in, const int* in_sizes, int n_in,
                              void* d_out, int out_size){
    const float* single = (const float*)d_in[0];
    const float* pair   = (const float*)d_in[1];
    const float* gs     = (const float*)d_in[2];
    const float* bs     = (const float*)d_in[3];
    const float* gz     = (const float*)d_in[4];
    const float* bz     = (const float*)d_in[5];
    const float* Wq     = (const float*)d_in[6];
    const float* Wk     = (const float*)d_in[7];
    const float* Wv     = (const float*)d_in[8];
    const float* Wb     = (const float*)d_in[9];
    const float* Wo     = (const float*)d_in[10];
    const float* bo     = (const float*)d_in[11];
    const float* Wg     = (const float*)d_in[12];
    const float* bg     = (const float*)d_in[13];
    float* out = (float*)d_out;

    conv_w_kernel<<<576, 256>>>(Wq, Wk, Wv, Wg);
    ln_single_kernel<<<L, 128>>>(single, gs, bs);
    ln_pair_bias_kernel<<<L, 256>>>((const float4*)pair, gz, bz, Wb);
    qkvg_mma<<<dim3(1536/64, L/128), 256>>>();
    s_mma<<<dim3(L/64, L/128, NH), 256>>>();
    softmax_kernel<<<NH*L, 256>>>();
    pv_kernel<<<dim3(1, L/128, 32), 128>>>();
    final_kernel<<<dim3(CS/64, L/64), 128>>>(Wo, bo, single, bg, out);
}

// round 7
// speedup vs baseline: 1.4983x; 1.0623x over previous
#include <cuda_runtime.h>
#include <cuda_bf16.h>
#include <cstdint>
#include <math.h>

// AttentionWithPairBias: B=1, L=768, C_S=384, C_Z=128, H=8, HD=48
#define L 768
#define CS 384
#define NH 8
#define HD 48
#define LL (L*L)
#define OPS (L*CS)

// -------------------- scratch (device globals; no allocs) --------------------
__device__ float g_bias[(size_t)NH*LL];  // bias -> logits (in place)
__device__ float g_gate[L*CS];
__device__ float g_opart[4*OPS];
__device__ __nv_bfloat16 g_ah[L*CS], g_al[L*CS];         // layernorm(single) hi/lo
__device__ __nv_bfloat16 g_wh[4*CS*CS], g_wl[4*CS*CS];   // Wq|Wk|Wv|Wg rows, hi/lo
__device__ __nv_bfloat16 g_qh[L*CS], g_ql[L*CS];         // Q hi/lo
__device__ __nv_bfloat16 g_kh[L*CS], g_kl[L*CS];         // K hi/lo
__device__ __nv_bfloat16 g_vth[CS*L], g_vtl[CS*L];       // V^T hi/lo: [d][j]
__device__ __nv_bfloat16 g_ph[(size_t)NH*LL], g_pl[(size_t)NH*LL]; // probs hi/lo

// -------------------- warp helpers --------------------
__device__ __forceinline__ float warp_sum(float v){
#pragma unroll
    for (int o = 16; o; o >>= 1) v += __shfl_xor_sync(0xffffffffu, v, o);
    return v;
}
__device__ __forceinline__ float warp_max(float v){
#pragma unroll
    for (int o = 16; o; o >>= 1) v = fmaxf(v, __shfl_xor_sync(0xffffffffu, v, o));
    return v;
}
__device__ __forceinline__ float tree8_distribute(float d[8], int lane){
    const unsigned F = 0xffffffffu;
    {
        bool up = (lane & 16) != 0;
#pragma unroll
        for (int k = 0; k < 4; k++){
            float send = up ? d[k]   : d[k+4];
            float keep = up ? d[k+4] : d[k];
            d[k] = keep + __shfl_xor_sync(F, send, 16);
        }
    }
    {
        bool up = (lane & 8) != 0;
#pragma unroll
        for (int k = 0; k < 2; k++){
            float send = up ? d[k]   : d[k+2];
            float keep = up ? d[k+2] : d[k];
            d[k] = keep + __shfl_xor_sync(F, send, 8);
        }
    }
    {
        bool up = (lane & 4) != 0;
        float send = up ? d[0] : d[1];
        float keep = up ? d[1] : d[0];
        d[0] = keep + __shfl_xor_sync(F, send, 4);
    }
    float v = d[0];
    v += __shfl_xor_sync(F, v, 2);
    v += __shfl_xor_sync(F, v, 1);
    return v;
}

// -------------------- mma.sync / ldmatrix primitives (plain PTX, sm_80+) ----
__device__ __forceinline__ uint32_t smem_u32(const void* p){
    uint32_t a;
    asm("{ .reg .u64 t; cvta.to.shared.u64 t, %1; cvt.u32.u64 %0, t; }" : "=r"(a) : "l"(p));
    return a;
}
__device__ __forceinline__ void ldsm4(uint32_t* r, uint32_t addr){
    asm volatile("ldmatrix.sync.aligned.m8n8.x4.shared.b16 {%0,%1,%2,%3}, [%4];"
        : "=r"(r[0]), "=r"(r[1]), "=r"(r[2]), "=r"(r[3]) : "r"(addr));
}
__device__ __forceinline__ void mma16816(float* c, const uint32_t* a, const uint32_t* b){
    asm volatile(
        "mma.sync.aligned.m16n8k16.row.col.f32.bf16.bf16.f32 "
        "{%0,%1,%2,%3}, {%4,%5,%6,%7}, {%8,%9}, {%0,%1,%2,%3};"
        : "+f"(c[0]), "+f"(c[1]), "+f"(c[2]), "+f"(c[3])
        : "r"(a[0]), "r"(a[1]), "r"(a[2]), "r"(a[3]), "r"(b[0]), "r"(b[1]));
}

// smem slab: one k16 slab = ROWS rows x 16 bf16, row pitch 48 bytes
#define SLA (128*48)
#define SLB (64*48)
#define SLV (48*48)

template<int ROWS, int NSLAB>
__device__ __forceinline__ void load_plane(char* dst, const __nv_bfloat16* src,
                                           int ld, int tid){
    constexpr int CH = ROWS * NSLAB * 2;         // 16B chunks
#pragma unroll
    for (int idx = tid; idx < CH; idx += 256){
        int r  = idx / (NSLAB*2);
        int cc = idx - r*(NSLAB*2);
        int s = cc >> 1, c = cc & 1;
        *(uint4*)(dst + s*(ROWS*48) + r*48 + c*16) =
            *(const uint4*)(src + (size_t)r*ld + s*16 + c*8);
    }
}

__device__ __forceinline__ void ldA(uint32_t a[4], uint32_t slab, int wm, int mt, int t){
    ldsm4(a, slab + (uint32_t)((wm + mt*16 + (t & 15))*48 + (t >> 4)*16));
}
__device__ __forceinline__ void ldB(uint32_t b[4], uint32_t slab, int nb16, int t){
    ldsm4(b, slab + (uint32_t)((nb16 + ((t >> 4) << 3) + (t & 7))*48 + ((t >> 3) & 1)*16));
}

// -------------------- K0: split Wq|Wk|Wv|Wg into bf16 hi/lo ------------------
__global__ void conv_w_kernel(const float* __restrict__ Wq, const float* __restrict__ Wk,
                              const float* __restrict__ Wv, const float* __restrict__ Wg){
    int idx = blockIdx.x*256 + threadIdx.x;
    int n  = idx / 96;
    int kq = idx - n*96;
    int which = n / 384;
    int r = n - which*384;
    const float* W = (which == 0) ? Wq : (which == 1) ? Wk : (which == 2) ? Wv : Wg;
    float4 v = *(const float4*)(W + (size_t)r*CS + kq*4);
    float x[4] = {v.x, v.y, v.z, v.w};
    __nv_bfloat16 h[4], l[4];
#pragma unroll
    for (int e = 0; e < 4; e++){
        h[e] = __float2bfloat16(x[e]);
        l[e] = __float2bfloat16(x[e] - __bfloat162float(h[e]));
    }
    size_t o = (size_t)n*CS + kq*4;
    *(__nv_bfloat162*)(g_wh + o)     = __halves2bfloat162(h[0], h[1]);
    *(__nv_bfloat162*)(g_wh + o + 2) = __halves2bfloat162(h[2], h[3]);
    *(__nv_bfloat162*)(g_wl + o)     = __halves2bfloat162(l[0], l[1]);
    *(__nv_bfloat162*)(g_wl + o + 2) = __halves2bfloat162(l[2], l[3]);
}

// -------------------- K1: layernorm(single) -> bf16 hi/lo --------------------
__global__ void ln_single_kernel(const float* __restrict__ x,
                                 const float* __restrict__ g,
                                 const float* __restrict__ b){
    __shared__ float rs[4], rq[4];
    int i = blockIdx.x, t = threadIdx.x;     // 128 threads
    int lane = t & 31, w = t >> 5;
    float v[3];
#pragma unroll
    for (int e = 0; e < 3; e++) v[e] = x[i*CS + e*128 + t];
    float s = v[0] + v[1] + v[2];
    float q = v[0]*v[0] + v[1]*v[1] + v[2]*v[2];
    s = warp_sum(s); q = warp_sum(q);
    if (lane == 0){ rs[w] = s; rq[w] = q; }
    __syncthreads();
    s = rs[0] + rs[1] + rs[2] + rs[3];
    q = rq[0] + rq[1] + rq[2] + rq[3];
    float mu   = s * (1.f/CS);
    float var  = q * (1.f/CS) - mu*mu;
    float rstd = rsqrtf(var + 1e-5f);
#pragma unroll
    for (int e = 0; e < 3; e++){
        int c = e*128 + t;
        float y = (v[e] - mu) * rstd * g[c] + b[c];
        __nv_bfloat16 hh = __float2bfloat16(y);
        g_ah[i*CS + c] = hh;
        g_al[i*CS + c] = __float2bfloat16(y - __bfloat162float(hh));
    }
}

// -------------------- K2: layernorm(pair) + bias = zn @ Wb -------------------
__global__ void ln_pair_bias_kernel(const float4* __restrict__ z4,
                                    const float* __restrict__ gz,
                                    const float* __restrict__ bz,
                                    const float* __restrict__ Wb){
    __shared__ float stage[8][772];
    const unsigned F = 0xffffffffu;
    const int tid  = threadIdx.x;
    const int warp = tid >> 5, lane = tid & 31;
    const int i    = blockIdx.x;
    const int zb   = lane * 4;

    float gw[4][8];
    float Gp[8] = {0,0,0,0,0,0,0,0};
    float Bp[8] = {0,0,0,0,0,0,0,0};
#pragma unroll
    for (int e = 0; e < 4; e++){
        float gze = gz[zb+e], bze = bz[zb+e];
        float4 w0 = ((const float4*)Wb)[(zb+e)*2 + 0];
        float4 w1 = ((const float4*)Wb)[(zb+e)*2 + 1];
        float w[8] = {w0.x,w0.y,w0.z,w0.w,w1.x,w1.y,w1.z,w1.w};
#pragma unroll
        for (int h = 0; h < 8; h++){
            gw[e][h] = gze * w[h];
            Gp[h] += gw[e][h];
            Bp[h] = fmaf(bze, w[h], Bp[h]);
        }
    }
    float Gh = tree8_distribute(Gp, lane);
    float Bh = tree8_distribute(Bp, lane);
    const int myh = (((lane>>4)&1)<<2) | (((lane>>3)&1)<<1) | ((lane>>2)&1);

    for (int jj = 0; jj < 96; jj++){
        int j = warp*96 + jj;
        float4 zv = z4[((size_t)i*L + j)*32 + lane];
        float z0 = zv.x, z1 = zv.y, z2 = zv.z, z3 = zv.w;
        float s = z0+z1+z2+z3;
        float q = fmaf(z0,z0, fmaf(z1,z1, fmaf(z2,z2, z3*z3)));
        float d[8];
#pragma unroll
        for (int h = 0; h < 8; h++)
            d[h] = fmaf(z3, gw[3][h], fmaf(z2, gw[2][h], fmaf(z1, gw[1][h], z0*gw[0][h])));
#pragma unroll
        for (int o = 16; o; o >>= 1){
            s += __shfl_xor_sync(F, s, o);
            q += __shfl_xor_sync(F, q, o);
        }
        float rd = tree8_distribute(d, lane);
        float mu   = s * (1.f/128.f);
        float var  = q * (1.f/128.f) - mu*mu;
        float rstd = rsqrtf(var + 1e-5f);
        float bias = fmaf(rstd, rd, fmaf(-rstd*mu, Gh, Bh));
        if ((lane & 3) == 0) stage[myh][j] = bias;
    }
    __syncthreads();
#pragma unroll
    for (int t = tid; t < 8*L; t += 256){
        int h = t / L, j = t % L;
        g_bias[(size_t)h*LL + (size_t)i*L + j] = stage[h][j];
    }
}

// -------------------- K3: Q,K,V^T,Gate via mma.sync bf16-split --------------
__global__ void __launch_bounds__(256) qkvg_mma(){
    __shared__ char sm[4*SLA + 4*SLB];
    char* pAH = sm;
    char* pAL = sm + 2*SLA;
    char* pBH = sm + 4*SLA;
    char* pBL = sm + 4*SLA + 2*SLB;
    const uint32_t uAH = smem_u32(pAH), uAL = smem_u32(pAL);
    const uint32_t uBH = smem_u32(pBH), uBL = smem_u32(pBL);

    const int tid = threadIdx.x, lane = tid & 31, wid = tid >> 5;
    const int wm32 = (wid & 3) * 32, wn32 = (wid >> 2) * 32;
    const int m0 = blockIdx.y * 128;
    const int ng = blockIdx.x * 64;

    float acc[2][4][4];
#pragma unroll
    for (int a = 0; a < 2; a++)
#pragma unroll
        for (int b = 0; b < 4; b++)
#pragma unroll
            for (int c = 0; c < 4; c++) acc[a][b][c] = 0.f;

    for (int ch = 0; ch < 12; ch++){
        int koff = ch * 32;
        if (ch) __syncthreads();
        load_plane<128,2>(pAH, g_ah + (size_t)m0*CS + koff, CS, tid);
        load_plane<128,2>(pAL, g_al + (size_t)m0*CS + koff, CS, tid);
        load_plane<64,2>(pBH, g_wh + (size_t)ng*CS + koff, CS, tid);
        load_plane<64,2>(pBL, g_wl + (size_t)ng*CS + koff, CS, tid);
        __syncthreads();
#pragma unroll
        for (int s = 0; s < 2; s++){
            uint32_t ah[2][4], al[2][4], bh[2][4], bl[2][4];
#pragma unroll
            for (int mt = 0; mt < 2; mt++){
                ldA(ah[mt], uAH + s*SLA, wm32, mt, lane);
                ldA(al[mt], uAL + s*SLA, wm32, mt, lane);
            }
#pragma unroll
            for (int pr = 0; pr < 2; pr++){
                ldB(bh[pr], uBH + s*SLB, wn32 + pr*16, lane);
                ldB(bl[pr], uBL + s*SLB, wn32 + pr*16, lane);
            }
#pragma unroll
            for (int mt = 0; mt < 2; mt++)
#pragma unroll
                for (int nt = 0; nt < 4; nt++){
                    const uint32_t* bhp = &bh[nt>>1][(nt&1)*2];
                    const uint32_t* blp = &bl[nt>>1][(nt&1)*2];
                    mma16816(acc[mt][nt], ah[mt], bhp);
                    mma16816(acc[mt][nt], ah[mt], blp);
                    mma16816(acc[mt][nt], al[mt], bhp);
                }
        }
    }

    const int which = ng / 384;
    const int nloc  = ng - which*384;
    const int rb = m0 + wm32 + (lane >> 2);
    const int cb = wn32 + (lane & 3)*2;
    if (which <= 1){
        __nv_bfloat16* PH = which ? g_kh : g_qh;
        __nv_bfloat16* PL = which ? g_kl : g_ql;
#pragma unroll
        for (int mt = 0; mt < 2; mt++)
#pragma unroll
            for (int half = 0; half < 2; half++){
                int i = rb + mt*16 + half*8;
#pragma unroll
                for (int nt = 0; nt < 4; nt++){
                    int cg = nloc + cb + nt*8;
                    float v0 = acc[mt][nt][half*2], v1 = acc[mt][nt][half*2+1];
                    __nv_bfloat16 h0 = __float2bfloat16(v0);
                    __nv_bfloat16 h1 = __float2bfloat16(v1);
                    __nv_bfloat16 l0 = __float2bfloat16(v0 - __bfloat162float(h0));
                    __nv_bfloat16 l1 = __float2bfloat16(v1 - __bfloat162float(h1));
                    *(__nv_bfloat162*)(PH + (size_t)i*CS + cg) = __halves2bfloat162(h0, h1);
                    *(__nv_bfloat162*)(PL + (size_t)i*CS + cg) = __halves2bfloat162(l0, l1);
                }
            }
    } else if (which == 2){
        // V^T bf16 hi/lo: g_vth[d][j] = V[j][d]
#pragma unroll
        for (int mt = 0; mt < 2; mt++)
#pragma unroll
            for (int half = 0; half < 2; half++){
                int i = rb + mt*16 + half*8;             // j (seq pos)
#pragma unroll
                for (int nt = 0; nt < 4; nt++){
                    int cg = nloc + cb + nt*8;           // d
                    float v0 = acc[mt][nt][half*2], v1 = acc[mt][nt][half*2+1];
                    __nv_bfloat16 h0 = __float2bfloat16(v0);
                    __nv_bfloat16 h1 = __float2bfloat16(v1);
                    g_vth[(size_t)cg*L + i]     = h0;
                    g_vth[(size_t)(cg+1)*L + i] = h1;
                    g_vtl[(size_t)cg*L + i]     = __float2bfloat16(v0 - __bfloat162float(h0));
                    g_vtl[(size_t)(cg+1)*L + i] = __float2bfloat16(v1 - __bfloat162float(h1));
                }
            }
    } else {
#pragma unroll
        for (int mt = 0; mt < 2; mt++)
#pragma unroll
            for (int half = 0; half < 2; half++){
                int i = rb + mt*16 + half*8;
#pragma unroll
                for (int nt = 0; nt < 4; nt++){
                    int cg = nloc + cb + nt*8;
                    float2 v = make_float2(acc[mt][nt][half*2], acc[mt][nt][half*2+1]);
                    *(float2*)(g_gate + (size_t)i*CS + cg) = v;
                }
            }
    }
}

// -------------------- K4: logits = Q K^T / sqrt(HD) + bias (mma) ------------
__global__ void __launch_bounds__(256) s_mma(){
    __shared__ char sm[6*SLA + 3*SLB];
    char* pAH = sm;
    char* pAL = sm + 3*SLA;
    char* pB  = sm + 6*SLA;
    const uint32_t uAH = smem_u32(pAH), uAL = smem_u32(pAL), uB = smem_u32(pB);

    const int tid = threadIdx.x, lane = tid & 31, wid = tid >> 5;
    const int wm32 = (wid & 3) * 32, wn32 = (wid >> 2) * 32;
    const int n0 = blockIdx.x * 64;
    const int m0 = blockIdx.y * 128;
    const int h  = blockIdx.z;

    float acc[2][4][4];
#pragma unroll
    for (int a = 0; a < 2; a++)
#pragma unroll
        for (int b = 0; b < 4; b++)
#pragma unroll
            for (int c = 0; c < 4; c++) acc[a][b][c] = 0.f;

    load_plane<128,3>(pAH, g_qh + (size_t)m0*CS + h*HD, CS, tid);
    load_plane<128,3>(pAL, g_ql + (size_t)m0*CS + h*HD, CS, tid);
    load_plane<64,3>(pB,  g_kh + (size_t)n0*CS + h*HD, CS, tid);
    __syncthreads();
#pragma unroll
    for (int s = 0; s < 3; s++){
        uint32_t ah[2][4], al[2][4], bh[2][4];
#pragma unroll
        for (int mt = 0; mt < 2; mt++){
            ldA(ah[mt], uAH + s*SLA, wm32, mt, lane);
            ldA(al[mt], uAL + s*SLA, wm32, mt, lane);
        }
#pragma unroll
        for (int pr = 0; pr < 2; pr++)
            ldB(bh[pr], uB + s*SLB, wn32 + pr*16, lane);
#pragma unroll
        for (int mt = 0; mt < 2; mt++)
#pragma unroll
            for (int nt = 0; nt < 4; nt++){
                const uint32_t* bp = &bh[nt>>1][(nt&1)*2];
                mma16816(acc[mt][nt], ah[mt], bp);
                mma16816(acc[mt][nt], al[mt], bp);
            }
    }
    __syncthreads();
    load_plane<64,3>(pB, g_kl + (size_t)n0*CS + h*HD, CS, tid);
    __syncthreads();
#pragma unroll
    for (int s = 0; s < 3; s++){
        uint32_t ah[2][4], bl[2][4];
#pragma unroll
        for (int mt = 0; mt < 2; mt++)
            ldA(ah[mt], uAH + s*SLA, wm32, mt, lane);
#pragma unroll
        for (int pr = 0; pr < 2; pr++)
            ldB(bl[pr], uB + s*SLB, wn32 + pr*16, lane);
#pragma unroll
        for (int mt = 0; mt < 2; mt++)
#pragma unroll
            for (int nt = 0; nt < 4; nt++)
                mma16816(acc[mt][nt], ah[mt], &bl[nt>>1][(nt&1)*2]);
    }

    const float sc = 0.14433756729740643f;
    const int rb = m0 + wm32 + (lane >> 2);
    const int cb = n0 + wn32 + (lane & 3)*2;
#pragma unroll
    for (int mt = 0; mt < 2; mt++)
#pragma unroll
        for (int half = 0; half < 2; half++){
            int i = rb + mt*16 + half*8;
            float* bp = g_bias + (size_t)h*LL + (size_t)i*L;
#pragma unroll
            for (int nt = 0; nt < 4; nt++){
                int cg = cb + nt*8;
                float2 b = *(float2*)(bp + cg);
                b.x = fmaf(acc[mt][nt][half*2],   sc, b.x);
                b.y = fmaf(acc[mt][nt][half*2+1], sc, b.y);
                *(float2*)(bp + cg) = b;
            }
        }
}

// -------------------- K5: row softmax -> P bf16 hi/lo ------------------------
__global__ void softmax_kernel(){
    __shared__ float red[8];
    size_t r = blockIdx.x;                    // flattened (h, i)
    float* row = g_bias + r * L;
    int t = threadIdx.x, lane = t & 31, w = t >> 5;   // 256 threads
    float v[3];
#pragma unroll
    for (int e = 0; e < 3; e++) v[e] = row[t + e*256];
    float m = fmaxf(fmaxf(v[0], v[1]), v[2]);
    m = warp_max(m);
    if (lane == 0) red[w] = m;
    __syncthreads();
    float mm = red[0];
#pragma unroll
    for (int k = 1; k < 8; k++) mm = fmaxf(mm, red[k]);
    __syncthreads();
    float sum = 0.f;
#pragma unroll
    for (int e = 0; e < 3; e++){ v[e] = __expf(v[e] - mm); sum += v[e]; }
    sum = warp_sum(sum);
    if (lane == 0) red[w] = sum;
    __syncthreads();
    float tot = 0.f;
#pragma unroll
    for (int k = 0; k < 8; k++) tot += red[k];
    float inv = 1.f / tot;
#pragma unroll
    for (int e = 0; e < 3; e++){
        float p = v[e] * inv;
        __nv_bfloat16 hh = __float2bfloat16(p);
        size_t o = r*L + t + e*256;
        g_ph[o] = hh;
        g_pl[o] = __float2bfloat16(p - __bfloat162float(hh));
    }
}

// -------------------- K6: O_partial = P @ V via mma (split-K = 4) -----------
// grid (ks=4, mt=6, h=8), 256 threads. Warp tile m16 x n48.
__global__ void __launch_bounds__(256) pv_mma(){
    __shared__ char sm[4*SLA + 4*SLV];   // P hi(2 slabs), P lo(2), V hi(2), V lo(2)
    char* pAH = sm;
    char* pAL = sm + 2*SLA;
    char* pBH = sm + 4*SLA;
    char* pBL = sm + 4*SLA + 2*SLV;
    const uint32_t uAH = smem_u32(pAH), uAL = smem_u32(pAL);
    const uint32_t uBH = smem_u32(pBH), uBL = smem_u32(pBL);

    const int tid = threadIdx.x, lane = tid & 31, wid = tid >> 5;
    const int ks = blockIdx.x;
    const int m0 = blockIdx.y * 128;
    const int h  = blockIdx.z;

    float acc[6][4];
#pragma unroll
    for (int a = 0; a < 6; a++)
#pragma unroll
        for (int c = 0; c < 4; c++) acc[a][c] = 0.f;

    for (int ch = 0; ch < 6; ch++){
        int j0 = ks*192 + ch*32;
        if (ch) __syncthreads();
        load_plane<128,2>(pAH, g_ph + (size_t)h*LL + (size_t)m0*L + j0, L, tid);
        load_plane<128,2>(pAL, g_pl + (size_t)h*LL + (size_t)m0*L + j0, L, tid);
        load_plane<48,2>(pBH, g_vth + (size_t)(h*HD)*L + j0, L, tid);
        load_plane<48,2>(pBL, g_vtl + (size_t)(h*HD)*L + j0, L, tid);
        __syncthreads();
#pragma unroll
        for (int s = 0; s < 2; s++){
            uint32_t ah[4], al[4], bh[3][4], bl[3][4];
            ldA(ah, uAH + s*SLA, wid*16, 0, lane);
            ldA(al, uAL + s*SLA, wid*16, 0, lane);
#pragma unroll
            for (int pr = 0; pr < 3; pr++){
                ldB(bh[pr], uBH + s*SLV, pr*16, lane);
                ldB(bl[pr], uBL + s*SLV, pr*16, lane);
            }
#pragma unroll
            for (int nt = 0; nt < 6; nt++){
                const uint32_t* bhp = &bh[nt>>1][(nt&1)*2];
                const uint32_t* blp = &bl[nt>>1][(nt&1)*2];
                mma16816(acc[nt], ah, bhp);
                mma16816(acc[nt], al, bhp);
                mma16816(acc[nt], ah, blp);
            }
        }
    }

    const int rb = m0 + wid*16 + (lane >> 2);
    const int cb = (lane & 3)*2;
#pragma unroll
    for (int half = 0; half < 2; half++){
        int i = rb + half*8;
        float* op = g_opart + (size_t)ks*OPS + (size_t)i*CS + h*HD;
#pragma unroll
        for (int nt = 0; nt < 6; nt++){
            float2 v = make_float2(acc[nt][half*2], acc[nt][half*2+1]);
            *(float2*)(op + cb + nt*8) = v;
        }
    }
}

// -------------------- FFMA GEMM body (final) --------------------------------
template<int BM,int BN,int BK,int TM,int TN,int THREADS,bool SUMA,int EPI>
__device__ __forceinline__ void gemm_body(
    float* As, float* Bs,
    const float* __restrict__ A, int lda, size_t aplane,
    const float* __restrict__ Bm, int ldb,
    float* __restrict__ C, int ldc,
    int m0, int n0, float scale, int K,
    const float* __restrict__ e0, const float* __restrict__ e1,
    const float* __restrict__ e2, const float* __restrict__ e3)
{
    constexpr int TX = BN / TN;
    constexpr int TY = BM / TM;
    static_assert(TX * TY == THREADS, "thread tiling mismatch");
    static_assert(TM == 8, "TM must be 8");
    constexpr int PA = BM + 4;
    constexpr int PB = BN + 4;
    constexpr int KQ  = BK / 4;
    constexpr int AF4 = BM * KQ;
    constexpr int BF4 = BN * KQ;
    constexpr int AIT = (AF4 + THREADS - 1) / THREADS;
    constexpr int BIT = (BF4 + THREADS - 1) / THREADS;

    const int tid = threadIdx.x;
    const int tx  = tid % TX, ty = tid / TX;

    float acc[TM][TN];
#pragma unroll
    for (int i = 0; i < TM; i++)
#pragma unroll
        for (int j = 0; j < TN; j++) acc[i][j] = 0.f;

    for (int kt = 0; kt < K; kt += BK){
#pragma unroll
        for (int u = 0; u < AIT; u++){
            int t4 = tid + u*THREADS;
            if ((AF4 % THREADS == 0) || t4 < AF4){
                int row = t4 / KQ, kq = t4 % KQ;
                const float* p = A + (size_t)(m0 + row)*lda + kt + kq*4;
                float4 v = *(const float4*)p;
                if (SUMA){
                    float4 v1 = *(const float4*)(p +   aplane);
                    float4 v2 = *(const float4*)(p + 2*aplane);
                    float4 v3 = *(const float4*)(p + 3*aplane);
                    v.x += v1.x+v2.x+v3.x; v.y += v1.y+v2.y+v3.y;
                    v.z += v1.z+v2.z+v3.z; v.w += v1.w+v2.w+v3.w;
                }
                As[(kq*4+0)*PA+row] = v.x; As[(kq*4+1)*PA+row] = v.y;
                As[(kq*4+2)*PA+row] = v.z; As[(kq*4+3)*PA+row] = v.w;
            }
        }
#pragma unroll
        for (int u = 0; u < BIT; u++){
            int t4 = tid + u*THREADS;
            if ((BF4 % THREADS == 0) || t4 < BF4){
                int row = t4 / KQ, kq = t4 % KQ;
                float4 v = *(const float4*)(Bm + (size_t)(n0 + row)*ldb + kt + kq*4);
                Bs[(kq*4+0)*PB+row] = v.x; Bs[(kq*4+1)*PB+row] = v.y;
                Bs[(kq*4+2)*PB+row] = v.z; Bs[(kq*4+3)*PB+row] = v.w;
            }
        }
        __syncthreads();
#pragma unroll
        for (int kk = 0; kk < BK; kk++){
            float af[TM], bf[TN];
            *(float4*)&af[0] = *(const float4*)&As[kk*PA + ty*TM];
            *(float4*)&af[4] = *(const float4*)&As[kk*PA + ty*TM + 4];
            if (TN == 4){
                *(float4*)&bf[0] = *(const float4*)&Bs[kk*PB + tx*TN];
            } else {
#pragma unroll
                for (int j = 0; j < TN; j += 2)
                    *(float2*)&bf[j] = *(const float2*)&Bs[kk*PB + tx*TN + j];
            }
#pragma unroll
            for (int i = 0; i < TM; i++)
#pragma unroll
                for (int j = 0; j < TN; j++)
                    acc[i][j] = fmaf(af[i], bf[j], acc[i][j]);
        }
        __syncthreads();
    }

#pragma unroll
    for (int i = 0; i < TM; i++){
        int row = m0 + ty*TM + i;
#pragma unroll
        for (int j = 0; j < TN; j++){
            int col = n0 + tx*TN + j;
            float r = acc[i][j];
            if (EPI == 0){
                C[(size_t)row*ldc + col] = r;
            } else if (EPI == 4){
                float y  = r + e3[col];
                float gp = e1[(size_t)row*CS + col] + e2[col];
                float gg = 1.f / (1.f + __expf(-gp));
                C[(size_t)row*ldc + col] = e0[(size_t)row*CS + col] + gg * y;
            }
        }
    }
}

// -------------------- K7: out = single + sigmoid(gate+bg)*(O@Wo^T+bo) -------
__global__ void __launch_bounds__(128) final_kernel(
        const float* __restrict__ Wo, const float* __restrict__ bo,
        const float* __restrict__ single, const float* __restrict__ bg,
        float* __restrict__ out){
    __shared__ float As[32*68];
    __shared__ float Bs[32*68];
    gemm_body<64,64,32,8,4,128,true,4>(As, Bs,
        g_opart, CS, OPS, Wo, CS, out, CS,
        blockIdx.y*64, blockIdx.x*64, 1.f, CS,
        single, g_gate, bg, bo);
}

// -------------------- launch --------------------
extern "C" void kernel_launch(void* const* d_in, const int* in_sizes, int n_in,
                              void* d_out, int out_size){
    const float* single = (const float*)d_in[0];
    const float* pair   = (const float*)d_in[1];
    const float* gs     = (const float*)d_in[2];
    const float* bs     = (const float*)d_in[3];
    const float* gz     = (const float*)d_in[4];
    const float* bz     = (const float*)d_in[5];
    const float* Wq     = (const float*)d_in[6];
    const float* Wk     = (const float*)d_in[7];
    const float* Wv     = (const float*)d_in[8];
    const float* Wb     = (const float*)d_in[9];
    const float* Wo     = (const float*)d_in[10];
    const float* bo     = (const float*)d_in[11];
    const float* Wg     = (const float*)d_in[12];
    const float* bg     = (const float*)d_in[13];
    float* out = (float*)d_out;

    conv_w_kernel<<<576, 256>>>(Wq, Wk, Wv, Wg);
    ln_single_kernel<<<L, 128>>>(single, gs, bs);
    ln_pair_bias_kernel<<<L, 256>>>((const float4*)pair, gz, bz, Wb);
    qkvg_mma<<<dim3(1536/64, L/128), 256>>>();
    s_mma<<<dim3(L/64, L/128, NH), 256>>>();
    softmax_kernel<<<NH*L, 256>>>();
    pv_mma<<<dim3(4, L/128, NH), 256>>>();
    final_kernel<<<dim3(CS/64, L/64), 128>>>(Wo, bo, single, bg, out);
}

// round 8
// speedup vs baseline: 1.5120x; 1.0091x over previous
#include <cuda_runtime.h>
#include <cuda_bf16.h>
#include <cstdint>
#include <math.h>

// AttentionWithPairBias: B=1, L=768, C_S=384, C_Z=128, H=8, HD=48
#define L 768
#define CS 384
#define NH 8
#define HD 48
#define LL (L*L)
#define OPS (L*CS)

// -------------------- scratch (device globals; no allocs) --------------------
__device__ float g_bias[(size_t)NH*LL];  // bias -> logits (in place)
__device__ float g_gate[L*CS];
__device__ float g_opart[4*OPS];
__device__ __nv_bfloat16 g_ah[L*CS], g_al[L*CS];         // layernorm(single) hi/lo
__device__ __nv_bfloat16 g_wh[4*CS*CS], g_wl[4*CS*CS];   // Wq|Wk|Wv|Wg rows, hi/lo
__device__ __nv_bfloat16 g_qh[L*CS], g_ql[L*CS];         // Q hi/lo
__device__ __nv_bfloat16 g_kh[L*CS], g_kl[L*CS];         // K hi/lo
__device__ __nv_bfloat16 g_vth[CS*L], g_vtl[CS*L];       // V^T hi/lo: [d][j]
__device__ __nv_bfloat16 g_ph[(size_t)NH*LL], g_pl[(size_t)NH*LL]; // probs hi/lo

// -------------------- warp helpers --------------------
__device__ __forceinline__ float warp_sum(float v){
#pragma unroll
    for (int o = 16; o; o >>= 1) v += __shfl_xor_sync(0xffffffffu, v, o);
    return v;
}
__device__ __forceinline__ float warp_max(float v){
#pragma unroll
    for (int o = 16; o; o >>= 1) v = fmaxf(v, __shfl_xor_sync(0xffffffffu, v, o));
    return v;
}
__device__ __forceinline__ float tree8_distribute(float d[8], int lane){
    const unsigned F = 0xffffffffu;
    {
        bool up = (lane & 16) != 0;
#pragma unroll
        for (int k = 0; k < 4; k++){
            float send = up ? d[k]   : d[k+4];
            float keep = up ? d[k+4] : d[k];
            d[k] = keep + __shfl_xor_sync(F, send, 16);
        }
    }
    {
        bool up = (lane & 8) != 0;
#pragma unroll
        for (int k = 0; k < 2; k++){
            float send = up ? d[k]   : d[k+2];
            float keep = up ? d[k+2] : d[k];
            d[k] = keep + __shfl_xor_sync(F, send, 8);
        }
    }
    {
        bool up = (lane & 4) != 0;
        float send = up ? d[0] : d[1];
        float keep = up ? d[1] : d[0];
        d[0] = keep + __shfl_xor_sync(F, send, 4);
    }
    float v = d[0];
    v += __shfl_xor_sync(F, v, 2);
    v += __shfl_xor_sync(F, v, 1);
    return v;
}

// -------------------- mma.sync / ldmatrix / cp.async (plain PTX, sm_80+) ----
__device__ __forceinline__ uint32_t smem_u32(const void* p){
    uint32_t a;
    asm("{ .reg .u64 t; cvta.to.shared.u64 t, %1; cvt.u32.u64 %0, t; }" : "=r"(a) : "l"(p));
    return a;
}
__device__ __forceinline__ void ldsm4(uint32_t* r, uint32_t addr){
    asm volatile("ldmatrix.sync.aligned.m8n8.x4.shared.b16 {%0,%1,%2,%3}, [%4];"
        : "=r"(r[0]), "=r"(r[1]), "=r"(r[2]), "=r"(r[3]) : "r"(addr));
}
__device__ __forceinline__ void mma16816(float* c, const uint32_t* a, const uint32_t* b){
    asm volatile(
        "mma.sync.aligned.m16n8k16.row.col.f32.bf16.bf16.f32 "
        "{%0,%1,%2,%3}, {%4,%5,%6,%7}, {%8,%9}, {%0,%1,%2,%3};"
        : "+f"(c[0]), "+f"(c[1]), "+f"(c[2]), "+f"(c[3])
        : "r"(a[0]), "r"(a[1]), "r"(a[2]), "r"(a[3]), "r"(b[0]), "r"(b[1]));
}
__device__ __forceinline__ void cpa16(uint32_t dst, const void* src){
    asm volatile("cp.async.cg.shared.global [%0], [%1], 16;" :: "r"(dst), "l"(src));
}
#define CPA_COMMIT() asm volatile("cp.async.commit_group;" ::: "memory")
#define CPA_WAIT1()  asm volatile("cp.async.wait_group 1;" ::: "memory")
#define CPA_WAIT0()  asm volatile("cp.async.wait_group 0;" ::: "memory")

// slab: ROWS rows x 16 bf16 payload (32B), pitch 48B (conflict-free ldmatrix)
__device__ __forceinline__ void ldA(uint32_t a[4], uint32_t slab, int wm, int t){
    ldsm4(a, slab + (uint32_t)((wm + (t & 15))*48 + (t >> 4)*16));
}
__device__ __forceinline__ void ldB(uint32_t b[4], uint32_t slab, int nb16, int t){
    ldsm4(b, slab + (uint32_t)((nb16 + ((t >> 4) << 3) + (t & 7))*48 + ((t >> 3) & 1)*16));
}

// -------------------- K0: split Wq|Wk|Wv|Wg into bf16 hi/lo ------------------
__global__ void conv_w_kernel(const float* __restrict__ Wq, const float* __restrict__ Wk,
                              const float* __restrict__ Wv, const float* __restrict__ Wg){
    int idx = blockIdx.x*256 + threadIdx.x;
    int n  = idx / 96;
    int kq = idx - n*96;
    int which = n / 384;
    int r = n - which*384;
    const float* W = (which == 0) ? Wq : (which == 1) ? Wk : (which == 2) ? Wv : Wg;
    float4 v = *(const float4*)(W + (size_t)r*CS + kq*4);
    float x[4] = {v.x, v.y, v.z, v.w};
    __nv_bfloat16 h[4], l[4];
#pragma unroll
    for (int e = 0; e < 4; e++){
        h[e] = __float2bfloat16(x[e]);
        l[e] = __float2bfloat16(x[e] - __bfloat162float(h[e]));
    }
    size_t o = (size_t)n*CS + kq*4;
    *(__nv_bfloat162*)(g_wh + o)     = __halves2bfloat162(h[0], h[1]);
    *(__nv_bfloat162*)(g_wh + o + 2) = __halves2bfloat162(h[2], h[3]);
    *(__nv_bfloat162*)(g_wl + o)     = __halves2bfloat162(l[0], l[1]);
    *(__nv_bfloat162*)(g_wl + o + 2) = __halves2bfloat162(l[2], l[3]);
}

// -------------------- K1: layernorm(single) -> bf16 hi/lo --------------------
__global__ void ln_single_kernel(const float* __restrict__ x,
                                 const float* __restrict__ g,
                                 const float* __restrict__ b){
    __shared__ float rs[4], rq[4];
    int i = blockIdx.x, t = threadIdx.x;     // 128 threads
    int lane = t & 31, w = t >> 5;
    float v[3];
#pragma unroll
    for (int e = 0; e < 3; e++) v[e] = x[i*CS + e*128 + t];
    float s = v[0] + v[1] + v[2];
    float q = v[0]*v[0] + v[1]*v[1] + v[2]*v[2];
    s = warp_sum(s); q = warp_sum(q);
    if (lane == 0){ rs[w] = s; rq[w] = q; }
    __syncthreads();
    s = rs[0] + rs[1] + rs[2] + rs[3];
    q = rq[0] + rq[1] + rq[2] + rq[3];
    float mu   = s * (1.f/CS);
    float var  = q * (1.f/CS) - mu*mu;
    float rstd = rsqrtf(var + 1e-5f);
#pragma unroll
    for (int e = 0; e < 3; e++){
        int c = e*128 + t;
        float y = (v[e] - mu) * rstd * g[c] + b[c];
        __nv_bfloat16 hh = __float2bfloat16(y);
        g_ah[i*CS + c] = hh;
        g_al[i*CS + c] = __float2bfloat16(y - __bfloat162float(hh));
    }
}

// -------------------- K2: layernorm(pair) + bias = zn @ Wb -------------------
__global__ void ln_pair_bias_kernel(const float4* __restrict__ z4,
                                    const float* __restrict__ gz,
                                    const float* __restrict__ bz,
                                    const float* __restrict__ Wb){
    __shared__ float stage[8][772];
    const unsigned F = 0xffffffffu;
    const int tid  = threadIdx.x;
    const int warp = tid >> 5, lane = tid & 31;
    const int i    = blockIdx.x;
    const int zb   = lane * 4;

    float gw[4][8];
    float Gp[8] = {0,0,0,0,0,0,0,0};
    float Bp[8] = {0,0,0,0,0,0,0,0};
#pragma unroll
    for (int e = 0; e < 4; e++){
        float gze = gz[zb+e], bze = bz[zb+e];
        float4 w0 = ((const float4*)Wb)[(zb+e)*2 + 0];
        float4 w1 = ((const float4*)Wb)[(zb+e)*2 + 1];
        float w[8] = {w0.x,w0.y,w0.z,w0.w,w1.x,w1.y,w1.z,w1.w};
#pragma unroll
        for (int h = 0; h < 8; h++){
            gw[e][h] = gze * w[h];
            Gp[h] += gw[e][h];
            Bp[h] = fmaf(bze, w[h], Bp[h]);
        }
    }
    float Gh = tree8_distribute(Gp, lane);
    float Bh = tree8_distribute(Bp, lane);
    const int myh = (((lane>>4)&1)<<2) | (((lane>>3)&1)<<1) | ((lane>>2)&1);

    for (int jj = 0; jj < 96; jj++){
        int j = warp*96 + jj;
        float4 zv = z4[((size_t)i*L + j)*32 + lane];
        float z0 = zv.x, z1 = zv.y, z2 = zv.z, z3 = zv.w;
        float s = z0+z1+z2+z3;
        float q = fmaf(z0,z0, fmaf(z1,z1, fmaf(z2,z2, z3*z3)));
        float d[8];
#pragma unroll
        for (int h = 0; h < 8; h++)
            d[h] = fmaf(z3, gw[3][h], fmaf(z2, gw[2][h], fmaf(z1, gw[1][h], z0*gw[0][h])));
#pragma unroll
        for (int o = 16; o; o >>= 1){
            s += __shfl_xor_sync(F, s, o);
            q += __shfl_xor_sync(F, q, o);
        }
        float rd = tree8_distribute(d, lane);
        float mu   = s * (1.f/128.f);
        float var  = q * (1.f/128.f) - mu*mu;
        float rstd = rsqrtf(var + 1e-5f);
        float bias = fmaf(rstd, rd, fmaf(-rstd*mu, Gh, Bh));
        if ((lane & 3) == 0) stage[myh][j] = bias;
    }
    __syncthreads();
#pragma unroll
    for (int t = tid; t < 8*L; t += 256){
        int h = t / L, j = t % L;
        g_bias[(size_t)h*LL + (size_t)i*L + j] = stage[h][j];
    }
}

// ============================================================================
// Pipelined mma kernels: 64x64 (qkvg, s) and 128x48 (pv) tiles, k16 chunks,
// double-buffered cp.async.
// ============================================================================
#define QCH 12288     // chunk: Ah(3072) Al(3072) Bh(3072) Bl(3072), rows=64

// -------------------- K3: Q,K,V^T,Gate (pipelined) --------------------------
__global__ void __launch_bounds__(256) qkvg_mma(){
    __shared__ __align__(16) char sm[2*QCH];
    const uint32_t sb = smem_u32(sm);
    const int tid = threadIdx.x, lane = tid & 31, wid = tid >> 5;
    const int wm16 = (wid & 3) * 16, wn32 = (wid >> 2) * 32;
    const int m0 = blockIdx.y * 64;
    const int ng = blockIdx.x * 64;

    float acc[4][4];
#pragma unroll
    for (int b = 0; b < 4; b++)
#pragma unroll
        for (int c = 0; c < 4; c++) acc[b][c] = 0.f;

    auto load = [&](int buf, int ch){
        int k = ch * 16;
#pragma unroll
        for (int u = 0; u < 2; u++){
            int idx = tid + u*256;               // [0,512)
            int s = idx >> 7, rc = idx & 127, r = rc >> 1, c = rc & 1;
            const __nv_bfloat16* src =
                (s == 0) ? g_ah + (size_t)(m0+r)*CS + k + c*8 :
                (s == 1) ? g_al + (size_t)(m0+r)*CS + k + c*8 :
                (s == 2) ? g_wh + (size_t)(ng+r)*CS + k + c*8 :
                           g_wl + (size_t)(ng+r)*CS + k + c*8;
            cpa16(sb + buf*QCH + s*3072 + r*48 + c*16, src);
        }
        CPA_COMMIT();
    };

    load(0, 0);
    for (int ch = 0; ch < 24; ch++){
        if (ch + 1 < 24){ load((ch+1) & 1, ch+1); CPA_WAIT1(); }
        else CPA_WAIT0();
        __syncthreads();
        uint32_t base = sb + (ch & 1)*QCH;
        uint32_t ah[4], al[4], bh[2][4], bl[2][4];
        ldA(ah, base,        wm16, lane);
        ldA(al, base + 3072, wm16, lane);
#pragma unroll
        for (int pr = 0; pr < 2; pr++){
            ldB(bh[pr], base + 6144, wn32 + pr*16, lane);
            ldB(bl[pr], base + 9216, wn32 + pr*16, lane);
        }
#pragma unroll
        for (int nt = 0; nt < 4; nt++){
            const uint32_t* bhp = &bh[nt>>1][(nt&1)*2];
            const uint32_t* blp = &bl[nt>>1][(nt&1)*2];
            mma16816(acc[nt], ah, bhp);
            mma16816(acc[nt], al, bhp);
            mma16816(acc[nt], ah, blp);
        }
        __syncthreads();
    }

    const int which = ng / 384;
    const int nloc  = ng - which*384;
    const int rb = m0 + wm16 + (lane >> 2);
    const int cb = wn32 + (lane & 3)*2;
    if (which <= 1){
        __nv_bfloat16* PH = which ? g_kh : g_qh;
        __nv_bfloat16* PL = which ? g_kl : g_ql;
#pragma unroll
        for (int half = 0; half < 2; half++){
            int i = rb + half*8;
#pragma unroll
            for (int nt = 0; nt < 4; nt++){
                int cg = nloc + cb + nt*8;
                float v0 = acc[nt][half*2], v1 = acc[nt][half*2+1];
                __nv_bfloat16 h0 = __float2bfloat16(v0);
                __nv_bfloat16 h1 = __float2bfloat16(v1);
                __nv_bfloat16 l0 = __float2bfloat16(v0 - __bfloat162float(h0));
                __nv_bfloat16 l1 = __float2bfloat16(v1 - __bfloat162float(h1));
                *(__nv_bfloat162*)(PH + (size_t)i*CS + cg) = __halves2bfloat162(h0, h1);
                *(__nv_bfloat162*)(PL + (size_t)i*CS + cg) = __halves2bfloat162(l0, l1);
            }
        }
    } else if (which == 2){
#pragma unroll
        for (int half = 0; half < 2; half++){
            int i = rb + half*8;
#pragma unroll
            for (int nt = 0; nt < 4; nt++){
                int cg = nloc + cb + nt*8;
                float v0 = acc[nt][half*2], v1 = acc[nt][half*2+1];
                __nv_bfloat16 h0 = __float2bfloat16(v0);
                __nv_bfloat16 h1 = __float2bfloat16(v1);
                g_vth[(size_t)cg*L + i]     = h0;
                g_vth[(size_t)(cg+1)*L + i] = h1;
                g_vtl[(size_t)cg*L + i]     = __float2bfloat16(v0 - __bfloat162float(h0));
                g_vtl[(size_t)(cg+1)*L + i] = __float2bfloat16(v1 - __bfloat162float(h1));
            }
        }
    } else {
#pragma unroll
        for (int half = 0; half < 2; half++){
            int i = rb + half*8;
#pragma unroll
            for (int nt = 0; nt < 4; nt++){
                int cg = nloc + cb + nt*8;
                float2 v = make_float2(acc[nt][half*2], acc[nt][half*2+1]);
                *(float2*)(g_gate + (size_t)i*CS + cg) = v;
            }
        }
    }
}

// -------------------- K4: logits = Q K^T / sqrt(HD) + bias (pipelined) ------
__global__ void __launch_bounds__(256) s_mma(){
    __shared__ __align__(16) char sm[2*QCH];
    const uint32_t sb = smem_u32(sm);
    const int tid = threadIdx.x, lane = tid & 31, wid = tid >> 5;
    const int wm16 = (wid & 3) * 16, wn32 = (wid >> 2) * 32;
    const int n0 = blockIdx.x * 64;
    const int m0 = blockIdx.y * 64;
    const int h  = blockIdx.z;

    float acc[4][4];
#pragma unroll
    for (int b = 0; b < 4; b++)
#pragma unroll
        for (int c = 0; c < 4; c++) acc[b][c] = 0.f;

    auto load = [&](int buf, int ch){
        int k = h*HD + ch * 16;
#pragma unroll
        for (int u = 0; u < 2; u++){
            int idx = tid + u*256;
            int s = idx >> 7, rc = idx & 127, r = rc >> 1, c = rc & 1;
            const __nv_bfloat16* src =
                (s == 0) ? g_qh + (size_t)(m0+r)*CS + k + c*8 :
                (s == 1) ? g_ql + (size_t)(m0+r)*CS + k + c*8 :
                (s == 2) ? g_kh + (size_t)(n0+r)*CS + k + c*8 :
                           g_kl + (size_t)(n0+r)*CS + k + c*8;
            cpa16(sb + buf*QCH + s*3072 + r*48 + c*16, src);
        }
        CPA_COMMIT();
    };

    load(0, 0);
#pragma unroll
    for (int ch = 0; ch < 3; ch++){
        if (ch + 1 < 3){ load((ch+1) & 1, ch+1); CPA_WAIT1(); }
        else CPA_WAIT0();
        __syncthreads();
        uint32_t base = sb + (ch & 1)*QCH;
        uint32_t ah[4], al[4], bh[2][4], bl[2][4];
        ldA(ah, base,        wm16, lane);
        ldA(al, base + 3072, wm16, lane);
#pragma unroll
        for (int pr = 0; pr < 2; pr++){
            ldB(bh[pr], base + 6144, wn32 + pr*16, lane);
            ldB(bl[pr], base + 9216, wn32 + pr*16, lane);
        }
#pragma unroll
        for (int nt = 0; nt < 4; nt++){
            const uint32_t* bhp = &bh[nt>>1][(nt&1)*2];
            const uint32_t* blp = &bl[nt>>1][(nt&1)*2];
            mma16816(acc[nt], ah, bhp);
            mma16816(acc[nt], al, bhp);
            mma16816(acc[nt], ah, blp);
        }
        __syncthreads();
    }

    const float sc = 0.14433756729740643f;
    const int rb = m0 + wm16 + (lane >> 2);
    const int cb = n0 + wn32 + (lane & 3)*2;
#pragma unroll
    for (int half = 0; half < 2; half++){
        int i = rb + half*8;
        float* bp = g_bias + (size_t)h*LL + (size_t)i*L;
#pragma unroll
        for (int nt = 0; nt < 4; nt++){
            int cg = cb + nt*8;
            float2 b = *(float2*)(bp + cg);
            b.x = fmaf(acc[nt][half*2],   sc, b.x);
            b.y = fmaf(acc[nt][half*2+1], sc, b.y);
            *(float2*)(bp + cg) = b;
        }
    }
}

// -------------------- K5: row softmax -> P bf16 hi/lo ------------------------
__global__ void softmax_kernel(){
    __shared__ float red[8];
    size_t r = blockIdx.x;
    float* row = g_bias + r * L;
    int t = threadIdx.x, lane = t & 31, w = t >> 5;   // 256 threads
    float v[3];
#pragma unroll
    for (int e = 0; e < 3; e++) v[e] = row[t + e*256];
    float m = fmaxf(fmaxf(v[0], v[1]), v[2]);
    m = warp_max(m);
    if (lane == 0) red[w] = m;
    __syncthreads();
    float mm = red[0];
#pragma unroll
    for (int k = 1; k < 8; k++) mm = fmaxf(mm, red[k]);
    __syncthreads();
    float sum = 0.f;
#pragma unroll
    for (int e = 0; e < 3; e++){ v[e] = __expf(v[e] - mm); sum += v[e]; }
    sum = warp_sum(sum);
    if (lane == 0) red[w] = sum;
    __syncthreads();
    float tot = 0.f;
#pragma unroll
    for (int k = 0; k < 8; k++) tot += red[k];
    float inv = 1.f / tot;
#pragma unroll
    for (int e = 0; e < 3; e++){
        float p = v[e] * inv;
        __nv_bfloat16 hh = __float2bfloat16(p);
        size_t o = r*L + t + e*256;
        g_ph[o] = hh;
        g_pl[o] = __float2bfloat16(p - __bfloat162float(hh));
    }
}

// -------------------- K6: O_partial = P @ V (pipelined, split-K=4) ----------
// tile 128x48, 12 k16 chunks. chunk: Ph(6144) Pl(6144) Vh(2304) Vl(2304) = 16896
#define PCH 16896
__global__ void __launch_bounds__(256) pv_mma(){
    __shared__ __align__(16) char sm[2*PCH];
    const uint32_t sb = smem_u32(sm);
    const int tid = threadIdx.x, lane = tid & 31, wid = tid >> 5;
    const int ks = blockIdx.x;
    const int m0 = blockIdx.y * 128;
    const int h  = blockIdx.z;

    float acc[6][4];
#pragma unroll
    for (int a = 0; a < 6; a++)
#pragma unroll
        for (int c = 0; c < 4; c++) acc[a][c] = 0.f;

    auto load = [&](int buf, int ch){
        int j0 = ks*192 + ch*16;
#pragma unroll
        for (int u = 0; u < 3; u++){
            int idx = tid + u*256;               // [0,704)
            if (idx < 704){
                const __nv_bfloat16* src;
                uint32_t dst;
                if (idx < 512){
                    int s = idx >> 8, rc = idx & 255, r = rc >> 1, c = rc & 1;
                    src = (s ? g_pl : g_ph) + (size_t)h*LL + (size_t)(m0+r)*L + j0 + c*8;
                    dst = sb + buf*PCH + s*6144 + r*48 + c*16;
                } else {
                    int q = idx - 512;           // [0,192)
                    int s = q / 96, rc = q - s*96, r = rc >> 1, c = rc & 1;
                    src = (s ? g_vtl : g_vth) + (size_t)(h*HD + r)*L + j0 + c*8;
                    dst = sb + buf*PCH + 12288 + s*2304 + r*48 + c*16;
                }
                cpa16(dst, src);
            }
        }
        CPA_COMMIT();
    };

    load(0, 0);
    for (int ch = 0; ch < 12; ch++){
        if (ch + 1 < 12){ load((ch+1) & 1, ch+1); CPA_WAIT1(); }
        else CPA_WAIT0();
        __syncthreads();
        uint32_t base = sb + (ch & 1)*PCH;
        uint32_t ah[4], al[4], bh[3][4], bl[3][4];
        ldA(ah, base,        wid*16, lane);
        ldA(al, base + 6144, wid*16, lane);
#pragma unroll
        for (int pr = 0; pr < 3; pr++){
            ldB(bh[pr], base + 12288, pr*16, lane);
            ldB(bl[pr], base + 14592, pr*16, lane);
        }
#pragma unroll
        for (int nt = 0; nt < 6; nt++){
            const uint32_t* bhp = &bh[nt>>1][(nt&1)*2];
            const uint32_t* blp = &bl[nt>>1][(nt&1)*2];
            mma16816(acc[nt], ah, bhp);
            mma16816(acc[nt], al, bhp);
            mma16816(acc[nt], ah, blp);
        }
        __syncthreads();
    }

    const int rb = m0 + wid*16 + (lane >> 2);
    const int cb = (lane & 3)*2;
#pragma unroll
    for (int half = 0; half < 2; half++){
        int i = rb + half*8;
        float* op = g_opart + (size_t)ks*OPS + (size_t)i*CS + h*HD;
#pragma unroll
        for (int nt = 0; nt < 6; nt++){
            float2 v = make_float2(acc[nt][half*2], acc[nt][half*2+1]);
            *(float2*)(op + cb + nt*8) = v;
        }
    }
}

// -------------------- FFMA GEMM body (final) --------------------------------
template<int BM,int BN,int BK,int TM,int TN,int THREADS,bool SUMA,int EPI>
__device__ __forceinline__ void gemm_body(
    float* As, float* Bs,
    const float* __restrict__ A, int lda, size_t aplane,
    const float* __restrict__ Bm, int ldb,
    float* __restrict__ C, int ldc,
    int m0, int n0, float scale, int K,
    const float* __restrict__ e0, const float* __restrict__ e1,
    const float* __restrict__ e2, const float* __restrict__ e3)
{
    constexpr int TX = BN / TN;
    constexpr int TY = BM / TM;
    static_assert(TX * TY == THREADS, "thread tiling mismatch");
    static_assert(TM == 8, "TM must be 8");
    constexpr int PA = BM + 4;
    constexpr int PB = BN + 4;
    constexpr int KQ  = BK / 4;
    constexpr int AF4 = BM * KQ;
    constexpr int BF4 = BN * KQ;
    constexpr int AIT = (AF4 + THREADS - 1) / THREADS;
    constexpr int BIT = (BF4 + THREADS - 1) / THREADS;

    const int tid = threadIdx.x;
    const int tx  = tid % TX, ty = tid / TX;

    float acc[TM][TN];
#pragma unroll
    for (int i = 0; i < TM; i++)
#pragma unroll
        for (int j = 0; j < TN; j++) acc[i][j] = 0.f;

    for (int kt = 0; kt < K; kt += BK){
#pragma unroll
        for (int u = 0; u < AIT; u++){
            int t4 = tid + u*THREADS;
            if ((AF4 % THREADS == 0) || t4 < AF4){
                int row = t4 / KQ, kq = t4 % KQ;
                const float* p = A + (size_t)(m0 + row)*lda + kt + kq*4;
                float4 v = *(const float4*)p;
                if (SUMA){
                    float4 v1 = *(const float4*)(p +   aplane);
                    float4 v2 = *(const float4*)(p + 2*aplane);
                    float4 v3 = *(const float4*)(p + 3*aplane);
                    v.x += v1.x+v2.x+v3.x; v.y += v1.y+v2.y+v3.y;
                    v.z += v1.z+v2.z+v3.z; v.w += v1.w+v2.w+v3.w;
                }
                As[(kq*4+0)*PA+row] = v.x; As[(kq*4+1)*PA+row] = v.y;
                As[(kq*4+2)*PA+row] = v.z; As[(kq*4+3)*PA+row] = v.w;
            }
        }
#pragma unroll
        for (int u = 0; u < BIT; u++){
            int t4 = tid + u*THREADS;
            if ((BF4 % THREADS == 0) || t4 < BF4){
                int row = t4 / KQ, kq = t4 % KQ;
                float4 v = *(const float4*)(Bm + (size_t)(n0 + row)*ldb + kt + kq*4);
                Bs[(kq*4+0)*PB+row] = v.x; Bs[(kq*4+1)*PB+row] = v.y;
                Bs[(kq*4+2)*PB+row] = v.z; Bs[(kq*4+3)*PB+row] = v.w;
            }
        }
        __syncthreads();
#pragma unroll
        for (int kk = 0; kk < BK; kk++){
            float af[TM], bf[TN];
            *(float4*)&af[0] = *(const float4*)&As[kk*PA + ty*TM];
            *(float4*)&af[4] = *(const float4*)&As[kk*PA + ty*TM + 4];
            if (TN == 4){
                *(float4*)&bf[0] = *(const float4*)&Bs[kk*PB + tx*TN];
            } else {
#pragma unroll
                for (int j = 0; j < TN; j += 2)
                    *(float2*)&bf[j] = *(const float2*)&Bs[kk*PB + tx*TN + j];
            }
#pragma unroll
            for (int i = 0; i < TM; i++)
#pragma unroll
                for (int j = 0; j < TN; j++)
                    acc[i][j] = fmaf(af[i], bf[j], acc[i][j]);
        }
        __syncthreads();
    }

#pragma unroll
    for (int i = 0; i < TM; i++){
        int row = m0 + ty*TM + i;
#pragma unroll
        for (int j = 0; j < TN; j++){
            int col = n0 + tx*TN + j;
            float r = acc[i][j];
            if (EPI == 0){
                C[(size_t)row*ldc + col] = r;
            } else if (EPI == 4){
                float y  = r + e3[col];
                float gp = e1[(size_t)row*CS + col] + e2[col];
                float gg = 1.f / (1.f + __expf(-gp));
                C[(size_t)row*ldc + col] = e0[(size_t)row*CS + col] + gg * y;
            }
        }
    }
}

// -------------------- K7: out = single + sigmoid(gate+bg)*(O@Wo^T+bo) -------
__global__ void __launch_bounds__(128) final_kernel(
        const float* __restrict__ Wo, const float* __restrict__ bo,
        const float* __restrict__ single, const float* __restrict__ bg,
        float* __restrict__ out){
    __shared__ float As[32*68];
    __shared__ float Bs[32*68];
    gemm_body<64,64,32,8,4,128,true,4>(As, Bs,
        g_opart, CS, OPS, Wo, CS, out, CS,
        blockIdx.y*64, blockIdx.x*64, 1.f, CS,
        single, g_gate, bg, bo);
}

// -------------------- launch --------------------
extern "C" void kernel_launch(void* const* d_in, const int* in_sizes, int n_in,
                              void* d_out, int out_size){
    const float* single = (const float*)d_in[0];
    const float* pair   = (const float*)d_in[1];
    const float* gs     = (const float*)d_in[2];
    const float* bs     = (const float*)d_in[3];
    const float* gz     = (const float*)d_in[4];
    const float* bz     = (const float*)d_in[5];
    const float* Wq     = (const float*)d_in[6];
    const float* Wk     = (const float*)d_in[7];
    const float* Wv     = (const float*)d_in[8];
    const float* Wb     = (const float*)d_in[9];
    const float* Wo     = (const float*)d_in[10];
    const float* bo     = (const float*)d_in[11];
    const float* Wg     = (const float*)d_in[12];
    const float* bg     = (const float*)d_in[13];
    float* out = (float*)d_out;

    conv_w_kernel<<<576, 256>>>(Wq, Wk, Wv, Wg);
    ln_single_kernel<<<L, 128>>>(single, gs, bs);
    ln_pair_bias_kernel<<<L, 256>>>((const float4*)pair, gz, bz, Wb);
    qkvg_mma<<<dim3(1536/64, L/64), 256>>>();
    s_mma<<<dim3(L/64, L/64, NH), 256>>>();
    softmax_kernel<<<NH*L, 256>>>();
    pv_mma<<<dim3(4, L/128, NH), 256>>>();
    final_kernel<<<dim3(CS/64, L/64), 128>>>(Wo, bo, single, bg, out);
}

// round 10
// speedup vs baseline: 1.5727x; 1.0402x over previous
#include <cuda_runtime.h>
#include <cuda_bf16.h>
#include <cstdint>
#include <math.h>

// AttentionWithPairBias: B=1, L=768, C_S=384, C_Z=128, H=8, HD=48
#define L 768
#define CS 384
#define NH 8
#define HD 48
#define LL (L*L)
#define OPS (L*CS)

// -------------------- scratch (device globals; no allocs) --------------------
__device__ float g_bias[(size_t)NH*LL];  // pair bias (fp32), read by attn
__device__ float g_gate[L*CS];
__device__ float g_opart[2*OPS];         // unnormalized O per j-split
__device__ float2 g_stat[2*NH*L];        // per split: (m, l) per (h, i)
__device__ __nv_bfloat16 g_ah[L*CS], g_al[L*CS];         // layernorm(single) hi/lo
__device__ __nv_bfloat16 g_wh[4*CS*CS], g_wl[4*CS*CS];   // Wq|Wk|Wv|Wg rows, hi/lo
__device__ __nv_bfloat16 g_qh[L*CS], g_ql[L*CS];         // Q hi/lo
__device__ __nv_bfloat16 g_kh[L*CS], g_kl[L*CS];         // K hi/lo
__device__ __nv_bfloat16 g_vth[CS*L], g_vtl[CS*L];       // V^T hi/lo: [d][j]

// -------------------- warp helpers --------------------
__device__ __forceinline__ float warp_sum(float v){
#pragma unroll
    for (int o = 16; o; o >>= 1) v += __shfl_xor_sync(0xffffffffu, v, o);
    return v;
}
__device__ __forceinline__ float tree8_distribute(float d[8], int lane){
    const unsigned F = 0xffffffffu;
    {
        bool up = (lane & 16) != 0;
#pragma unroll
        for (int k = 0; k < 4; k++){
            float send = up ? d[k]   : d[k+4];
            float keep = up ? d[k+4] : d[k];
            d[k] = keep + __shfl_xor_sync(F, send, 16);
        }
    }
    {
        bool up = (lane & 8) != 0;
#pragma unroll
        for (int k = 0; k < 2; k++){
            float send = up ? d[k]   : d[k+2];
            float keep = up ? d[k+2] : d[k];
            d[k] = keep + __shfl_xor_sync(F, send, 8);
        }
    }
    {
        bool up = (lane & 4) != 0;
        float send = up ? d[0] : d[1];
        float keep = up ? d[1] : d[0];
        d[0] = keep + __shfl_xor_sync(F, send, 4);
    }
    float v = d[0];
    v += __shfl_xor_sync(F, v, 2);
    v += __shfl_xor_sync(F, v, 1);
    return v;
}

// -------------------- mma.sync / ldmatrix / cp.async (plain PTX, sm_80+) ----
__device__ __forceinline__ uint32_t smem_u32(const void* p){
    uint32_t a;
    asm("{ .reg .u64 t; cvta.to.shared.u64 t, %1; cvt.u32.u64 %0, t; }" : "=r"(a) : "l"(p));
    return a;
}
__device__ __forceinline__ void ldsm4(uint32_t* r, uint32_t addr){
    asm volatile("ldmatrix.sync.aligned.m8n8.x4.shared.b16 {%0,%1,%2,%3}, [%4];"
        : "=r"(r[0]), "=r"(r[1]), "=r"(r[2]), "=r"(r[3]) : "r"(addr));
}
__device__ __forceinline__ void mma16816(float* c, const uint32_t* a, const uint32_t* b){
    asm volatile(
        "mma.sync.aligned.m16n8k16.row.col.f32.bf16.bf16.f32 "
        "{%0,%1,%2,%3}, {%4,%5,%6,%7}, {%8,%9}, {%0,%1,%2,%3};"
        : "+f"(c[0]), "+f"(c[1]), "+f"(c[2]), "+f"(c[3])
        : "r"(a[0]), "r"(a[1]), "r"(a[2]), "r"(a[3]), "r"(b[0]), "r"(b[1]));
}
__device__ __forceinline__ void cpa16(uint32_t dst, const void* src){
    asm volatile("cp.async.cg.shared.global [%0], [%1], 16;" :: "r"(dst), "l"(src));
}
#define CPA_COMMIT() asm volatile("cp.async.commit_group;" ::: "memory")
#define CPA_WAIT1()  asm volatile("cp.async.wait_group 1;" ::: "memory")
#define CPA_WAIT0()  asm volatile("cp.async.wait_group 0;" ::: "memory")

// slab: rows x 16 bf16 payload (32B), pitch 48B (conflict-free ldmatrix)
__device__ __forceinline__ void ldA(uint32_t a[4], uint32_t slab, int wm, int t){
    ldsm4(a, slab + (uint32_t)((wm + (t & 15))*48 + (t >> 4)*16));
}
__device__ __forceinline__ void ldB(uint32_t b[4], uint32_t slab, int nb16, int t){
    ldsm4(b, slab + (uint32_t)((nb16 + ((t >> 4) << 3) + (t & 7))*48 + ((t >> 3) & 1)*16));
}
__device__ __forceinline__ uint32_t packbf2(float a, float b){
    __nv_bfloat162 t = __halves2bfloat162(__float2bfloat16(a), __float2bfloat16(b));
    return *(uint32_t*)&t;
}

// -------------------- K0: split Wq|Wk|Wv|Wg into bf16 hi/lo ------------------
__global__ void conv_w_kernel(const float* __restrict__ Wq, const float* __restrict__ Wk,
                              const float* __restrict__ Wv, const float* __restrict__ Wg){
    int idx = blockIdx.x*256 + threadIdx.x;
    int n  = idx / 96;
    int kq = idx - n*96;
    int which = n / 384;
    int r = n - which*384;
    const float* W = (which == 0) ? Wq : (which == 1) ? Wk : (which == 2) ? Wv : Wg;
    float4 v = *(const float4*)(W + (size_t)r*CS + kq*4);
    float x[4] = {v.x, v.y, v.z, v.w};
    __nv_bfloat16 h[4], l[4];
#pragma unroll
    for (int e = 0; e < 4; e++){
        h[e] = __float2bfloat16(x[e]);
        l[e] = __float2bfloat16(x[e] - __bfloat162float(h[e]));
    }
    size_t o = (size_t)n*CS + kq*4;
    *(__nv_bfloat162*)(g_wh + o)     = __halves2bfloat162(h[0], h[1]);
    *(__nv_bfloat162*)(g_wh + o + 2) = __halves2bfloat162(h[2], h[3]);
    *(__nv_bfloat162*)(g_wl + o)     = __halves2bfloat162(l[0], l[1]);
    *(__nv_bfloat162*)(g_wl + o + 2) = __halves2bfloat162(l[2], l[3]);
}

// -------------------- K1: layernorm(single) -> bf16 hi/lo --------------------
__global__ void ln_single_kernel(const float* __restrict__ x,
                                 const float* __restrict__ g,
                                 const float* __restrict__ b){
    __shared__ float rs[4], rq[4];
    int i = blockIdx.x, t = threadIdx.x;     // 128 threads
    int lane = t & 31, w = t >> 5;
    float v[3];
#pragma unroll
    for (int e = 0; e < 3; e++) v[e] = x[i*CS + e*128 + t];
    float s = v[0] + v[1] + v[2];
    float q = v[0]*v[0] + v[1]*v[1] + v[2]*v[2];
    s = warp_sum(s); q = warp_sum(q);
    if (lane == 0){ rs[w] = s; rq[w] = q; }
    __syncthreads();
    s = rs[0] + rs[1] + rs[2] + rs[3];
    q = rq[0] + rq[1] + rq[2] + rq[3];
    float mu   = s * (1.f/CS);
    float var  = q * (1.f/CS) - mu*mu;
    float rstd = rsqrtf(var + 1e-5f);
#pragma unroll
    for (int e = 0; e < 3; e++){
        int c = e*128 + t;
        float y = (v[e] - mu) * rstd * g[c] + b[c];
        __nv_bfloat16 hh = __float2bfloat16(y);
        g_ah[i*CS + c] = hh;
        g_al[i*CS + c] = __float2bfloat16(y - __bfloat162float(hh));
    }
}

// -------------------- K2: layernorm(pair) + bias = zn @ Wb -------------------
__global__ void ln_pair_bias_kernel(const float4* __restrict__ z4,
                                    const float* __restrict__ gz,
                                    const float* __restrict__ bz,
                                    const float* __restrict__ Wb){
    __shared__ float stage[8][772];
    const unsigned F = 0xffffffffu;
    const int tid  = threadIdx.x;
    const int warp = tid >> 5, lane = tid & 31;
    const int i    = blockIdx.x;
    const int zb   = lane * 4;

    float gw[4][8];
    float Gp[8] = {0,0,0,0,0,0,0,0};
    float Bp[8] = {0,0,0,0,0,0,0,0};
#pragma unroll
    for (int e = 0; e < 4; e++){
        float gze = gz[zb+e], bze = bz[zb+e];
        float4 w0 = ((const float4*)Wb)[(zb+e)*2 + 0];
        float4 w1 = ((const float4*)Wb)[(zb+e)*2 + 1];
        float w[8] = {w0.x,w0.y,w0.z,w0.w,w1.x,w1.y,w1.z,w1.w};
#pragma unroll
        for (int h = 0; h < 8; h++){
            gw[e][h] = gze * w[h];
            Gp[h] += gw[e][h];
            Bp[h] = fmaf(bze, w[h], Bp[h]);
        }
    }
    float Gh = tree8_distribute(Gp, lane);
    float Bh = tree8_distribute(Bp, lane);
    const int myh = (((lane>>4)&1)<<2) | (((lane>>3)&1)<<1) | ((lane>>2)&1);

    for (int jj = 0; jj < 96; jj++){
        int j = warp*96 + jj;
        float4 zv = z4[((size_t)i*L + j)*32 + lane];
        float z0 = zv.x, z1 = zv.y, z2 = zv.z, z3 = zv.w;
        float s = z0+z1+z2+z3;
        float q = fmaf(z0,z0, fmaf(z1,z1, fmaf(z2,z2, z3*z3)));
        float d[8];
#pragma unroll
        for (int h = 0; h < 8; h++)
            d[h] = fmaf(z3, gw[3][h], fmaf(z2, gw[2][h], fmaf(z1, gw[1][h], z0*gw[0][h])));
#pragma unroll
        for (int o = 16; o; o >>= 1){
            s += __shfl_xor_sync(F, s, o);
            q += __shfl_xor_sync(F, q, o);
        }
        float rd = tree8_distribute(d, lane);
        float mu   = s * (1.f/128.f);
        float var  = q * (1.f/128.f) - mu*mu;
        float rstd = rsqrtf(var + 1e-5f);
        float bias = fmaf(rstd, rd, fmaf(-rstd*mu, Gh, Bh));
        if ((lane & 3) == 0) stage[myh][j] = bias;
    }
    __syncthreads();
#pragma unroll
    for (int t = tid; t < 8*L; t += 256){
        int h = t / L, j = t % L;
        g_bias[(size_t)h*LL + (size_t)i*L + j] = stage[h][j];
    }
}

// -------------------- K3: Q,K,V^T,Gate (pipelined mma, from R8) --------------
#define QCH 12288
__global__ void __launch_bounds__(256) qkvg_mma(){
    __shared__ __align__(16) char sm[2*QCH];
    const uint32_t sb = smem_u32(sm);
    const int tid = threadIdx.x, lane = tid & 31, wid = tid >> 5;
    const int wm16 = (wid & 3) * 16, wn32 = (wid >> 2) * 32;
    const int m0 = blockIdx.y * 64;
    const int ng = blockIdx.x * 64;

    float acc[4][4];
#pragma unroll
    for (int b = 0; b < 4; b++)
#pragma unroll
        for (int c = 0; c < 4; c++) acc[b][c] = 0.f;

    auto load = [&](int buf, int ch){
        int k = ch * 16;
#pragma unroll
        for (int u = 0; u < 2; u++){
            int idx = tid + u*256;
            int s = idx >> 7, rc = idx & 127, r = rc >> 1, c = rc & 1;
            const __nv_bfloat16* src =
                (s == 0) ? g_ah + (size_t)(m0+r)*CS + k + c*8 :
                (s == 1) ? g_al + (size_t)(m0+r)*CS + k + c*8 :
                (s == 2) ? g_wh + (size_t)(ng+r)*CS + k + c*8 :
                           g_wl + (size_t)(ng+r)*CS + k + c*8;
            cpa16(sb + buf*QCH + s*3072 + r*48 + c*16, src);
        }
        CPA_COMMIT();
    };

    load(0, 0);
    for (int ch = 0; ch < 24; ch++){
        if (ch + 1 < 24){ load((ch+1) & 1, ch+1); CPA_WAIT1(); }
        else CPA_WAIT0();
        __syncthreads();
        uint32_t base = sb + (ch & 1)*QCH;
        uint32_t ah[4], al[4], bh[2][4], bl[2][4];
        ldA(ah, base,        wm16, lane);
        ldA(al, base + 3072, wm16, lane);
#pragma unroll
        for (int pr = 0; pr < 2; pr++){
            ldB(bh[pr], base + 6144, wn32 + pr*16, lane);
            ldB(bl[pr], base + 9216, wn32 + pr*16, lane);
        }
#pragma unroll
        for (int nt = 0; nt < 4; nt++){
            const uint32_t* bhp = &bh[nt>>1][(nt&1)*2];
            const uint32_t* blp = &bl[nt>>1][(nt&1)*2];
            mma16816(acc[nt], ah, bhp);
            mma16816(acc[nt], al, bhp);
            mma16816(acc[nt], ah, blp);
        }
        __syncthreads();
    }

    const int which = ng / 384;
    const int nloc  = ng - which*384;
    const int rb = m0 + wm16 + (lane >> 2);
    const int cb = wn32 + (lane & 3)*2;
    if (which <= 1){
        __nv_bfloat16* PH = which ? g_kh : g_qh;
        __nv_bfloat16* PL = which ? g_kl : g_ql;
#pragma unroll
        for (int half = 0; half < 2; half++){
            int i = rb + half*8;
#pragma unroll
            for (int nt = 0; nt < 4; nt++){
                int cg = nloc + cb + nt*8;
                float v0 = acc[nt][half*2], v1 = acc[nt][half*2+1];
                __nv_bfloat16 h0 = __float2bfloat16(v0);
                __nv_bfloat16 h1 = __float2bfloat16(v1);
                __nv_bfloat16 l0 = __float2bfloat16(v0 - __bfloat162float(h0));
                __nv_bfloat16 l1 = __float2bfloat16(v1 - __bfloat162float(h1));
                *(__nv_bfloat162*)(PH + (size_t)i*CS + cg) = __halves2bfloat162(h0, h1);
                *(__nv_bfloat162*)(PL + (size_t)i*CS + cg) = __halves2bfloat162(l0, l1);
            }
        }
    } else if (which == 2){
#pragma unroll
        for (int half = 0; half < 2; half++){
            int i = rb + half*8;
#pragma unroll
            for (int nt = 0; nt < 4; nt++){
                int cg = nloc + cb + nt*8;
                float v0 = acc[nt][half*2], v1 = acc[nt][half*2+1];
                __nv_bfloat16 h0 = __float2bfloat16(v0);
                __nv_bfloat16 h1 = __float2bfloat16(v1);
                g_vth[(size_t)cg*L + i]     = h0;
                g_vth[(size_t)(cg+1)*L + i] = h1;
                g_vtl[(size_t)cg*L + i]     = __float2bfloat16(v0 - __bfloat162float(h0));
                g_vtl[(size_t)(cg+1)*L + i] = __float2bfloat16(v1 - __bfloat162float(h1));
            }
        }
    } else {
#pragma unroll
        for (int half = 0; half < 2; half++){
            int i = rb + half*8;
#pragma unroll
            for (int nt = 0; nt < 4; nt++){
                int cg = nloc + cb + nt*8;
                float2 v = make_float2(acc[nt][half*2], acc[nt][half*2+1]);
                *(float2*)(g_gate + (size_t)i*CS + cg) = v;
            }
        }
    }
}

// -------------------- K4: fused flash attention ------------------------------
// grid (jsplit=2, mtiles=12, h=8), 128 threads (4 warps x m16, full n=64).
// smem: K hi[0,9216) K lo[9216,18432) V hi[18432,27648) V lo[27648,36864)
__global__ void __launch_bounds__(128) attn_fused(){
    __shared__ __align__(16) char sm[36864];
    const uint32_t sb = smem_u32(sm);
    const int tid = threadIdx.x, lane = tid & 31, wid = tid >> 5;
    const int js = blockIdx.x;
    const int m0 = blockIdx.y * 64;
    const int h  = blockIdx.z;
    const int jb = js * 384;
    const float sc = 0.14433756729740643f;

    // --- stage Q tile through smem, keep A-fragments in registers ---
#pragma unroll
    for (int u = 0; u < 6; u++){
        int idx = tid + u*128;               // [0,768)
        int plane = idx / 384, rem = idx - plane*384;
        int s = rem >> 7, rc = rem & 127, r = rc >> 1, c = rc & 1;
        const __nv_bfloat16* src = (plane ? g_ql : g_qh)
            + (size_t)(m0+r)*CS + h*HD + s*16 + c*8;
        *(uint4*)(sm + plane*9216 + s*3072 + r*48 + c*16) = *(const uint4*)src;
    }
    __syncthreads();
    uint32_t qh[3][4], ql[3][4];
#pragma unroll
    for (int s = 0; s < 3; s++){
        ldA(qh[s], sb +        (uint32_t)(s*3072), wid*16, lane);
        ldA(ql[s], sb + 9216 + (uint32_t)(s*3072), wid*16, lane);
    }

    float mrow[2] = {-INFINITY, -INFINITY};
    float lrow[2] = {0.f, 0.f};
    float o[6][4];
#pragma unroll
    for (int dn = 0; dn < 6; dn++)
#pragma unroll
        for (int e = 0; e < 4; e++) o[dn][e] = 0.f;

    const int r0 = lane >> 2;                 // warp-local row (and +8)
    const int c0 = (lane & 3) * 2;

    for (int step = 0; step < 6; step++){
        int j0 = jb + step*64;
        __syncthreads();   // prior iteration's smem reads complete
        // load K tile (64 rows j x 48) hi/lo and V^T tile (48 rows d x 64 j) hi/lo
#pragma unroll
        for (int u = 0; u < 12; u++){
            int idx = tid + u*128;            // [0,1536)
            if (idx < 768){
                int plane = idx / 384, rem = idx - plane*384;
                int s = rem >> 7, rc = rem & 127, r = rc >> 1, c = rc & 1;
                const __nv_bfloat16* src = (plane ? g_kl : g_kh)
                    + (size_t)(j0+r)*CS + h*HD + s*16 + c*8;
                *(uint4*)(sm + plane*9216 + s*3072 + r*48 + c*16) = *(const uint4*)src;
            } else {
                int q2 = idx - 768;
                int plane = q2 / 384, rem = q2 - plane*384;
                int g = rem / 96, rc = rem - g*96, r = rc >> 1, c = rc & 1;
                const __nv_bfloat16* src = (plane ? g_vtl : g_vth)
                    + (size_t)(h*HD + r)*L + j0 + g*16 + c*8;
                *(uint4*)(sm + 18432 + plane*9216 + g*2304 + r*48 + c*16) = *(const uint4*)src;
            }
        }
        __syncthreads();

        // --- S = Q K^T (bf16-split, 3 terms) ---
        float s_[8][4];
#pragma unroll
        for (int nt = 0; nt < 8; nt++)
#pragma unroll
            for (int e = 0; e < 4; e++) s_[nt][e] = 0.f;
#pragma unroll
        for (int sl = 0; sl < 3; sl++){
            uint32_t bh[4][4], bl[4][4];
#pragma unroll
            for (int p = 0; p < 4; p++){
                ldB(bh[p], sb +        (uint32_t)(sl*3072), p*16, lane);
                ldB(bl[p], sb + 9216 + (uint32_t)(sl*3072), p*16, lane);
            }
#pragma unroll
            for (int nt = 0; nt < 8; nt++){
                const uint32_t* bhp = &bh[nt>>1][(nt&1)*2];
                const uint32_t* blp = &bl[nt>>1][(nt&1)*2];
                mma16816(s_[nt], qh[sl], bhp);
                mma16816(s_[nt], ql[sl], bhp);
                mma16816(s_[nt], qh[sl], blp);
            }
        }

        // --- add bias (direct from L2-resident g_bias) ---
#pragma unroll
        for (int nt = 0; nt < 8; nt++)
#pragma unroll
            for (int e = 0; e < 2; e++){
                int i = m0 + wid*16 + r0 + e*8;
                float2 b = *(const float2*)(g_bias + (size_t)h*LL + (size_t)i*L
                                            + j0 + nt*8 + c0);
                s_[nt][e*2]   = fmaf(s_[nt][e*2],   sc, b.x);
                s_[nt][e*2+1] = fmaf(s_[nt][e*2+1], sc, b.y);
            }

        // --- online softmax (rows fully inside warp quad) ---
#pragma unroll
        for (int e = 0; e < 2; e++){
            float mx = -INFINITY;
#pragma unroll
            for (int nt = 0; nt < 8; nt++)
                mx = fmaxf(mx, fmaxf(s_[nt][e*2], s_[nt][e*2+1]));
            mx = fmaxf(mx, __shfl_xor_sync(0xffffffffu, mx, 1));
            mx = fmaxf(mx, __shfl_xor_sync(0xffffffffu, mx, 2));
            float mn = fmaxf(mrow[e], mx);
            float alpha = __expf(mrow[e] - mn);
            mrow[e] = mn;
            float sum = 0.f;
#pragma unroll
            for (int nt = 0; nt < 8; nt++){
                float p0 = __expf(s_[nt][e*2]   - mn);
                float p1 = __expf(s_[nt][e*2+1] - mn);
                s_[nt][e*2] = p0; s_[nt][e*2+1] = p1;
                sum += p0 + p1;
            }
            sum += __shfl_xor_sync(0xffffffffu, sum, 1);
            sum += __shfl_xor_sync(0xffffffffu, sum, 2);
            lrow[e] = lrow[e]*alpha + sum;
#pragma unroll
            for (int dn = 0; dn < 6; dn++){
                o[dn][e*2]   *= alpha;
                o[dn][e*2+1] *= alpha;
            }
        }

        // --- O += P V  (P from C-frag -> A-frag identity, hi/lo split) ---
#pragma unroll
        for (int g = 0; g < 4; g++){
            uint32_t aH[4], aL[4];
#pragma unroll
            for (int half = 0; half < 2; half++){     // half 0: k 0-7 (nt=2g), 1: k 8-15
                int nt = 2*g + half;
#pragma unroll
                for (int e = 0; e < 2; e++){          // e 0: rows r0, 1: rows r0+8
                    float p0 = s_[nt][e*2], p1 = s_[nt][e*2+1];
                    uint32_t hi = packbf2(p0, p1);
                    __nv_bfloat162 hv = *(__nv_bfloat162*)&hi;
                    uint32_t lo = packbf2(p0 - __bfloat162float(hv.x),
                                          p1 - __bfloat162float(hv.y));
                    aH[half*2 + e] = hi;
                    aL[half*2 + e] = lo;
                }
            }
            uint32_t vh[3][4], vl[3][4];
#pragma unroll
            for (int q = 0; q < 3; q++){
                ldB(vh[q], sb + 18432 + (uint32_t)(g*2304), q*16, lane);
                ldB(vl[q], sb + 27648 + (uint32_t)(g*2304), q*16, lane);
            }
#pragma unroll
            for (int dn = 0; dn < 6; dn++){
                const uint32_t* vhp = &vh[dn>>1][(dn&1)*2];
                const uint32_t* vlp = &vl[dn>>1][(dn&1)*2];
                mma16816(o[dn], aH, vhp);
                mma16816(o[dn], aL, vhp);
                mma16816(o[dn], aH, vlp);
            }
        }
    }

    // --- write unnormalized O + stats ---
#pragma unroll
    for (int e = 0; e < 2; e++){
        int i = m0 + wid*16 + r0 + e*8;
        float* op = g_opart + (size_t)js*OPS + (size_t)i*CS + h*HD;
#pragma unroll
        for (int dn = 0; dn < 6; dn++)
            *(float2*)(op + dn*8 + c0) = make_float2(o[dn][e*2], o[dn][e*2+1]);
        if ((lane & 3) == 0)
            g_stat[js*NH*L + h*L + i] = make_float2(mrow[e], lrow[e]);
    }
}

// -------------------- K5: out = single + sigmoid(gate+bg)*(O@Wo^T+bo) -------
// A = softmax-combined O from 2 splits. 64x64 tile, BK=32, 128 threads.
__global__ void __launch_bounds__(128) final_kernel(
        const float* __restrict__ Wo, const float* __restrict__ bo,
        const float* __restrict__ single, const float* __restrict__ bg,
        float* __restrict__ out){
    __shared__ float As[32*68];
    __shared__ float Bs[32*68];
    const int tid = threadIdx.x;
    const int tx  = tid % 16, ty = tid / 16;   // TN=4, TM=8
    const int m0 = blockIdx.y*64, n0 = blockIdx.x*64;

    float acc[8][4];
#pragma unroll
    for (int i = 0; i < 8; i++)
#pragma unroll
        for (int j = 0; j < 4; j++) acc[i][j] = 0.f;

    for (int kt = 0; kt < CS; kt += 32){
#pragma unroll
        for (int u = 0; u < 4; u++){
            int t4 = tid + u*128;             // AF4 = 64*8 = 512
            int row = t4 >> 3, kq = t4 & 7;
            int c = kt + kq*4;
            int h = c / HD;
            int gi = m0 + row;
            float2 st0 = g_stat[h*L + gi];
            float2 st1 = g_stat[NH*L + h*L + gi];
            float M  = fmaxf(st0.x, st1.x);
            float w0 = __expf(st0.x - M), w1 = __expf(st1.x - M);
            float inv = 1.f / (w0*st0.y + w1*st1.y);
            w0 *= inv; w1 *= inv;
            const float* p = g_opart + (size_t)gi*CS + c;
            float4 v0 = *(const float4*)p;
            float4 v1 = *(const float4*)(p + OPS);
            float4 v;
            v.x = w0*v0.x + w1*v1.x; v.y = w0*v0.y + w1*v1.y;
            v.z = w0*v0.z + w1*v1.z; v.w = w0*v0.w + w1*v1.w;
            As[(kq*4+0)*68+row] = v.x; As[(kq*4+1)*68+row] = v.y;
            As[(kq*4+2)*68+row] = v.z; As[(kq*4+3)*68+row] = v.w;
        }
#pragma unroll
        for (int u = 0; u < 4; u++){
            int t4 = tid + u*128;             // BF4 = 64*8 = 512
            int row = t4 >> 3, kq = t4 & 7;
            float4 v = *(const float4*)(Wo + (size_t)(n0 + row)*CS + kt + kq*4);
            Bs[(kq*4+0)*68+row] = v.x; Bs[(kq*4+1)*68+row] = v.y;
            Bs[(kq*4+2)*68+row] = v.z; Bs[(kq*4+3)*68+row] = v.w;
        }
        __syncthreads();
#pragma unroll
        for (int kk = 0; kk < 32; kk++){
            float af[8], bf[4];
            *(float4*)&af[0] = *(const float4*)&As[kk*68 + ty*8];
            *(float4*)&af[4] = *(const float4*)&As[kk*68 + ty*8 + 4];
            *(float4*)&bf[0] = *(const float4*)&Bs[kk*68 + tx*4];
#pragma unroll
            for (int i = 0; i < 8; i++)
#pragma unroll
                for (int j = 0; j < 4; j++)
                    acc[i][j] = fmaf(af[i], bf[j], acc[i][j]);
        }
        __syncthreads();
    }

#pragma unroll
    for (int i = 0; i < 8; i++){
        int row = m0 + ty*8 + i;
#pragma unroll
        for (int j = 0; j < 4; j++){
            int col = n0 + tx*4 + j;
            float y  = acc[i][j] + bo[col];
            float gp = g_gate[(size_t)row*CS + col] + bg[col];
            float gg = 1.f / (1.f + __expf(-gp));
            out[(size_t)row*CS + col] = single[(size_t)row*CS + col] + gg * y;
        }
    }
}

// -------------------- launch --------------------
extern "C" void kernel_launch(void* const* d_in, const int* in_sizes, int n_in,
                              void* d_out, int out_size){
    const float* single = (const float*)d_in[0];
    const float* pair   = (const float*)d_in[1];
    const float* gs     = (const float*)d_in[2];
    const float* bs     = (const float*)d_in[3];
    const float* gz     = (const float*)d_in[4];
    const float* bz     = (const float*)d_in[5];
    const float* Wq     = (const float*)d_in[6];
    const float* Wk     = (const float*)d_in[7];
    const float* Wv     = (const float*)d_in[8];
    const float* Wb     = (const float*)d_in[9];
    const float* Wo     = (const float*)d_in[10];
    const float* bo     = (const float*)d_in[11];
    const float* Wg     = (const float*)d_in[12];
    const float* bg     = (const float*)d_in[13];
    float* out = (float*)d_out;

    conv_w_kernel<<<576, 256>>>(Wq, Wk, Wv, Wg);
    ln_single_kernel<<<L, 128>>>(single, gs, bs);
    ln_pair_bias_kernel<<<L, 256>>>((const float4*)pair, gz, bz, Wb);
    qkvg_mma<<<dim3(1536/64, L/64), 256>>>();
    attn_fused<<<dim3(2, L/64, NH), 128>>>();
    final_kernel<<<dim3(CS/64, L/64), 128>>>(Wo, bo, single, bg, out);
}

// round 11
// speedup vs baseline: 1.8837x; 1.1977x over previous
#include <cuda_runtime.h>
#include <cuda_bf16.h>
#include <cstdint>
#include <math.h>

// AttentionWithPairBias: B=1, L=768, C_S=384, C_Z=128, H=8, HD=48
#define L 768
#define CS 384
#define NH 8
#define HD 48
#define LL (L*L)
#define OPS (L*CS)
#define NSPLIT 4

// -------------------- scratch (device globals; no allocs) --------------------
__device__ float g_bias[(size_t)NH*LL];  // pair bias (fp32), read by attn
__device__ float g_gate[L*CS];
__device__ float g_opart[NSPLIT*OPS];    // unnormalized O per j-split
__device__ float2 g_stat[NSPLIT*NH*L];   // per split: (m, l) per (h, i)
__device__ __nv_bfloat16 g_ah[L*CS], g_al[L*CS];         // layernorm(single) hi/lo
__device__ __nv_bfloat16 g_wh[4*CS*CS], g_wl[4*CS*CS];   // Wq|Wk|Wv|Wg rows, hi/lo
__device__ __nv_bfloat16 g_qh[L*CS], g_ql[L*CS];         // Q hi/lo
__device__ __nv_bfloat16 g_kh[L*CS], g_kl[L*CS];         // K hi/lo
__device__ __nv_bfloat16 g_vth[CS*L], g_vtl[CS*L];       // V^T hi/lo: [d][j]

// -------------------- warp helpers --------------------
__device__ __forceinline__ float warp_sum(float v){
#pragma unroll
    for (int o = 16; o; o >>= 1) v += __shfl_xor_sync(0xffffffffu, v, o);
    return v;
}
__device__ __forceinline__ float tree8_distribute(float d[8], int lane){
    const unsigned F = 0xffffffffu;
    {
        bool up = (lane & 16) != 0;
#pragma unroll
        for (int k = 0; k < 4; k++){
            float send = up ? d[k]   : d[k+4];
            float keep = up ? d[k+4] : d[k];
            d[k] = keep + __shfl_xor_sync(F, send, 16);
        }
    }
    {
        bool up = (lane & 8) != 0;
#pragma unroll
        for (int k = 0; k < 2; k++){
            float send = up ? d[k]   : d[k+2];
            float keep = up ? d[k+2] : d[k];
            d[k] = keep + __shfl_xor_sync(F, send, 8);
        }
    }
    {
        bool up = (lane & 4) != 0;
        float send = up ? d[0] : d[1];
        float keep = up ? d[1] : d[0];
        d[0] = keep + __shfl_xor_sync(F, send, 4);
    }
    float v = d[0];
    v += __shfl_xor_sync(F, v, 2);
    v += __shfl_xor_sync(F, v, 1);
    return v;
}

// -------------------- mma.sync / ldmatrix / cp.async (plain PTX, sm_80+) ----
__device__ __forceinline__ uint32_t smem_u32(const void* p){
    uint32_t a;
    asm("{ .reg .u64 t; cvta.to.shared.u64 t, %1; cvt.u32.u64 %0, t; }" : "=r"(a) : "l"(p));
    return a;
}
__device__ __forceinline__ void ldsm4(uint32_t* r, uint32_t addr){
    asm volatile("ldmatrix.sync.aligned.m8n8.x4.shared.b16 {%0,%1,%2,%3}, [%4];"
        : "=r"(r[0]), "=r"(r[1]), "=r"(r[2]), "=r"(r[3]) : "r"(addr));
}
__device__ __forceinline__ void mma16816(float* c, const uint32_t* a, const uint32_t* b){
    asm volatile(
        "mma.sync.aligned.m16n8k16.row.col.f32.bf16.bf16.f32 "
        "{%0,%1,%2,%3}, {%4,%5,%6,%7}, {%8,%9}, {%0,%1,%2,%3};"
        : "+f"(c[0]), "+f"(c[1]), "+f"(c[2]), "+f"(c[3])
        : "r"(a[0]), "r"(a[1]), "r"(a[2]), "r"(a[3]), "r"(b[0]), "r"(b[1]));
}
__device__ __forceinline__ void cpa16(uint32_t dst, const void* src){
    asm volatile("cp.async.cg.shared.global [%0], [%1], 16;" :: "r"(dst), "l"(src));
}
#define CPA_COMMIT() asm volatile("cp.async.commit_group;" ::: "memory")
#define CPA_WAIT1()  asm volatile("cp.async.wait_group 1;" ::: "memory")
#define CPA_WAIT0()  asm volatile("cp.async.wait_group 0;" ::: "memory")

// slab: rows x 16 bf16 payload (32B), pitch 48B (conflict-free ldmatrix)
__device__ __forceinline__ void ldA(uint32_t a[4], uint32_t slab, int wm, int t){
    ldsm4(a, slab + (uint32_t)((wm + (t & 15))*48 + (t >> 4)*16));
}
__device__ __forceinline__ void ldB(uint32_t b[4], uint32_t slab, int nb16, int t){
    ldsm4(b, slab + (uint32_t)((nb16 + ((t >> 4) << 3) + (t & 7))*48 + ((t >> 3) & 1)*16));
}
__device__ __forceinline__ uint32_t packbf2(float a, float b){
    __nv_bfloat162 t = __halves2bfloat162(__float2bfloat16(a), __float2bfloat16(b));
    return *(uint32_t*)&t;
}

// -------------------- K0: split Wq|Wk|Wv|Wg into bf16 hi/lo ------------------
__global__ void conv_w_kernel(const float* __restrict__ Wq, const float* __restrict__ Wk,
                              const float* __restrict__ Wv, const float* __restrict__ Wg){
    int idx = blockIdx.x*256 + threadIdx.x;
    int n  = idx / 96;
    int kq = idx - n*96;
    int which = n / 384;
    int r = n - which*384;
    const float* W = (which == 0) ? Wq : (which == 1) ? Wk : (which == 2) ? Wv : Wg;
    float4 v = *(const float4*)(W + (size_t)r*CS + kq*4);
    float x[4] = {v.x, v.y, v.z, v.w};
    __nv_bfloat16 h[4], l[4];
#pragma unroll
    for (int e = 0; e < 4; e++){
        h[e] = __float2bfloat16(x[e]);
        l[e] = __float2bfloat16(x[e] - __bfloat162float(h[e]));
    }
    size_t o = (size_t)n*CS + kq*4;
    *(__nv_bfloat162*)(g_wh + o)     = __halves2bfloat162(h[0], h[1]);
    *(__nv_bfloat162*)(g_wh + o + 2) = __halves2bfloat162(h[2], h[3]);
    *(__nv_bfloat162*)(g_wl + o)     = __halves2bfloat162(l[0], l[1]);
    *(__nv_bfloat162*)(g_wl + o + 2) = __halves2bfloat162(l[2], l[3]);
}

// -------------------- K1: layernorm(single) -> bf16 hi/lo --------------------
__global__ void ln_single_kernel(const float* __restrict__ x,
                                 const float* __restrict__ g,
                                 const float* __restrict__ b){
    __shared__ float rs[4], rq[4];
    int i = blockIdx.x, t = threadIdx.x;     // 128 threads
    int lane = t & 31, w = t >> 5;
    float v[3];
#pragma unroll
    for (int e = 0; e < 3; e++) v[e] = x[i*CS + e*128 + t];
    float s = v[0] + v[1] + v[2];
    float q = v[0]*v[0] + v[1]*v[1] + v[2]*v[2];
    s = warp_sum(s); q = warp_sum(q);
    if (lane == 0){ rs[w] = s; rq[w] = q; }
    __syncthreads();
    s = rs[0] + rs[1] + rs[2] + rs[3];
    q = rq[0] + rq[1] + rq[2] + rq[3];
    float mu   = s * (1.f/CS);
    float var  = q * (1.f/CS) - mu*mu;
    float rstd = rsqrtf(var + 1e-5f);
#pragma unroll
    for (int e = 0; e < 3; e++){
        int c = e*128 + t;
        float y = (v[e] - mu) * rstd * g[c] + b[c];
        __nv_bfloat16 hh = __float2bfloat16(y);
        g_ah[i*CS + c] = hh;
        g_al[i*CS + c] = __float2bfloat16(y - __bfloat162float(hh));
    }
}

// -------------------- K2: layernorm(pair) + bias = zn @ Wb -------------------
// Prefetch next z-vector before the shuffle chain; unroll 2 for MLP.
__global__ void ln_pair_bias_kernel(const float4* __restrict__ z4,
                                    const float* __restrict__ gz,
                                    const float* __restrict__ bz,
                                    const float* __restrict__ Wb){
    __shared__ float stage[8][772];
    const unsigned F = 0xffffffffu;
    const int tid  = threadIdx.x;
    const int warp = tid >> 5, lane = tid & 31;
    const int i    = blockIdx.x;
    const int zb   = lane * 4;

    float gw[4][8];
    float Gp[8] = {0,0,0,0,0,0,0,0};
    float Bp[8] = {0,0,0,0,0,0,0,0};
#pragma unroll
    for (int e = 0; e < 4; e++){
        float gze = gz[zb+e], bze = bz[zb+e];
        float4 w0 = ((const float4*)Wb)[(zb+e)*2 + 0];
        float4 w1 = ((const float4*)Wb)[(zb+e)*2 + 1];
        float w[8] = {w0.x,w0.y,w0.z,w0.w,w1.x,w1.y,w1.z,w1.w};
#pragma unroll
        for (int h = 0; h < 8; h++){
            gw[e][h] = gze * w[h];
            Gp[h] += gw[e][h];
            Bp[h] = fmaf(bze, w[h], Bp[h]);
        }
    }
    float Gh = tree8_distribute(Gp, lane);
    float Bh = tree8_distribute(Bp, lane);
    const int myh = (((lane>>4)&1)<<2) | (((lane>>3)&1)<<1) | ((lane>>2)&1);

    const float4* zp = z4 + ((size_t)i*L + warp*96)*32 + lane;
    float4 zv = *zp;
#pragma unroll 2
    for (int jj = 0; jj < 96; jj++){
        int j = warp*96 + jj;
        float4 cur = zv;
        if (jj + 1 < 96) zv = zp[(size_t)(jj+1)*32];
        float z0 = cur.x, z1 = cur.y, z2 = cur.z, z3 = cur.w;
        float s = z0+z1+z2+z3;
        float q = fmaf(z0,z0, fmaf(z1,z1, fmaf(z2,z2, z3*z3)));
        float d[8];
#pragma unroll
        for (int h = 0; h < 8; h++)
            d[h] = fmaf(z3, gw[3][h], fmaf(z2, gw[2][h], fmaf(z1, gw[1][h], z0*gw[0][h])));
#pragma unroll
        for (int o = 16; o; o >>= 1){
            s += __shfl_xor_sync(F, s, o);
            q += __shfl_xor_sync(F, q, o);
        }
        float rd = tree8_distribute(d, lane);
        float mu   = s * (1.f/128.f);
        float var  = q * (1.f/128.f) - mu*mu;
        float rstd = rsqrtf(var + 1e-5f);
        float bias = fmaf(rstd, rd, fmaf(-rstd*mu, Gh, Bh));
        if ((lane & 3) == 0) stage[myh][j] = bias;
    }
    __syncthreads();
#pragma unroll
    for (int t = tid; t < 8*L; t += 256){
        int h = t / L, j = t % L;
        g_bias[(size_t)h*LL + (size_t)i*L + j] = stage[h][j];
    }
}

// -------------------- K3: Q,K,V^T,Gate (pipelined mma) -----------------------
#define QCH 12288
__global__ void __launch_bounds__(256) qkvg_mma(){
    __shared__ __align__(16) char sm[2*QCH];
    const uint32_t sb = smem_u32(sm);
    const int tid = threadIdx.x, lane = tid & 31, wid = tid >> 5;
    const int wm16 = (wid & 3) * 16, wn32 = (wid >> 2) * 32;
    const int m0 = blockIdx.y * 64;
    const int ng = blockIdx.x * 64;

    float acc[4][4];
#pragma unroll
    for (int b = 0; b < 4; b++)
#pragma unroll
        for (int c = 0; c < 4; c++) acc[b][c] = 0.f;

    auto load = [&](int buf, int ch){
        int k = ch * 16;
#pragma unroll
        for (int u = 0; u < 2; u++){
            int idx = tid + u*256;
            int s = idx >> 7, rc = idx & 127, r = rc >> 1, c = rc & 1;
            const __nv_bfloat16* src =
                (s == 0) ? g_ah + (size_t)(m0+r)*CS + k + c*8 :
                (s == 1) ? g_al + (size_t)(m0+r)*CS + k + c*8 :
                (s == 2) ? g_wh + (size_t)(ng+r)*CS + k + c*8 :
                           g_wl + (size_t)(ng+r)*CS + k + c*8;
            cpa16(sb + buf*QCH + s*3072 + r*48 + c*16, src);
        }
        CPA_COMMIT();
    };

    load(0, 0);
    for (int ch = 0; ch < 24; ch++){
        if (ch + 1 < 24){ load((ch+1) & 1, ch+1); CPA_WAIT1(); }
        else CPA_WAIT0();
        __syncthreads();
        uint32_t base = sb + (ch & 1)*QCH;
        uint32_t ah[4], al[4], bh[2][4], bl[2][4];
        ldA(ah, base,        wm16, lane);
        ldA(al, base + 3072, wm16, lane);
#pragma unroll
        for (int pr = 0; pr < 2; pr++){
            ldB(bh[pr], base + 6144, wn32 + pr*16, lane);
            ldB(bl[pr], base + 9216, wn32 + pr*16, lane);
        }
#pragma unroll
        for (int nt = 0; nt < 4; nt++){
            const uint32_t* bhp = &bh[nt>>1][(nt&1)*2];
            const uint32_t* blp = &bl[nt>>1][(nt&1)*2];
            mma16816(acc[nt], ah, bhp);
            mma16816(acc[nt], al, bhp);
            mma16816(acc[nt], ah, blp);
        }
        __syncthreads();
    }

    const int which = ng / 384;
    const int nloc  = ng - which*384;
    const int rb = m0 + wm16 + (lane >> 2);
    const int cb = wn32 + (lane & 3)*2;
    if (which <= 1){
        __nv_bfloat16* PH = which ? g_kh : g_qh;
        __nv_bfloat16* PL = which ? g_kl : g_ql;
#pragma unroll
        for (int half = 0; half < 2; half++){
            int i = rb + half*8;
#pragma unroll
            for (int nt = 0; nt < 4; nt++){
                int cg = nloc + cb + nt*8;
                float v0 = acc[nt][half*2], v1 = acc[nt][half*2+1];
                __nv_bfloat16 h0 = __float2bfloat16(v0);
                __nv_bfloat16 h1 = __float2bfloat16(v1);
                __nv_bfloat16 l0 = __float2bfloat16(v0 - __bfloat162float(h0));
                __nv_bfloat16 l1 = __float2bfloat16(v1 - __bfloat162float(h1));
                *(__nv_bfloat162*)(PH + (size_t)i*CS + cg) = __halves2bfloat162(h0, h1);
                *(__nv_bfloat162*)(PL + (size_t)i*CS + cg) = __halves2bfloat162(l0, l1);
            }
        }
    } else if (which == 2){
#pragma unroll
        for (int half = 0; half < 2; half++){
            int i = rb + half*8;
#pragma unroll
            for (int nt = 0; nt < 4; nt++){
                int cg = nloc + cb + nt*8;
                float v0 = acc[nt][half*2], v1 = acc[nt][half*2+1];
                __nv_bfloat16 h0 = __float2bfloat16(v0);
                __nv_bfloat16 h1 = __float2bfloat16(v1);
                g_vth[(size_t)cg*L + i]     = h0;
                g_vth[(size_t)(cg+1)*L + i] = h1;
                g_vtl[(size_t)cg*L + i]     = __float2bfloat16(v0 - __bfloat162float(h0));
                g_vtl[(size_t)(cg+1)*L + i] = __float2bfloat16(v1 - __bfloat162float(h1));
            }
        }
    } else {
#pragma unroll
        for (int half = 0; half < 2; half++){
            int i = rb + half*8;
#pragma unroll
            for (int nt = 0; nt < 4; nt++){
                int cg = nloc + cb + nt*8;
                float2 v = make_float2(acc[nt][half*2], acc[nt][half*2+1]);
                *(float2*)(g_gate + (size_t)i*CS + cg) = v;
            }
        }
    }
}

// -------------------- K4: fused flash attention ------------------------------
// grid (jsplit=4, mtiles=12, h=8), 128 threads (4 warps x m16, full n=64).
// smem: K hi[0,9216) K lo[9216,18432) V hi[18432,27648) V lo[27648,36864)
__global__ void __launch_bounds__(128) attn_fused(){
    __shared__ __align__(16) char sm[36864];
    const uint32_t sb = smem_u32(sm);
    const int tid = threadIdx.x, lane = tid & 31, wid = tid >> 5;
    const int js = blockIdx.x;
    const int m0 = blockIdx.y * 64;
    const int h  = blockIdx.z;
    const int jb = js * 192;
    const float sc = 0.14433756729740643f;

    // --- stage Q tile through smem, keep A-fragments in registers ---
#pragma unroll
    for (int u = 0; u < 6; u++){
        int idx = tid + u*128;               // [0,768)
        int plane = idx / 384, rem = idx - plane*384;
        int s = rem >> 7, rc = rem & 127, r = rc >> 1, c = rc & 1;
        const __nv_bfloat16* src = (plane ? g_ql : g_qh)
            + (size_t)(m0+r)*CS + h*HD + s*16 + c*8;
        *(uint4*)(sm + plane*9216 + s*3072 + r*48 + c*16) = *(const uint4*)src;
    }
    __syncthreads();
    uint32_t qh[3][4], ql[3][4];
#pragma unroll
    for (int s = 0; s < 3; s++){
        ldA(qh[s], sb +        (uint32_t)(s*3072), wid*16, lane);
        ldA(ql[s], sb + 9216 + (uint32_t)(s*3072), wid*16, lane);
    }

    float mrow[2] = {-INFINITY, -INFINITY};
    float lrow[2] = {0.f, 0.f};
    float o[6][4];
#pragma unroll
    for (int dn = 0; dn < 6; dn++)
#pragma unroll
        for (int e = 0; e < 4; e++) o[dn][e] = 0.f;

    const int r0 = lane >> 2;                 // warp-local row (and +8)
    const int c0 = (lane & 3) * 2;

    for (int step = 0; step < 3; step++){
        int j0 = jb + step*64;
        __syncthreads();   // prior iteration's smem reads complete
        // load K tile (64 rows j x 48) hi/lo and V^T tile (48 rows d x 64 j) hi/lo
#pragma unroll
        for (int u = 0; u < 12; u++){
            int idx = tid + u*128;            // [0,1536)
            if (idx < 768){
                int plane = idx / 384, rem = idx - plane*384;
                int s = rem >> 7, rc = rem & 127, r = rc >> 1, c = rc & 1;
                const __nv_bfloat16* src = (plane ? g_kl : g_kh)
                    + (size_t)(j0+r)*CS + h*HD + s*16 + c*8;
                *(uint4*)(sm + plane*9216 + s*3072 + r*48 + c*16) = *(const uint4*)src;
            } else {
                int q2 = idx - 768;
                int plane = q2 / 384, rem = q2 - plane*384;
                int g = rem / 96, rc = rem - g*96, r = rc >> 1, c = rc & 1;
                const __nv_bfloat16* src = (plane ? g_vtl : g_vth)
                    + (size_t)(h*HD + r)*L + j0 + g*16 + c*8;
                *(uint4*)(sm + 18432 + plane*9216 + g*2304 + r*48 + c*16) = *(const uint4*)src;
            }
        }
        __syncthreads();

        // --- S = Q K^T (bf16-split, 3 terms) ---
        float s_[8][4];
#pragma unroll
        for (int nt = 0; nt < 8; nt++)
#pragma unroll
            for (int e = 0; e < 4; e++) s_[nt][e] = 0.f;
#pragma unroll
        for (int sl = 0; sl < 3; sl++){
            uint32_t bh[4][4], bl[4][4];
#pragma unroll
            for (int p = 0; p < 4; p++){
                ldB(bh[p], sb +        (uint32_t)(sl*3072), p*16, lane);
                ldB(bl[p], sb + 9216 + (uint32_t)(sl*3072), p*16, lane);
            }
#pragma unroll
            for (int nt = 0; nt < 8; nt++){
                const uint32_t* bhp = &bh[nt>>1][(nt&1)*2];
                const uint32_t* blp = &bl[nt>>1][(nt&1)*2];
                mma16816(s_[nt], qh[sl], bhp);
                mma16816(s_[nt], ql[sl], bhp);
                mma16816(s_[nt], qh[sl], blp);
            }
        }

        // --- add bias (direct from L2-resident g_bias) ---
#pragma unroll
        for (int nt = 0; nt < 8; nt++)
#pragma unroll
            for (int e = 0; e < 2; e++){
                int i = m0 + wid*16 + r0 + e*8;
                float2 b = *(const float2*)(g_bias + (size_t)h*LL + (size_t)i*L
                                            + j0 + nt*8 + c0);
                s_[nt][e*2]   = fmaf(s_[nt][e*2],   sc, b.x);
                s_[nt][e*2+1] = fmaf(s_[nt][e*2+1], sc, b.y);
            }

        // --- online softmax (rows fully inside warp quad) ---
#pragma unroll
        for (int e = 0; e < 2; e++){
            float mx = -INFINITY;
#pragma unroll
            for (int nt = 0; nt < 8; nt++)
                mx = fmaxf(mx, fmaxf(s_[nt][e*2], s_[nt][e*2+1]));
            mx = fmaxf(mx, __shfl_xor_sync(0xffffffffu, mx, 1));
            mx = fmaxf(mx, __shfl_xor_sync(0xffffffffu, mx, 2));
            float mn = fmaxf(mrow[e], mx);
            float alpha = __expf(mrow[e] - mn);
            mrow[e] = mn;
            float sum = 0.f;
#pragma unroll
            for (int nt = 0; nt < 8; nt++){
                float p0 = __expf(s_[nt][e*2]   - mn);
                float p1 = __expf(s_[nt][e*2+1] - mn);
                s_[nt][e*2] = p0; s_[nt][e*2+1] = p1;
                sum += p0 + p1;
            }
            sum += __shfl_xor_sync(0xffffffffu, sum, 1);
            sum += __shfl_xor_sync(0xffffffffu, sum, 2);
            lrow[e] = lrow[e]*alpha + sum;
#pragma unroll
            for (int dn = 0; dn < 6; dn++){
                o[dn][e*2]   *= alpha;
                o[dn][e*2+1] *= alpha;
            }
        }

        // --- O += P V  (P from C-frag -> A-frag identity, hi/lo split) ---
#pragma unroll
        for (int g = 0; g < 4; g++){
            uint32_t aH[4], aL[4];
#pragma unroll
            for (int half = 0; half < 2; half++){
                int nt = 2*g + half;
#pragma unroll
                for (int e = 0; e < 2; e++){
                    float p0 = s_[nt][e*2], p1 = s_[nt][e*2+1];
                    uint32_t hi = packbf2(p0, p1);
                    __nv_bfloat162 hv = *(__nv_bfloat162*)&hi;
                    uint32_t lo = packbf2(p0 - __bfloat162float(hv.x),
                                          p1 - __bfloat162float(hv.y));
                    aH[half*2 + e] = hi;
                    aL[half*2 + e] = lo;
                }
            }
            uint32_t vh[3][4], vl[3][4];
#pragma unroll
            for (int q = 0; q < 3; q++){
                ldB(vh[q], sb + 18432 + (uint32_t)(g*2304), q*16, lane);
                ldB(vl[q], sb + 27648 + (uint32_t)(g*2304), q*16, lane);
            }
#pragma unroll
            for (int dn = 0; dn < 6; dn++){
                const uint32_t* vhp = &vh[dn>>1][(dn&1)*2];
                const uint32_t* vlp = &vl[dn>>1][(dn&1)*2];
                mma16816(o[dn], aH, vhp);
                mma16816(o[dn], aL, vhp);
                mma16816(o[dn], aH, vlp);
            }
        }
    }

    // --- write unnormalized O + stats ---
#pragma unroll
    for (int e = 0; e < 2; e++){
        int i = m0 + wid*16 + r0 + e*8;
        float* op = g_opart + (size_t)js*OPS + (size_t)i*CS + h*HD;
#pragma unroll
        for (int dn = 0; dn < 6; dn++)
            *(float2*)(op + dn*8 + c0) = make_float2(o[dn][e*2], o[dn][e*2+1]);
        if ((lane & 3) == 0)
            g_stat[js*NH*L + h*L + i] = make_float2(mrow[e], lrow[e]);
    }
}

// -------------------- K5: out = single + sigmoid(gate+bg)*(O@Wo^T+bo) -------
// A = softmax-combined O from NSPLIT splits. 64x64 tile, BK=32, 128 threads.
__global__ void __launch_bounds__(128) final_kernel(
        const float* __restrict__ Wo, const float* __restrict__ bo,
        const float* __restrict__ single, const float* __restrict__ bg,
        float* __restrict__ out){
    __shared__ float As[32*68];
    __shared__ float Bs[32*68];
    __shared__ float wsm[64][8][NSPLIT];    // combine weights per (row, head)
    const int tid = threadIdx.x;
    const int tx  = tid % 16, ty = tid / 16;   // TN=4, TM=8
    const int m0 = blockIdx.y*64, n0 = blockIdx.x*64;

    // precompute split-combine weights
    for (int p = tid; p < 64*8; p += 128){
        int row = p >> 3, h = p & 7;
        int gi = m0 + row;
        float2 st[NSPLIT];
        float M = -INFINITY;
#pragma unroll
        for (int s = 0; s < NSPLIT; s++){
            st[s] = g_stat[s*NH*L + h*L + gi];
            M = fmaxf(M, st[s].x);
        }
        float w[NSPLIT], den = 0.f;
#pragma unroll
        for (int s = 0; s < NSPLIT; s++){
            w[s] = __expf(st[s].x - M);
            den = fmaf(w[s], st[s].y, den);
        }
        float inv = 1.f / den;
#pragma unroll
        for (int s = 0; s < NSPLIT; s++) wsm[row][h][s] = w[s]*inv;
    }
    __syncthreads();

    float acc[8][4];
#pragma unroll
    for (int i = 0; i < 8; i++)
#pragma unroll
        for (int j = 0; j < 4; j++) acc[i][j] = 0.f;

    for (int kt = 0; kt < CS; kt += 32){
#pragma unroll
        for (int u = 0; u < 4; u++){
            int t4 = tid + u*128;             // AF4 = 64*8 = 512
            int row = t4 >> 3, kq = t4 & 7;
            int c = kt + kq*4;
            int h = c / HD;
            int gi = m0 + row;
            const float* p = g_opart + (size_t)gi*CS + c;
            float4 v = make_float4(0.f, 0.f, 0.f, 0.f);
#pragma unroll
            for (int s = 0; s < NSPLIT; s++){
                float ws = wsm[row][h][s];
                float4 vs = *(const float4*)(p + (size_t)s*OPS);
                v.x = fmaf(ws, vs.x, v.x); v.y = fmaf(ws, vs.y, v.y);
                v.z = fmaf(ws, vs.z, v.z); v.w = fmaf(ws, vs.w, v.w);
            }
            As[(kq*4+0)*68+row] = v.x; As[(kq*4+1)*68+row] = v.y;
            As[(kq*4+2)*68+row] = v.z; As[(kq*4+3)*68+row] = v.w;
        }
#pragma unroll
        for (int u = 0; u < 4; u++){
            int t4 = tid + u*128;             // BF4 = 64*8 = 512
            int row = t4 >> 3, kq = t4 & 7;
            float4 v = *(const float4*)(Wo + (size_t)(n0 + row)*CS + kt + kq*4);
            Bs[(kq*4+0)*68+row] = v.x; Bs[(kq*4+1)*68+row] = v.y;
            Bs[(kq*4+2)*68+row] = v.z; Bs[(kq*4+3)*68+row] = v.w;
        }
        __syncthreads();
#pragma unroll
        for (int kk = 0; kk < 32; kk++){
            float af[8], bf[4];
            *(float4*)&af[0] = *(const float4*)&As[kk*68 + ty*8];
            *(float4*)&af[4] = *(const float4*)&As[kk*68 + ty*8 + 4];
            *(float4*)&bf[0] = *(const float4*)&Bs[kk*68 + tx*4];
#pragma unroll
            for (int i = 0; i < 8; i++)
#pragma unroll
                for (int j = 0; j < 4; j++)
                    acc[i][j] = fmaf(af[i], bf[j], acc[i][j]);
        }
        __syncthreads();
    }

#pragma unroll
    for (int i = 0; i < 8; i++){
        int row = m0 + ty*8 + i;
#pragma unroll
        for (int j = 0; j < 4; j++){
            int col = n0 + tx*4 + j;
            float y  = acc[i][j] + bo[col];
            float gp = g_gate[(size_t)row*CS + col] + bg[col];
            float gg = 1.f / (1.f + __expf(-gp));
            out[(size_t)row*CS + col] = single[(size_t)row*CS + col] + gg * y;
        }
    }
}

// -------------------- launch --------------------
extern "C" void kernel_launch(void* const* d_in, const int* in_sizes, int n_in,
                              void* d_out, int out_size){
    const float* single = (const float*)d_in[0];
    const float* pair   = (const float*)d_in[1];
    const float* gs     = (const float*)d_in[2];
    const float* bs     = (const float*)d_in[3];
    const float* gz     = (const float*)d_in[4];
    const float* bz     = (const float*)d_in[5];
    const float* Wq     = (const float*)d_in[6];
    const float* Wk     = (const float*)d_in[7];
    const float* Wv     = (const float*)d_in[8];
    const float* Wb     = (const float*)d_in[9];
    const float* Wo     = (const float*)d_in[10];
    const float* bo     = (const float*)d_in[11];
    const float* Wg     = (const float*)d_in[12];
    const float* bg     = (const float*)d_in[13];
    float* out = (float*)d_out;

    // NOTE: ln_pair_bias moved to 4th slot (profiler captures launch #4);
    // dependency-legal since qkvg only needs ln_single + conv_w outputs.
    conv_w_kernel<<<576, 256>>>(Wq, Wk, Wv, Wg);
    ln_single_kernel<<<L, 128>>>(single, gs, bs);
    qkvg_mma<<<dim3(1536/64, L/64), 256>>>();
    ln_pair_bias_kernel<<<L, 256>>>((const float4*)pair, gz, bz, Wb);
    attn_fused<<<dim3(NSPLIT, L/64, NH), 128>>>();
    final_kernel<<<dim3(CS/64, L/64), 128>>>(Wo, bo, single, bg, out);
}

// round 12
// speedup vs baseline: 2.0038x; 1.0638x over previous
#include <cuda_runtime.h>
#include <cuda_bf16.h>
#include <cstdint>
#include <math.h>

// AttentionWithPairBias: B=1, L=768, C_S=384, C_Z=128, H=8, HD=48
#define L 768
#define CS 384
#define NH 8
#define HD 48
#define LL (L*L)
#define OPS (L*CS)
#define NSPLIT 4

// -------------------- scratch (device globals; no allocs) --------------------
__device__ float g_bias[(size_t)NH*LL];  // pair bias (fp32), read by attn
__device__ float g_gate[L*CS];
__device__ float g_opart[NSPLIT*OPS];    // unnormalized O per j-split
__device__ float2 g_stat[NSPLIT*NH*L];   // per split: (m, l) per (h, i)
__device__ __nv_bfloat16 g_ah[L*CS], g_al[L*CS];         // layernorm(single) hi/lo
__device__ __nv_bfloat16 g_wh[4*CS*CS], g_wl[4*CS*CS];   // Wq|Wk|Wv|Wg rows, hi/lo
__device__ __nv_bfloat16 g_qh[L*CS], g_ql[L*CS];         // Q hi/lo
__device__ __nv_bfloat16 g_kh[L*CS], g_kl[L*CS];         // K hi/lo
__device__ __nv_bfloat16 g_vth[CS*L], g_vtl[CS*L];       // V^T hi/lo: [d][j]

// -------------------- warp helpers --------------------
__device__ __forceinline__ float warp_sum(float v){
#pragma unroll
    for (int o = 16; o; o >>= 1) v += __shfl_xor_sync(0xffffffffu, v, o);
    return v;
}
__device__ __forceinline__ float tree8_distribute(float d[8], int lane){
    const unsigned F = 0xffffffffu;
    {
        bool up = (lane & 16) != 0;
#pragma unroll
        for (int k = 0; k < 4; k++){
            float send = up ? d[k]   : d[k+4];
            float keep = up ? d[k+4] : d[k];
            d[k] = keep + __shfl_xor_sync(F, send, 16);
        }
    }
    {
        bool up = (lane & 8) != 0;
#pragma unroll
        for (int k = 0; k < 2; k++){
            float send = up ? d[k]   : d[k+2];
            float keep = up ? d[k+2] : d[k];
            d[k] = keep + __shfl_xor_sync(F, send, 8);
        }
    }
    {
        bool up = (lane & 4) != 0;
        float send = up ? d[0] : d[1];
        float keep = up ? d[1] : d[0];
        d[0] = keep + __shfl_xor_sync(F, send, 4);
    }
    float v = d[0];
    v += __shfl_xor_sync(F, v, 2);
    v += __shfl_xor_sync(F, v, 1);
    return v;
}

// -------------------- mma.sync / ldmatrix / cp.async (plain PTX, sm_80+) ----
__device__ __forceinline__ uint32_t smem_u32(const void* p){
    uint32_t a;
    asm("{ .reg .u64 t; cvta.to.shared.u64 t, %1; cvt.u32.u64 %0, t; }" : "=r"(a) : "l"(p));
    return a;
}
__device__ __forceinline__ void ldsm4(uint32_t* r, uint32_t addr){
    asm volatile("ldmatrix.sync.aligned.m8n8.x4.shared.b16 {%0,%1,%2,%3}, [%4];"
        : "=r"(r[0]), "=r"(r[1]), "=r"(r[2]), "=r"(r[3]) : "r"(addr));
}
__device__ __forceinline__ void mma16816(float* c, const uint32_t* a, const uint32_t* b){
    asm volatile(
        "mma.sync.aligned.m16n8k16.row.col.f32.bf16.bf16.f32 "
        "{%0,%1,%2,%3}, {%4,%5,%6,%7}, {%8,%9}, {%0,%1,%2,%3};"
        : "+f"(c[0]), "+f"(c[1]), "+f"(c[2]), "+f"(c[3])
        : "r"(a[0]), "r"(a[1]), "r"(a[2]), "r"(a[3]), "r"(b[0]), "r"(b[1]));
}
__device__ __forceinline__ void cpa16(uint32_t dst, const void* src){
    asm volatile("cp.async.cg.shared.global [%0], [%1], 16;" :: "r"(dst), "l"(src));
}
#define CPA_COMMIT() asm volatile("cp.async.commit_group;" ::: "memory")
#define CPA_WAIT1()  asm volatile("cp.async.wait_group 1;" ::: "memory")
#define CPA_WAIT0()  asm volatile("cp.async.wait_group 0;" ::: "memory")

// slab: rows x 16 bf16 payload (32B), pitch 48B (conflict-free ldmatrix)
__device__ __forceinline__ void ldA(uint32_t a[4], uint32_t slab, int wm, int t){
    ldsm4(a, slab + (uint32_t)((wm + (t & 15))*48 + (t >> 4)*16));
}
__device__ __forceinline__ void ldB(uint32_t b[4], uint32_t slab, int nb16, int t){
    ldsm4(b, slab + (uint32_t)((nb16 + ((t >> 4) << 3) + (t & 7))*48 + ((t >> 3) & 1)*16));
}
__device__ __forceinline__ uint32_t packbf2(float a, float b){
    __nv_bfloat162 t = __halves2bfloat162(__float2bfloat16(a), __float2bfloat16(b));
    return *(uint32_t*)&t;
}

// -------------------- K0: split Wq|Wk|Wv|Wg into bf16 hi/lo ------------------
__global__ void conv_w_kernel(const float* __restrict__ Wq, const float* __restrict__ Wk,
                              const float* __restrict__ Wv, const float* __restrict__ Wg){
    int idx = blockIdx.x*256 + threadIdx.x;
    int n  = idx / 96;
    int kq = idx - n*96;
    int which = n / 384;
    int r = n - which*384;
    const float* W = (which == 0) ? Wq : (which == 1) ? Wk : (which == 2) ? Wv : Wg;
    float4 v = *(const float4*)(W + (size_t)r*CS + kq*4);
    float x[4] = {v.x, v.y, v.z, v.w};
    __nv_bfloat16 h[4], l[4];
#pragma unroll
    for (int e = 0; e < 4; e++){
        h[e] = __float2bfloat16(x[e]);
        l[e] = __float2bfloat16(x[e] - __bfloat162float(h[e]));
    }
    size_t o = (size_t)n*CS + kq*4;
    *(__nv_bfloat162*)(g_wh + o)     = __halves2bfloat162(h[0], h[1]);
    *(__nv_bfloat162*)(g_wh + o + 2) = __halves2bfloat162(h[2], h[3]);
    *(__nv_bfloat162*)(g_wl + o)     = __halves2bfloat162(l[0], l[1]);
    *(__nv_bfloat162*)(g_wl + o + 2) = __halves2bfloat162(l[2], l[3]);
}

// -------------------- K1: layernorm(single) -> bf16 hi/lo --------------------
__global__ void ln_single_kernel(const float* __restrict__ x,
                                 const float* __restrict__ g,
                                 const float* __restrict__ b){
    __shared__ float rs[4], rq[4];
    int i = blockIdx.x, t = threadIdx.x;     // 128 threads
    int lane = t & 31, w = t >> 5;
    float v[3];
#pragma unroll
    for (int e = 0; e < 3; e++) v[e] = x[i*CS + e*128 + t];
    float s = v[0] + v[1] + v[2];
    float q = v[0]*v[0] + v[1]*v[1] + v[2]*v[2];
    s = warp_sum(s); q = warp_sum(q);
    if (lane == 0){ rs[w] = s; rq[w] = q; }
    __syncthreads();
    s = rs[0] + rs[1] + rs[2] + rs[3];
    q = rq[0] + rq[1] + rq[2] + rq[3];
    float mu   = s * (1.f/CS);
    float var  = q * (1.f/CS) - mu*mu;
    float rstd = rsqrtf(var + 1e-5f);
#pragma unroll
    for (int e = 0; e < 3; e++){
        int c = e*128 + t;
        float y = (v[e] - mu) * rstd * g[c] + b[c];
        __nv_bfloat16 hh = __float2bfloat16(y);
        g_ah[i*CS + c] = hh;
        g_al[i*CS + c] = __float2bfloat16(y - __bfloat162float(hh));
    }
}

// -------------------- K2: layernorm(pair) + bias = zn @ Wb -------------------
// v3: 4-j batches; all reductions interleaved round-by-round across the batch
// so the shuffle chains of 4 independent j's overlap (latency hiding by ILP).
__global__ void __launch_bounds__(256, 2) ln_pair_bias_kernel(
                                    const float4* __restrict__ z4,
                                    const float* __restrict__ gz,
                                    const float* __restrict__ bz,
                                    const float* __restrict__ Wb){
    __shared__ float stage[8][772];
    const unsigned F = 0xffffffffu;
    const int tid  = threadIdx.x;
    const int warp = tid >> 5, lane = tid & 31;
    const int i    = blockIdx.x;
    const int zb   = lane * 4;

    float gw[4][8];
    float Gp[8] = {0,0,0,0,0,0,0,0};
    float Bp[8] = {0,0,0,0,0,0,0,0};
#pragma unroll
    for (int e = 0; e < 4; e++){
        float gze = gz[zb+e], bze = bz[zb+e];
        float4 w0 = ((const float4*)Wb)[(zb+e)*2 + 0];
        float4 w1 = ((const float4*)Wb)[(zb+e)*2 + 1];
        float w[8] = {w0.x,w0.y,w0.z,w0.w,w1.x,w1.y,w1.z,w1.w};
#pragma unroll
        for (int h = 0; h < 8; h++){
            gw[e][h] = gze * w[h];
            Gp[h] += gw[e][h];
            Bp[h] = fmaf(bze, w[h], Bp[h]);
        }
    }
    float Gh = tree8_distribute(Gp, lane);
    float Bh = tree8_distribute(Bp, lane);
    const int myh = (((lane>>4)&1)<<2) | (((lane>>3)&1)<<1) | ((lane>>2)&1);

    const float4* zp = z4 + ((size_t)i*L + warp*96)*32 + lane;

    for (int b = 0; b < 24; b++){
        float S[4], Q[4], D[4][8];
        // --- partials: 4 independent loads + FMA blocks ---
#pragma unroll
        for (int u = 0; u < 4; u++){
            float4 zv = zp[(size_t)(b*4 + u)*32];
            float z0 = zv.x, z1 = zv.y, z2 = zv.z, z3 = zv.w;
            S[u] = z0+z1+z2+z3;
            Q[u] = fmaf(z0,z0, fmaf(z1,z1, fmaf(z2,z2, z3*z3)));
#pragma unroll
            for (int h = 0; h < 8; h++)
                D[u][h] = fmaf(z3, gw[3][h], fmaf(z2, gw[2][h],
                          fmaf(z1, gw[1][h], z0*gw[0][h])));
        }
        // --- S,Q butterfly, interleaved across u ---
#pragma unroll
        for (int o = 16; o; o >>= 1){
#pragma unroll
            for (int u = 0; u < 4; u++){
                S[u] += __shfl_xor_sync(F, S[u], o);
                Q[u] += __shfl_xor_sync(F, Q[u], o);
            }
        }
        // --- tree8 distribute, interleaved across u ---
        {
            bool up = (lane & 16) != 0;
#pragma unroll
            for (int u = 0; u < 4; u++)
#pragma unroll
                for (int k = 0; k < 4; k++){
                    float send = up ? D[u][k]   : D[u][k+4];
                    float keep = up ? D[u][k+4] : D[u][k];
                    D[u][k] = keep + __shfl_xor_sync(F, send, 16);
                }
        }
        {
            bool up = (lane & 8) != 0;
#pragma unroll
            for (int u = 0; u < 4; u++)
#pragma unroll
                for (int k = 0; k < 2; k++){
                    float send = up ? D[u][k]   : D[u][k+2];
                    float keep = up ? D[u][k+2] : D[u][k];
                    D[u][k] = keep + __shfl_xor_sync(F, send, 8);
                }
        }
        {
            bool up = (lane & 4) != 0;
#pragma unroll
            for (int u = 0; u < 4; u++){
                float send = up ? D[u][0] : D[u][1];
                float keep = up ? D[u][1] : D[u][0];
                D[u][0] = keep + __shfl_xor_sync(F, send, 4);
            }
        }
#pragma unroll
        for (int u = 0; u < 4; u++) D[u][0] += __shfl_xor_sync(F, D[u][0], 2);
#pragma unroll
        for (int u = 0; u < 4; u++) D[u][0] += __shfl_xor_sync(F, D[u][0], 1);

        // --- bias + staged write ---
#pragma unroll
        for (int u = 0; u < 4; u++){
            int j = warp*96 + b*4 + u;
            float mu   = S[u] * (1.f/128.f);
            float var  = Q[u] * (1.f/128.f) - mu*mu;
            float rstd = rsqrtf(var + 1e-5f);
            float bias = fmaf(rstd, D[u][0], fmaf(-rstd*mu, Gh, Bh));
            if ((lane & 3) == 0) stage[myh][j] = bias;
        }
    }
    __syncthreads();
#pragma unroll
    for (int t = tid; t < 8*L; t += 256){
        int h = t / L, j = t % L;
        g_bias[(size_t)h*LL + (size_t)i*L + j] = stage[h][j];
    }
}

// -------------------- K3: Q,K,V^T,Gate (pipelined mma) -----------------------
#define QCH 12288
__global__ void __launch_bounds__(256) qkvg_mma(){
    __shared__ __align__(16) char sm[2*QCH];
    const uint32_t sb = smem_u32(sm);
    const int tid = threadIdx.x, lane = tid & 31, wid = tid >> 5;
    const int wm16 = (wid & 3) * 16, wn32 = (wid >> 2) * 32;
    const int m0 = blockIdx.y * 64;
    const int ng = blockIdx.x * 64;

    float acc[4][4];
#pragma unroll
    for (int b = 0; b < 4; b++)
#pragma unroll
        for (int c = 0; c < 4; c++) acc[b][c] = 0.f;

    auto load = [&](int buf, int ch){
        int k = ch * 16;
#pragma unroll
        for (int u = 0; u < 2; u++){
            int idx = tid + u*256;
            int s = idx >> 7, rc = idx & 127, r = rc >> 1, c = rc & 1;
            const __nv_bfloat16* src =
                (s == 0) ? g_ah + (size_t)(m0+r)*CS + k + c*8 :
                (s == 1) ? g_al + (size_t)(m0+r)*CS + k + c*8 :
                (s == 2) ? g_wh + (size_t)(ng+r)*CS + k + c*8 :
                           g_wl + (size_t)(ng+r)*CS + k + c*8;
            cpa16(sb + buf*QCH + s*3072 + r*48 + c*16, src);
        }
        CPA_COMMIT();
    };

    load(0, 0);
    for (int ch = 0; ch < 24; ch++){
        if (ch + 1 < 24){ load((ch+1) & 1, ch+1); CPA_WAIT1(); }
        else CPA_WAIT0();
        __syncthreads();
        uint32_t base = sb + (ch & 1)*QCH;
        uint32_t ah[4], al[4], bh[2][4], bl[2][4];
        ldA(ah, base,        wm16, lane);
        ldA(al, base + 3072, wm16, lane);
#pragma unroll
        for (int pr = 0; pr < 2; pr++){
            ldB(bh[pr], base + 6144, wn32 + pr*16, lane);
            ldB(bl[pr], base + 9216, wn32 + pr*16, lane);
        }
#pragma unroll
        for (int nt = 0; nt < 4; nt++){
            const uint32_t* bhp = &bh[nt>>1][(nt&1)*2];
            const uint32_t* blp = &bl[nt>>1][(nt&1)*2];
            mma16816(acc[nt], ah, bhp);
            mma16816(acc[nt], al, bhp);
            mma16816(acc[nt], ah, blp);
        }
        __syncthreads();
    }

    const int which = ng / 384;
    const int nloc  = ng - which*384;
    const int rb = m0 + wm16 + (lane >> 2);
    const int cb = wn32 + (lane & 3)*2;
    if (which <= 1){
        __nv_bfloat16* PH = which ? g_kh : g_qh;
        __nv_bfloat16* PL = which ? g_kl : g_ql;
#pragma unroll
        for (int half = 0; half < 2; half++){
            int i = rb + half*8;
#pragma unroll
            for (int nt = 0; nt < 4; nt++){
                int cg = nloc + cb + nt*8;
                float v0 = acc[nt][half*2], v1 = acc[nt][half*2+1];
                __nv_bfloat16 h0 = __float2bfloat16(v0);
                __nv_bfloat16 h1 = __float2bfloat16(v1);
                __nv_bfloat16 l0 = __float2bfloat16(v0 - __bfloat162float(h0));
                __nv_bfloat16 l1 = __float2bfloat16(v1 - __bfloat162float(h1));
                *(__nv_bfloat162*)(PH + (size_t)i*CS + cg) = __halves2bfloat162(h0, h1);
                *(__nv_bfloat162*)(PL + (size_t)i*CS + cg) = __halves2bfloat162(l0, l1);
            }
        }
    } else if (which == 2){
#pragma unroll
        for (int half = 0; half < 2; half++){
            int i = rb + half*8;
#pragma unroll
            for (int nt = 0; nt < 4; nt++){
                int cg = nloc + cb + nt*8;
                float v0 = acc[nt][half*2], v1 = acc[nt][half*2+1];
                __nv_bfloat16 h0 = __float2bfloat16(v0);
                __nv_bfloat16 h1 = __float2bfloat16(v1);
                g_vth[(size_t)cg*L + i]     = h0;
                g_vth[(size_t)(cg+1)*L + i] = h1;
                g_vtl[(size_t)cg*L + i]     = __float2bfloat16(v0 - __bfloat162float(h0));
                g_vtl[(size_t)(cg+1)*L + i] = __float2bfloat16(v1 - __bfloat162float(h1));
            }
        }
    } else {
#pragma unroll
        for (int half = 0; half < 2; half++){
            int i = rb + half*8;
#pragma unroll
            for (int nt = 0; nt < 4; nt++){
                int cg = nloc + cb + nt*8;
                float2 v = make_float2(acc[nt][half*2], acc[nt][half*2+1]);
                *(float2*)(g_gate + (size_t)i*CS + cg) = v;
            }
        }
    }
}

// -------------------- K4: fused flash attention ------------------------------
// grid (jsplit=4, mtiles=12, h=8), 128 threads (4 warps x m16, full n=64).
// smem: K hi[0,9216) K lo[9216,18432) V hi[18432,27648) V lo[27648,36864)
__global__ void __launch_bounds__(128) attn_fused(){
    __shared__ __align__(16) char sm[36864];
    const uint32_t sb = smem_u32(sm);
    const int tid = threadIdx.x, lane = tid & 31, wid = tid >> 5;
    const int js = blockIdx.x;
    const int m0 = blockIdx.y * 64;
    const int h  = blockIdx.z;
    const int jb = js * 192;
    const float sc = 0.14433756729740643f;

    // --- stage Q tile through smem, keep A-fragments in registers ---
#pragma unroll
    for (int u = 0; u < 6; u++){
        int idx = tid + u*128;               // [0,768)
        int plane = idx / 384, rem = idx - plane*384;
        int s = rem >> 7, rc = rem & 127, r = rc >> 1, c = rc & 1;
        const __nv_bfloat16* src = (plane ? g_ql : g_qh)
            + (size_t)(m0+r)*CS + h*HD + s*16 + c*8;
        *(uint4*)(sm + plane*9216 + s*3072 + r*48 + c*16) = *(const uint4*)src;
    }
    __syncthreads();
    uint32_t qh[3][4], ql[3][4];
#pragma unroll
    for (int s = 0; s < 3; s++){
        ldA(qh[s], sb +        (uint32_t)(s*3072), wid*16, lane);
        ldA(ql[s], sb + 9216 + (uint32_t)(s*3072), wid*16, lane);
    }

    float mrow[2] = {-INFINITY, -INFINITY};
    float lrow[2] = {0.f, 0.f};
    float o[6][4];
#pragma unroll
    for (int dn = 0; dn < 6; dn++)
#pragma unroll
        for (int e = 0; e < 4; e++) o[dn][e] = 0.f;

    const int r0 = lane >> 2;                 // warp-local row (and +8)
    const int c0 = (lane & 3) * 2;

    for (int step = 0; step < 3; step++){
        int j0 = jb + step*64;
        __syncthreads();   // prior iteration's smem reads complete
        // load K tile (64 rows j x 48) hi/lo and V^T tile (48 rows d x 64 j) hi/lo
#pragma unroll
        for (int u = 0; u < 12; u++){
            int idx = tid + u*128;            // [0,1536)
            if (idx < 768){
                int plane = idx / 384, rem = idx - plane*384;
                int s = rem >> 7, rc = rem & 127, r = rc >> 1, c = rc & 1;
                const __nv_bfloat16* src = (plane ? g_kl : g_kh)
                    + (size_t)(j0+r)*CS + h*HD + s*16 + c*8;
                *(uint4*)(sm + plane*9216 + s*3072 + r*48 + c*16) = *(const uint4*)src;
            } else {
                int q2 = idx - 768;
                int plane = q2 / 384, rem = q2 - plane*384;
                int g = rem / 96, rc = rem - g*96, r = rc >> 1, c = rc & 1;
                const __nv_bfloat16* src = (plane ? g_vtl : g_vth)
                    + (size_t)(h*HD + r)*L + j0 + g*16 + c*8;
                *(uint4*)(sm + 18432 + plane*9216 + g*2304 + r*48 + c*16) = *(const uint4*)src;
            }
        }
        __syncthreads();

        // --- S = Q K^T (bf16-split, 3 terms) ---
        float s_[8][4];
#pragma unroll
        for (int nt = 0; nt < 8; nt++)
#pragma unroll
            for (int e = 0; e < 4; e++) s_[nt][e] = 0.f;
#pragma unroll
        for (int sl = 0; sl < 3; sl++){
            uint32_t bh[4][4], bl[4][4];
#pragma unroll
            for (int p = 0; p < 4; p++){
                ldB(bh[p], sb +        (uint32_t)(sl*3072), p*16, lane);
                ldB(bl[p], sb + 9216 + (uint32_t)(sl*3072), p*16, lane);
            }
#pragma unroll
            for (int nt = 0; nt < 8; nt++){
                const uint32_t* bhp = &bh[nt>>1][(nt&1)*2];
                const uint32_t* blp = &bl[nt>>1][(nt&1)*2];
                mma16816(s_[nt], qh[sl], bhp);
                mma16816(s_[nt], ql[sl], bhp);
                mma16816(s_[nt], qh[sl], blp);
            }
        }

        // --- add bias (direct from L2-resident g_bias) ---
#pragma unroll
        for (int nt = 0; nt < 8; nt++)
#pragma unroll
            for (int e = 0; e < 2; e++){
                int i = m0 + wid*16 + r0 + e*8;
                float2 b = *(const float2*)(g_bias + (size_t)h*LL + (size_t)i*L
                                            + j0 + nt*8 + c0);
                s_[nt][e*2]   = fmaf(s_[nt][e*2],   sc, b.x);
                s_[nt][e*2+1] = fmaf(s_[nt][e*2+1], sc, b.y);
            }

        // --- online softmax (rows fully inside warp quad) ---
#pragma unroll
        for (int e = 0; e < 2; e++){
            float mx = -INFINITY;
#pragma unroll
            for (int nt = 0; nt < 8; nt++)
                mx = fmaxf(mx, fmaxf(s_[nt][e*2], s_[nt][e*2+1]));
            mx = fmaxf(mx, __shfl_xor_sync(0xffffffffu, mx, 1));
            mx = fmaxf(mx, __shfl_xor_sync(0xffffffffu, mx, 2));
            float mn = fmaxf(mrow[e], mx);
            float alpha = __expf(mrow[e] - mn);
            mrow[e] = mn;
            float sum = 0.f;
#pragma unroll
            for (int nt = 0; nt < 8; nt++){
                float p0 = __expf(s_[nt][e*2]   - mn);
                float p1 = __expf(s_[nt][e*2+1] - mn);
                s_[nt][e*2] = p0; s_[nt][e*2+1] = p1;
                sum += p0 + p1;
            }
            sum += __shfl_xor_sync(0xffffffffu, sum, 1);
            sum += __shfl_xor_sync(0xffffffffu, sum, 2);
            lrow[e] = lrow[e]*alpha + sum;
#pragma unroll
            for (int dn = 0; dn < 6; dn++){
                o[dn][e*2]   *= alpha;
                o[dn][e*2+1] *= alpha;
            }
        }

        // --- O += P V  (P from C-frag -> A-frag identity, hi/lo split) ---
#pragma unroll
        for (int g = 0; g < 4; g++){
            uint32_t aH[4], aL[4];
#pragma unroll
            for (int half = 0; half < 2; half++){
                int nt = 2*g + half;
#pragma unroll
                for (int e = 0; e < 2; e++){
                    float p0 = s_[nt][e*2], p1 = s_[nt][e*2+1];
                    uint32_t hi = packbf2(p0, p1);
                    __nv_bfloat162 hv = *(__nv_bfloat162*)&hi;
                    uint32_t lo = packbf2(p0 - __bfloat162float(hv.x),
                                          p1 - __bfloat162float(hv.y));
                    aH[half*2 + e] = hi;
                    aL[half*2 + e] = lo;
                }
            }
            uint32_t vh[3][4], vl[3][4];
#pragma unroll
            for (int q = 0; q < 3; q++){
                ldB(vh[q], sb + 18432 + (uint32_t)(g*2304), q*16, lane);
                ldB(vl[q], sb + 27648 + (uint32_t)(g*2304), q*16, lane);
            }
#pragma unroll
            for (int dn = 0; dn < 6; dn++){
                const uint32_t* vhp = &vh[dn>>1][(dn&1)*2];
                const uint32_t* vlp = &vl[dn>>1][(dn&1)*2];
                mma16816(o[dn], aH, vhp);
                mma16816(o[dn], aL, vhp);
                mma16816(o[dn], aH, vlp);
            }
        }
    }

    // --- write unnormalized O + stats ---
#pragma unroll
    for (int e = 0; e < 2; e++){
        int i = m0 + wid*16 + r0 + e*8;
        float* op = g_opart + (size_t)js*OPS + (size_t)i*CS + h*HD;
#pragma unroll
        for (int dn = 0; dn < 6; dn++)
            *(float2*)(op + dn*8 + c0) = make_float2(o[dn][e*2], o[dn][e*2+1]);
        if ((lane & 3) == 0)
            g_stat[js*NH*L + h*L + i] = make_float2(mrow[e], lrow[e]);
    }
}

// -------------------- K5: out = single + sigmoid(gate+bg)*(O@Wo^T+bo) -------
// A = softmax-combined O from NSPLIT splits. 64x64 tile, BK=32, 128 threads.
__global__ void __launch_bounds__(128) final_kernel(
        const float* __restrict__ Wo, const float* __restrict__ bo,
        const float* __restrict__ single, const float* __restrict__ bg,
        float* __restrict__ out){
    __shared__ float As[32*68];
    __shared__ float Bs[32*68];
    __shared__ float wsm[64][8][NSPLIT];    // combine weights per (row, head)
    const int tid = threadIdx.x;
    const int tx  = tid % 16, ty = tid / 16;   // TN=4, TM=8
    const int m0 = blockIdx.y*64, n0 = blockIdx.x*64;

    // precompute split-combine weights
    for (int p = tid; p < 64*8; p += 128){
        int row = p >> 3, h = p & 7;
        int gi = m0 + row;
        float2 st[NSPLIT];
        float M = -INFINITY;
#pragma unroll
        for (int s = 0; s < NSPLIT; s++){
            st[s] = g_stat[s*NH*L + h*L + gi];
            M = fmaxf(M, st[s].x);
        }
        float w[NSPLIT], den = 0.f;
#pragma unroll
        for (int s = 0; s < NSPLIT; s++){
            w[s] = __expf(st[s].x - M);
            den = fmaf(w[s], st[s].y, den);
        }
        float inv = 1.f / den;
#pragma unroll
        for (int s = 0; s < NSPLIT; s++) wsm[row][h][s] = w[s]*inv;
    }
    __syncthreads();

    float acc[8][4];
#pragma unroll
    for (int i = 0; i < 8; i++)
#pragma unroll
        for (int j = 0; j < 4; j++) acc[i][j] = 0.f;

    for (int kt = 0; kt < CS; kt += 32){
#pragma unroll
        for (int u = 0; u < 4; u++){
            int t4 = tid + u*128;             // AF4 = 64*8 = 512
            int row = t4 >> 3, kq = t4 & 7;
            int c = kt + kq*4;
            int h = c / HD;
            int gi = m0 + row;
            const float* p = g_opart + (size_t)gi*CS + c;
            float4 v = make_float4(0.f, 0.f, 0.f, 0.f);
#pragma unroll
            for (int s = 0; s < NSPLIT; s++){
                float ws = wsm[row][h][s];
                float4 vs = *(const float4*)(p + (size_t)s*OPS);
                v.x = fmaf(ws, vs.x, v.x); v.y = fmaf(ws, vs.y, v.y);
                v.z = fmaf(ws, vs.z, v.z); v.w = fmaf(ws, vs.w, v.w);
            }
            As[(kq*4+0)*68+row] = v.x; As[(kq*4+1)*68+row] = v.y;
            As[(kq*4+2)*68+row] = v.z; As[(kq*4+3)*68+row] = v.w;
        }
#pragma unroll
        for (int u = 0; u < 4; u++){
            int t4 = tid + u*128;             // BF4 = 64*8 = 512
            int row = t4 >> 3, kq = t4 & 7;
            float4 v = *(const float4*)(Wo + (size_t)(n0 + row)*CS + kt + kq*4);
            Bs[(kq*4+0)*68+row] = v.x; Bs[(kq*4+1)*68+row] = v.y;
            Bs[(kq*4+2)*68+row] = v.z; Bs[(kq*4+3)*68+row] = v.w;
        }
        __syncthreads();
#pragma unroll
        for (int kk = 0; kk < 32; kk++){
            float af[8], bf[4];
            *(float4*)&af[0] = *(const float4*)&As[kk*68 + ty*8];
            *(float4*)&af[4] = *(const float4*)&As[kk*68 + ty*8 + 4];
            *(float4*)&bf[0] = *(const float4*)&Bs[kk*68 + tx*4];
#pragma unroll
            for (int i = 0; i < 8; i++)
#pragma unroll
                for (int j = 0; j < 4; j++)
                    acc[i][j] = fmaf(af[i], bf[j], acc[i][j]);
        }
        __syncthreads();
    }

#pragma unroll
    for (int i = 0; i < 8; i++){
        int row = m0 + ty*8 + i;
#pragma unroll
        for (int j = 0; j < 4; j++){
            int col = n0 + tx*4 + j;
            float y  = acc[i][j] + bo[col];
            float gp = g_gate[(size_t)row*CS + col] + bg[col];
            float gg = 1.f / (1.f + __expf(-gp));
            out[(size_t)row*CS + col] = single[(size_t)row*CS + col] + gg * y;
        }
    }
}

// -------------------- launch --------------------
extern "C" void kernel_launch(void* const* d_in, const int* in_sizes, int n_in,
                              void* d_out, int out_size){
    const float* single = (const float*)d_in[0];
    const float* pair   = (const float*)d_in[1];
    const float* gs     = (const float*)d_in[2];
    const float* bs     = (const float*)d_in[3];
    const float* gz     = (const float*)d_in[4];
    const float* bz     = (const float*)d_in[5];
    const float* Wq     = (const float*)d_in[6];
    const float* Wk     = (const float*)d_in[7];
    const float* Wv     = (const float*)d_in[8];
    const float* Wb     = (const float*)d_in[9];
    const float* Wo     = (const float*)d_in[10];
    const float* bo     = (const float*)d_in[11];
    const float* Wg     = (const float*)d_in[12];
    const float* bg     = (const float*)d_in[13];
    float* out = (float*)d_out;

    // ln_pair_bias kept in 4th slot (profiler captures launch #4).
    conv_w_kernel<<<576, 256>>>(Wq, Wk, Wv, Wg);
    ln_single_kernel<<<L, 128>>>(single, gs, bs);
    qkvg_mma<<<dim3(1536/64, L/64), 256>>>();
    ln_pair_bias_kernel<<<L, 256>>>((const float4*)pair, gz, bz, Wb);
    attn_fused<<<dim3(NSPLIT, L/64, NH), 128>>>();
    final_kernel<<<dim3(CS/64, L/64), 128>>>(Wo, bo, single, bg, out);
}

// round 13
// speedup vs baseline: 2.2950x; 1.1453x over previous
#include <cuda_runtime.h>
#include <cuda_bf16.h>
#include <cstdint>
#include <math.h>

// AttentionWithPairBias: B=1, L=768, C_S=384, C_Z=128, H=8, HD=48
#define L 768
#define CS 384
#define NH 8
#define HD 48
#define LL (L*L)
#define OPS (L*CS)
#define NSPLIT 4

// -------------------- scratch (device globals; no allocs) --------------------
__device__ float g_bias[(size_t)NH*LL];  // pair bias (fp32), read by attn
__device__ float g_gate[L*CS];
__device__ float g_opart[NSPLIT*OPS];    // unnormalized O per j-split
__device__ float2 g_stat[NSPLIT*NH*L];   // per split: (m, l) per (h, i)
__device__ __nv_bfloat16 g_ah[L*CS], g_al[L*CS];         // layernorm(single) hi/lo
__device__ __nv_bfloat16 g_wh[4*CS*CS], g_wl[4*CS*CS];   // Wq|Wk|Wv|Wg rows, hi/lo
__device__ __nv_bfloat16 g_qh[L*CS], g_ql[L*CS];         // Q hi/lo
__device__ __nv_bfloat16 g_kh[L*CS], g_kl[L*CS];         // K hi/lo
__device__ __nv_bfloat16 g_vth[CS*L], g_vtl[CS*L];       // V^T hi/lo: [d][j]

// -------------------- warp helpers --------------------
__device__ __forceinline__ float warp_sum(float v){
#pragma unroll
    for (int o = 16; o; o >>= 1) v += __shfl_xor_sync(0xffffffffu, v, o);
    return v;
}

// -------------------- mma.sync / ldmatrix / cp.async (plain PTX, sm_80+) ----
__device__ __forceinline__ uint32_t smem_u32(const void* p){
    uint32_t a;
    asm("{ .reg .u64 t; cvta.to.shared.u64 t, %1; cvt.u32.u64 %0, t; }" : "=r"(a) : "l"(p));
    return a;
}
__device__ __forceinline__ void ldsm4(uint32_t* r, uint32_t addr){
    asm volatile("ldmatrix.sync.aligned.m8n8.x4.shared.b16 {%0,%1,%2,%3}, [%4];"
        : "=r"(r[0]), "=r"(r[1]), "=r"(r[2]), "=r"(r[3]) : "r"(addr));
}
__device__ __forceinline__ void mma16816(float* c, const uint32_t* a, const uint32_t* b){
    asm volatile(
        "mma.sync.aligned.m16n8k16.row.col.f32.bf16.bf16.f32 "
        "{%0,%1,%2,%3}, {%4,%5,%6,%7}, {%8,%9}, {%0,%1,%2,%3};"
        : "+f"(c[0]), "+f"(c[1]), "+f"(c[2]), "+f"(c[3])
        : "r"(a[0]), "r"(a[1]), "r"(a[2]), "r"(a[3]), "r"(b[0]), "r"(b[1]));
}
__device__ __forceinline__ void cpa16(uint32_t dst, const void* src){
    asm volatile("cp.async.cg.shared.global [%0], [%1], 16;" :: "r"(dst), "l"(src));
}
#define CPA_COMMIT() asm volatile("cp.async.commit_group;" ::: "memory")
#define CPA_WAIT1()  asm volatile("cp.async.wait_group 1;" ::: "memory")
#define CPA_WAIT0()  asm volatile("cp.async.wait_group 0;" ::: "memory")

// slab: rows x 16 bf16 payload (32B), pitch 48B (conflict-free ldmatrix)
__device__ __forceinline__ void ldA(uint32_t a[4], uint32_t slab, int wm, int t){
    ldsm4(a, slab + (uint32_t)((wm + (t & 15))*48 + (t >> 4)*16));
}
__device__ __forceinline__ void ldB(uint32_t b[4], uint32_t slab, int nb16, int t){
    ldsm4(b, slab + (uint32_t)((nb16 + ((t >> 4) << 3) + (t & 7))*48 + ((t >> 3) & 1)*16));
}
__device__ __forceinline__ uint32_t packbf2(float a, float b){
    __nv_bfloat162 t = __halves2bfloat162(__float2bfloat16(a), __float2bfloat16(b));
    return *(uint32_t*)&t;
}

// -------------------- K0: split Wq|Wk|Wv|Wg into bf16 hi/lo ------------------
__global__ void conv_w_kernel(const float* __restrict__ Wq, const float* __restrict__ Wk,
                              const float* __restrict__ Wv, const float* __restrict__ Wg){
    int idx = blockIdx.x*256 + threadIdx.x;
    int n  = idx / 96;
    int kq = idx - n*96;
    int which = n / 384;
    int r = n - which*384;
    const float* W = (which == 0) ? Wq : (which == 1) ? Wk : (which == 2) ? Wv : Wg;
    float4 v = *(const float4*)(W + (size_t)r*CS + kq*4);
    float x[4] = {v.x, v.y, v.z, v.w};
    __nv_bfloat16 h[4], l[4];
#pragma unroll
    for (int e = 0; e < 4; e++){
        h[e] = __float2bfloat16(x[e]);
        l[e] = __float2bfloat16(x[e] - __bfloat162float(h[e]));
    }
    size_t o = (size_t)n*CS + kq*4;
    *(__nv_bfloat162*)(g_wh + o)     = __halves2bfloat162(h[0], h[1]);
    *(__nv_bfloat162*)(g_wh + o + 2) = __halves2bfloat162(h[2], h[3]);
    *(__nv_bfloat162*)(g_wl + o)     = __halves2bfloat162(l[0], l[1]);
    *(__nv_bfloat162*)(g_wl + o + 2) = __halves2bfloat162(l[2], l[3]);
}

// -------------------- K1: layernorm(single) -> bf16 hi/lo --------------------
__global__ void ln_single_kernel(const float* __restrict__ x,
                                 const float* __restrict__ g,
                                 const float* __restrict__ b){
    __shared__ float rs[4], rq[4];
    int i = blockIdx.x, t = threadIdx.x;     // 128 threads
    int lane = t & 31, w = t >> 5;
    float v[3];
#pragma unroll
    for (int e = 0; e < 3; e++) v[e] = x[i*CS + e*128 + t];
    float s = v[0] + v[1] + v[2];
    float q = v[0]*v[0] + v[1]*v[1] + v[2]*v[2];
    s = warp_sum(s); q = warp_sum(q);
    if (lane == 0){ rs[w] = s; rq[w] = q; }
    __syncthreads();
    s = rs[0] + rs[1] + rs[2] + rs[3];
    q = rq[0] + rq[1] + rq[2] + rq[3];
    float mu   = s * (1.f/CS);
    float var  = q * (1.f/CS) - mu*mu;
    float rstd = rsqrtf(var + 1e-5f);
#pragma unroll
    for (int e = 0; e < 3; e++){
        int c = e*128 + t;
        float y = (v[e] - mu) * rstd * g[c] + b[c];
        __nv_bfloat16 hh = __float2bfloat16(y);
        g_ah[i*CS + c] = hh;
        g_al[i*CS + c] = __float2bfloat16(y - __bfloat162float(hh));
    }
}

// -------------------- K2: layernorm(pair) + bias = zn @ Wb -------------------
// v4: thread-per-j, zero shuffles. z staged through smem in 32-channel chunks
// (coalesced LDG.128, pitch-33 conflict-free LDS); gzW broadcast from smem.
// bias_h = rstd * d_h - rstd*mu*G_h + B_h with d_h = sum_c z_c * gz_c * Wb[c,h].
__global__ void __launch_bounds__(256) ln_pair_bias_kernel(
                                    const float4* __restrict__ z4,
                                    const float* __restrict__ gz,
                                    const float* __restrict__ bz,
                                    const float* __restrict__ Wb){
    __shared__ float zs[256*33];        // [j][c] pitch 33
    __shared__ float gzw[128*8];        // gz[c]*Wb[c][h], rows of 32B
    __shared__ float GB[16];            // G[8], B[8]
    const int tid = threadIdx.x;
    const int i   = blockIdx.y;
    const int jt0 = blockIdx.x * 256;

    // stage gzw
    for (int p = tid; p < 1024; p += 256){
        int c = p >> 3, h = p & 7;
        gzw[p] = gz[c] * Wb[c*8 + h];
    }
    __syncthreads();
    if (tid < 8){
        float G = 0.f, B = 0.f;
        for (int c = 0; c < 128; c++){
            G += gzw[c*8 + tid];
            B = fmaf(bz[c], Wb[c*8 + tid], B);
        }
        GB[tid] = G; GB[8 + tid] = B;
    }

    const float4* zbase = z4 + ((size_t)i*L + jt0)*32;

    // prefetch chunk 0 (coalesced: consecutive threads -> consecutive float4)
    float4 r[8];
#pragma unroll
    for (int u = 0; u < 8; u++){
        int idx = tid + u*256;              // [0,2048)
        int j = idx >> 3, cq = idx & 7;
        r[u] = zbase[(size_t)j*32 + cq];
    }

    float s = 0.f, q = 0.f;
    float d[8] = {0,0,0,0,0,0,0,0};

#pragma unroll
    for (int ch = 0; ch < 4; ch++){
        // store current chunk to smem (conflict-free: bank = (j + 4cq + e) mod 32)
#pragma unroll
        for (int u = 0; u < 8; u++){
            int idx = tid + u*256;
            int j = idx >> 3, cq = idx & 7;
            float* p = zs + j*33 + cq*4;
            p[0] = r[u].x; p[1] = r[u].y; p[2] = r[u].z; p[3] = r[u].w;
        }
        // prefetch next chunk
        if (ch < 3){
#pragma unroll
            for (int u = 0; u < 8; u++){
                int idx = tid + u*256;
                int j = idx >> 3, cq = idx & 7;
                r[u] = zbase[(size_t)j*32 + (ch+1)*8 + cq];
            }
        }
        __syncthreads();
        // compute own j's 32 channels
        const float* zrow = zs + tid*33;
        const float* gw = gzw + ch*32*8;
#pragma unroll
        for (int c = 0; c < 32; c++){
            float z = zrow[c];
            s += z;
            q = fmaf(z, z, q);
            float4 w0 = *(const float4*)(gw + c*8);
            float4 w1 = *(const float4*)(gw + c*8 + 4);
            d[0] = fmaf(z, w0.x, d[0]);
            d[1] = fmaf(z, w0.y, d[1]);
            d[2] = fmaf(z, w0.z, d[2]);
            d[3] = fmaf(z, w0.w, d[3]);
            d[4] = fmaf(z, w1.x, d[4]);
            d[5] = fmaf(z, w1.y, d[5]);
            d[6] = fmaf(z, w1.z, d[6]);
            d[7] = fmaf(z, w1.w, d[7]);
        }
        __syncthreads();
    }

    float mu   = s * (1.f/128.f);
    float var  = q * (1.f/128.f) - mu*mu;
    float rstd = rsqrtf(var + 1e-5f);
    float nm   = -rstd * mu;
    size_t jg  = (size_t)i*L + jt0 + tid;
#pragma unroll
    for (int h = 0; h < 8; h++){
        float bias = fmaf(rstd, d[h], fmaf(nm, GB[h], GB[8+h]));
        g_bias[(size_t)h*LL + jg] = bias;
    }
}

// -------------------- K3: Q,K,V^T,Gate (pipelined mma) -----------------------
#define QCH 12288
__global__ void __launch_bounds__(256) qkvg_mma(){
    __shared__ __align__(16) char sm[2*QCH];
    const uint32_t sb = smem_u32(sm);
    const int tid = threadIdx.x, lane = tid & 31, wid = tid >> 5;
    const int wm16 = (wid & 3) * 16, wn32 = (wid >> 2) * 32;
    const int m0 = blockIdx.y * 64;
    const int ng = blockIdx.x * 64;

    float acc[4][4];
#pragma unroll
    for (int b = 0; b < 4; b++)
#pragma unroll
        for (int c = 0; c < 4; c++) acc[b][c] = 0.f;

    auto load = [&](int buf, int ch){
        int k = ch * 16;
#pragma unroll
        for (int u = 0; u < 2; u++){
            int idx = tid + u*256;
            int s = idx >> 7, rc = idx & 127, r = rc >> 1, c = rc & 1;
            const __nv_bfloat16* src =
                (s == 0) ? g_ah + (size_t)(m0+r)*CS + k + c*8 :
                (s == 1) ? g_al + (size_t)(m0+r)*CS + k + c*8 :
                (s == 2) ? g_wh + (size_t)(ng+r)*CS + k + c*8 :
                           g_wl + (size_t)(ng+r)*CS + k + c*8;
            cpa16(sb + buf*QCH + s*3072 + r*48 + c*16, src);
        }
        CPA_COMMIT();
    };

    load(0, 0);
    for (int ch = 0; ch < 24; ch++){
        if (ch + 1 < 24){ load((ch+1) & 1, ch+1); CPA_WAIT1(); }
        else CPA_WAIT0();
        __syncthreads();
        uint32_t base = sb + (ch & 1)*QCH;
        uint32_t ah[4], al[4], bh[2][4], bl[2][4];
        ldA(ah, base,        wm16, lane);
        ldA(al, base + 3072, wm16, lane);
#pragma unroll
        for (int pr = 0; pr < 2; pr++){
            ldB(bh[pr], base + 6144, wn32 + pr*16, lane);
            ldB(bl[pr], base + 9216, wn32 + pr*16, lane);
        }
#pragma unroll
        for (int nt = 0; nt < 4; nt++){
            const uint32_t* bhp = &bh[nt>>1][(nt&1)*2];
            const uint32_t* blp = &bl[nt>>1][(nt&1)*2];
            mma16816(acc[nt], ah, bhp);
            mma16816(acc[nt], al, bhp);
            mma16816(acc[nt], ah, blp);
        }
        __syncthreads();
    }

    const int which = ng / 384;
    const int nloc  = ng - which*384;
    const int rb = m0 + wm16 + (lane >> 2);
    const int cb = wn32 + (lane & 3)*2;
    if (which <= 1){
        __nv_bfloat16* PH = which ? g_kh : g_qh;
        __nv_bfloat16* PL = which ? g_kl : g_ql;
#pragma unroll
        for (int half = 0; half < 2; half++){
            int i = rb + half*8;
#pragma unroll
            for (int nt = 0; nt < 4; nt++){
                int cg = nloc + cb + nt*8;
                float v0 = acc[nt][half*2], v1 = acc[nt][half*2+1];
                __nv_bfloat16 h0 = __float2bfloat16(v0);
                __nv_bfloat16 h1 = __float2bfloat16(v1);
                __nv_bfloat16 l0 = __float2bfloat16(v0 - __bfloat162float(h0));
                __nv_bfloat16 l1 = __float2bfloat16(v1 - __bfloat162float(h1));
                *(__nv_bfloat162*)(PH + (size_t)i*CS + cg) = __halves2bfloat162(h0, h1);
                *(__nv_bfloat162*)(PL + (size_t)i*CS + cg) = __halves2bfloat162(l0, l1);
            }
        }
    } else if (which == 2){
#pragma unroll
        for (int half = 0; half < 2; half++){
            int i = rb + half*8;
#pragma unroll
            for (int nt = 0; nt < 4; nt++){
                int cg = nloc + cb + nt*8;
                float v0 = acc[nt][half*2], v1 = acc[nt][half*2+1];
                __nv_bfloat16 h0 = __float2bfloat16(v0);
                __nv_bfloat16 h1 = __float2bfloat16(v1);
                g_vth[(size_t)cg*L + i]     = h0;
                g_vth[(size_t)(cg+1)*L + i] = h1;
                g_vtl[(size_t)cg*L + i]     = __float2bfloat16(v0 - __bfloat162float(h0));
                g_vtl[(size_t)(cg+1)*L + i] = __float2bfloat16(v1 - __bfloat162float(h1));
            }
        }
    } else {
#pragma unroll
        for (int half = 0; half < 2; half++){
            int i = rb + half*8;
#pragma unroll
            for (int nt = 0; nt < 4; nt++){
                int cg = nloc + cb + nt*8;
                float2 v = make_float2(acc[nt][half*2], acc[nt][half*2+1]);
                *(float2*)(g_gate + (size_t)i*CS + cg) = v;
            }
        }
    }
}

// -------------------- K4: fused flash attention ------------------------------
// grid (jsplit=4, mtiles=12, h=8), 128 threads (4 warps x m16, full n=64).
// smem: K hi[0,9216) K lo[9216,18432) V hi[18432,27648) V lo[27648,36864)
__global__ void __launch_bounds__(128) attn_fused(){
    __shared__ __align__(16) char sm[36864];
    const uint32_t sb = smem_u32(sm);
    const int tid = threadIdx.x, lane = tid & 31, wid = tid >> 5;
    const int js = blockIdx.x;
    const int m0 = blockIdx.y * 64;
    const int h  = blockIdx.z;
    const int jb = js * 192;
    const float sc = 0.14433756729740643f;

    // --- stage Q tile through smem, keep A-fragments in registers ---
#pragma unroll
    for (int u = 0; u < 6; u++){
        int idx = tid + u*128;               // [0,768)
        int plane = idx / 384, rem = idx - plane*384;
        int s = rem >> 7, rc = rem & 127, r = rc >> 1, c = rc & 1;
        const __nv_bfloat16* src = (plane ? g_ql : g_qh)
            + (size_t)(m0+r)*CS + h*HD + s*16 + c*8;
        *(uint4*)(sm + plane*9216 + s*3072 + r*48 + c*16) = *(const uint4*)src;
    }
    __syncthreads();
    uint32_t qh[3][4], ql[3][4];
#pragma unroll
    for (int s = 0; s < 3; s++){
        ldA(qh[s], sb +        (uint32_t)(s*3072), wid*16, lane);
        ldA(ql[s], sb + 9216 + (uint32_t)(s*3072), wid*16, lane);
    }

    float mrow[2] = {-INFINITY, -INFINITY};
    float lrow[2] = {0.f, 0.f};
    float o[6][4];
#pragma unroll
    for (int dn = 0; dn < 6; dn++)
#pragma unroll
        for (int e = 0; e < 4; e++) o[dn][e] = 0.f;

    const int r0 = lane >> 2;                 // warp-local row (and +8)
    const int c0 = (lane & 3) * 2;

    for (int step = 0; step < 3; step++){
        int j0 = jb + step*64;
        __syncthreads();   // prior iteration's smem reads complete
        // load K tile (64 rows j x 48) hi/lo and V^T tile (48 rows d x 64 j) hi/lo
#pragma unroll
        for (int u = 0; u < 12; u++){
            int idx = tid + u*128;            // [0,1536)
            if (idx < 768){
                int plane = idx / 384, rem = idx - plane*384;
                int s = rem >> 7, rc = rem & 127, r = rc >> 1, c = rc & 1;
                const __nv_bfloat16* src = (plane ? g_kl : g_kh)
                    + (size_t)(j0+r)*CS + h*HD + s*16 + c*8;
                *(uint4*)(sm + plane*9216 + s*3072 + r*48 + c*16) = *(const uint4*)src;
            } else {
                int q2 = idx - 768;
                int plane = q2 / 384, rem = q2 - plane*384;
                int g = rem / 96, rc = rem - g*96, r = rc >> 1, c = rc & 1;
                const __nv_bfloat16* src = (plane ? g_vtl : g_vth)
                    + (size_t)(h*HD + r)*L + j0 + g*16 + c*8;
                *(uint4*)(sm + 18432 + plane*9216 + g*2304 + r*48 + c*16) = *(const uint4*)src;
            }
        }
        __syncthreads();

        // --- S = Q K^T (bf16-split, 3 terms) ---
        float s_[8][4];
#pragma unroll
        for (int nt = 0; nt < 8; nt++)
#pragma unroll
            for (int e = 0; e < 4; e++) s_[nt][e] = 0.f;
#pragma unroll
        for (int sl = 0; sl < 3; sl++){
            uint32_t bh[4][4], bl[4][4];
#pragma unroll
            for (int p = 0; p < 4; p++){
                ldB(bh[p], sb +        (uint32_t)(sl*3072), p*16, lane);
                ldB(bl[p], sb + 9216 + (uint32_t)(sl*3072), p*16, lane);
            }
#pragma unroll
            for (int nt = 0; nt < 8; nt++){
                const uint32_t* bhp = &bh[nt>>1][(nt&1)*2];
                const uint32_t* blp = &bl[nt>>1][(nt&1)*2];
                mma16816(s_[nt], qh[sl], bhp);
                mma16816(s_[nt], ql[sl], bhp);
                mma16816(s_[nt], qh[sl], blp);
            }
        }

        // --- add bias (direct from L2-resident g_bias) ---
#pragma unroll
        for (int nt = 0; nt < 8; nt++)
#pragma unroll
            for (int e = 0; e < 2; e++){
                int i = m0 + wid*16 + r0 + e*8;
                float2 b = *(const float2*)(g_bias + (size_t)h*LL + (size_t)i*L
                                            + j0 + nt*8 + c0);
                s_[nt][e*2]   = fmaf(s_[nt][e*2],   sc, b.x);
                s_[nt][e*2+1] = fmaf(s_[nt][e*2+1], sc, b.y);
            }

        // --- online softmax (rows fully inside warp quad) ---
#pragma unroll
        for (int e = 0; e < 2; e++){
            float mx = -INFINITY;
#pragma unroll
            for (int nt = 0; nt < 8; nt++)
                mx = fmaxf(mx, fmaxf(s_[nt][e*2], s_[nt][e*2+1]));
            mx = fmaxf(mx, __shfl_xor_sync(0xffffffffu, mx, 1));
            mx = fmaxf(mx, __shfl_xor_sync(0xffffffffu, mx, 2));
            float mn = fmaxf(mrow[e], mx);
            float alpha = __expf(mrow[e] - mn);
            mrow[e] = mn;
            float sum = 0.f;
#pragma unroll
            for (int nt = 0; nt < 8; nt++){
                float p0 = __expf(s_[nt][e*2]   - mn);
                float p1 = __expf(s_[nt][e*2+1] - mn);
                s_[nt][e*2] = p0; s_[nt][e*2+1] = p1;
                sum += p0 + p1;
            }
            sum += __shfl_xor_sync(0xffffffffu, sum, 1);
            sum += __shfl_xor_sync(0xffffffffu, sum, 2);
            lrow[e] = lrow[e]*alpha + sum;
#pragma unroll
            for (int dn = 0; dn < 6; dn++){
                o[dn][e*2]   *= alpha;
                o[dn][e*2+1] *= alpha;
            }
        }

        // --- O += P V  (P from C-frag -> A-frag identity, hi/lo split) ---
#pragma unroll
        for (int g = 0; g < 4; g++){
            uint32_t aH[4], aL[4];
#pragma unroll
            for (int half = 0; half < 2; half++){
                int nt = 2*g + half;
#pragma unroll
                for (int e = 0; e < 2; e++){
                    float p0 = s_[nt][e*2], p1 = s_[nt][e*2+1];
                    uint32_t hi = packbf2(p0, p1);
                    __nv_bfloat162 hv = *(__nv_bfloat162*)&hi;
                    uint32_t lo = packbf2(p0 - __bfloat162float(hv.x),
                                          p1 - __bfloat162float(hv.y));
                    aH[half*2 + e] = hi;
                    aL[half*2 + e] = lo;
                }
            }
            uint32_t vh[3][4], vl[3][4];
#pragma unroll
            for (int q = 0; q < 3; q++){
                ldB(vh[q], sb + 18432 + (uint32_t)(g*2304), q*16, lane);
                ldB(vl[q], sb + 27648 + (uint32_t)(g*2304), q*16, lane);
            }
#pragma unroll
            for (int dn = 0; dn < 6; dn++){
                const uint32_t* vhp = &vh[dn>>1][(dn&1)*2];
                const uint32_t* vlp = &vl[dn>>1][(dn&1)*2];
                mma16816(o[dn], aH, vhp);
                mma16816(o[dn], aL, vhp);
                mma16816(o[dn], aH, vlp);
            }
        }
    }

    // --- write unnormalized O + stats ---
#pragma unroll
    for (int e = 0; e < 2; e++){
        int i = m0 + wid*16 + r0 + e*8;
        float* op = g_opart + (size_t)js*OPS + (size_t)i*CS + h*HD;
#pragma unroll
        for (int dn = 0; dn < 6; dn++)
            *(float2*)(op + dn*8 + c0) = make_float2(o[dn][e*2], o[dn][e*2+1]);
        if ((lane & 3) == 0)
            g_stat[js*NH*L + h*L + i] = make_float2(mrow[e], lrow[e]);
    }
}

// -------------------- K5: out = single + sigmoid(gate+bg)*(O@Wo^T+bo) -------
// A = softmax-combined O from NSPLIT splits. 64x64 tile, BK=32, 128 threads.
__global__ void __launch_bounds__(128) final_kernel(
        const float* __restrict__ Wo, const float* __restrict__ bo,
        const float* __restrict__ single, const float* __restrict__ bg,
        float* __restrict__ out){
    __shared__ float As[32*68];
    __shared__ float Bs[32*68];
    __shared__ float wsm[64][8][NSPLIT];    // combine weights per (row, head)
    const int tid = threadIdx.x;
    const int tx  = tid % 16, ty = tid / 16;   // TN=4, TM=8
    const int m0 = blockIdx.y*64, n0 = blockIdx.x*64;

    // precompute split-combine weights
    for (int p = tid; p < 64*8; p += 128){
        int row = p >> 3, h = p & 7;
        int gi = m0 + row;
        float2 st[NSPLIT];
        float M = -INFINITY;
#pragma unroll
        for (int s = 0; s < NSPLIT; s++){
            st[s] = g_stat[s*NH*L + h*L + gi];
            M = fmaxf(M, st[s].x);
        }
        float w[NSPLIT], den = 0.f;
#pragma unroll
        for (int s = 0; s < NSPLIT; s++){
            w[s] = __expf(st[s].x - M);
            den = fmaf(w[s], st[s].y, den);
        }
        float inv = 1.f / den;
#pragma unroll
        for (int s = 0; s < NSPLIT; s++) wsm[row][h][s] = w[s]*inv;
    }
    __syncthreads();

    float acc[8][4];
#pragma unroll
    for (int i = 0; i < 8; i++)
#pragma unroll
        for (int j = 0; j < 4; j++) acc[i][j] = 0.f;

    for (int kt = 0; kt < CS; kt += 32){
#pragma unroll
        for (int u = 0; u < 4; u++){
            int t4 = tid + u*128;             // AF4 = 64*8 = 512
            int row = t4 >> 3, kq = t4 & 7;
            int c = kt + kq*4;
            int h = c / HD;
            int gi = m0 + row;
            const float* p = g_opart + (size_t)gi*CS + c;
            float4 v = make_float4(0.f, 0.f, 0.f, 0.f);
#pragma unroll
            for (int s = 0; s < NSPLIT; s++){
                float ws = wsm[row][h][s];
                float4 vs = *(const float4*)(p + (size_t)s*OPS);
                v.x = fmaf(ws, vs.x, v.x); v.y = fmaf(ws, vs.y, v.y);
                v.z = fmaf(ws, vs.z, v.z); v.w = fmaf(ws, vs.w, v.w);
            }
            As[(kq*4+0)*68+row] = v.x; As[(kq*4+1)*68+row] = v.y;
            As[(kq*4+2)*68+row] = v.z; As[(kq*4+3)*68+row] = v.w;
        }
#pragma unroll
        for (int u = 0; u < 4; u++){
            int t4 = tid + u*128;             // BF4 = 64*8 = 512
            int row = t4 >> 3, kq = t4 & 7;
            float4 v = *(const float4*)(Wo + (size_t)(n0 + row)*CS + kt + kq*4);
            Bs[(kq*4+0)*68+row] = v.x; Bs[(kq*4+1)*68+row] = v.y;
            Bs[(kq*4+2)*68+row] = v.z; Bs[(kq*4+3)*68+row] = v.w;
        }
        __syncthreads();
#pragma unroll
        for (int kk = 0; kk < 32; kk++){
            float af[8], bf[4];
            *(float4*)&af[0] = *(const float4*)&As[kk*68 + ty*8];
            *(float4*)&af[4] = *(const float4*)&As[kk*68 + ty*8 + 4];
            *(float4*)&bf[0] = *(const float4*)&Bs[kk*68 + tx*4];
#pragma unroll
            for (int i = 0; i < 8; i++)
#pragma unroll
                for (int j = 0; j < 4; j++)
                    acc[i][j] = fmaf(af[i], bf[j], acc[i][j]);
        }
        __syncthreads();
    }

#pragma unroll
    for (int i = 0; i < 8; i++){
        int row = m0 + ty*8 + i;
#pragma unroll
        for (int j = 0; j < 4; j++){
            int col = n0 + tx*4 + j;
            float y  = acc[i][j] + bo[col];
            float gp = g_gate[(size_t)row*CS + col] + bg[col];
            float gg = 1.f / (1.f + __expf(-gp));
            out[(size_t)row*CS + col] = single[(size_t)row*CS + col] + gg * y;
        }
    }
}

// -------------------- launch --------------------
extern "C" void kernel_launch(void* const* d_in, const int* in_sizes, int n_in,
                              void* d_out, int out_size){
    const float* single = (const float*)d_in[0];
    const float* pair   = (const float*)d_in[1];
    const float* gs     = (const float*)d_in[2];
    const float* bs     = (const float*)d_in[3];
    const float* gz     = (const float*)d_in[4];
    const float* bz     = (const float*)d_in[5];
    const float* Wq     = (const float*)d_in[6];
    const float* Wk     = (const float*)d_in[7];
    const float* Wv     = (const float*)d_in[8];
    const float* Wb     = (const float*)d_in[9];
    const float* Wo     = (const float*)d_in[10];
    const float* bo     = (const float*)d_in[11];
    const float* Wg     = (const float*)d_in[12];
    const float* bg     = (const float*)d_in[13];
    float* out = (float*)d_out;

    // ln_pair_bias kept in 4th slot (profiler captures launch #4).
    conv_w_kernel<<<576, 256>>>(Wq, Wk, Wv, Wg);
    ln_single_kernel<<<L, 128>>>(single, gs, bs);
    qkvg_mma<<<dim3(1536/64, L/64), 256>>>();
    ln_pair_bias_kernel<<<dim3(3, L), 256>>>((const float4*)pair, gz, bz, Wb);
    attn_fused<<<dim3(NSPLIT, L/64, NH), 128>>>();
    final_kernel<<<dim3(CS/64, L/64), 128>>>(Wo, bo, single, bg, out);
}